// round 1
// baseline (speedup 1.0000x reference)
#include <cuda_runtime.h>

#define NNODES 50000
#define NEDGE  1000000
#define DIN0   2000
#define EPS_BN 1e-5f
#define LSLOPE 0.01f
#define KC     40
#define SAS    42   /* padded smem stride (even for f32x2 pairs, odd/32 for banks) */

// ------------------------- scratch (device globals) -------------------------
__device__ float    g_qkvA[NNODES * 80];
__device__ float    g_qkvB[NNODES * 80];
__device__ float    g_logit[NEDGE];
__device__ unsigned g_menc[NNODES];
__device__ float    g_denom[NNODES];
__device__ float    g_agg[NNODES * 20];
__device__ float    g_pre[NNODES * 20];
__device__ float    g_x1[NNODES * 20];
__device__ float    g_x2[NNODES * 20];
__device__ float    g_fc[NNODES * 100];
__device__ float    g_stats[40];

// ------------------------- helpers -------------------------
__device__ __forceinline__ unsigned long long ffma2(unsigned long long a,
                                                    unsigned long long b,
                                                    unsigned long long c) {
    unsigned long long d;
    asm("fma.rn.f32x2 %0, %1, %2, %3;" : "=l"(d) : "l"(a), "l"(b), "l"(c));
    return d;
}

__device__ __forceinline__ unsigned fenc(float f) {
    unsigned u = __float_as_uint(f);
    return (u & 0x80000000u) ? ~u : (u | 0x80000000u);
}
__device__ __forceinline__ float fdec(unsigned e) {
    return __uint_as_float((e & 0x80000000u) ? (e & 0x7fffffffu) : ~e);
}

__device__ __forceinline__ void red_add4(float* a, float x, float y, float z, float w) {
    asm volatile("red.global.add.v4.f32 [%0], {%1,%2,%3,%4};"
                 :: "l"(a), "f"(x), "f"(y), "f"(z), "f"(w) : "memory");
}

// ------------------------- GEMM (f32x2 packed) -------------------------
// Computes out[N, NCOLS] = A[N, Din] @ W + b, where W is packed [4, Din, 20]
// (q,k,v,skip) per conv; for NCOLS=160 two convs (W1 cols 0..79 -> outA,
// W2 cols 80..159 -> outB). A is either `features` (Afeat != null) or the
// concat(xa, xb) gather (Din=40).
template <int NCOLS>
__global__ void __launch_bounds__(NCOLS * 64 / 20, 1)
gemm_kernel(const float* __restrict__ Afeat,
            const float* __restrict__ xa, const float* __restrict__ xb,
            int Din,
            const float* __restrict__ W1, const float* __restrict__ W2,
            const float* __restrict__ b1, const float* __restrict__ b2,
            float* __restrict__ outA, float* __restrict__ outB) {
    constexpr int NTH = NCOLS * 64 / 20;  // 512 (NCOLS=160) or 256 (NCOLS=80)
    __shared__ __align__(16) float sA[128 * SAS];
    __shared__ __align__(16) float sWt[NCOLS * SAS];

    const int tid = threadIdx.x;
    const int rowbase = blockIdx.x * 128;
    const int cg = tid / 64;   // column group (20 cols each)
    const int rs = tid % 64;   // row slot (handles rows rs and rs+64)

    unsigned long long acc[2][20];
#pragma unroll
    for (int i = 0; i < 2; i++)
#pragma unroll
        for (int c = 0; c < 20; c++) acc[i][c] = 0ull;

    const int nchunks = Din / KC;
    for (int ch = 0; ch < nchunks; ch++) {
        const int k0 = ch * KC;
        // load A tile [128, KC]
        for (int l = tid; l < 128 * KC; l += NTH) {
            int r = l / KC, k = l % KC;
            int row = rowbase + r;
            float v = 0.f;
            if (row < NNODES) {
                if (Afeat) {
                    v = Afeat[(size_t)row * DIN0 + k0 + k];
                } else {
                    v = (k < 20) ? xa[row * 20 + k] : xb[row * 20 + k - 20];
                }
            }
            sA[r * SAS + k] = v;
        }
        // load W tile transposed: sWt[col][k]
        for (int l = tid; l < NCOLS * KC; l += NTH) {
            int kk = l / NCOLS, c = l % NCOLS;
            int cc = (c >= 80) ? c - 80 : c;
            const float* Wsrc = (c >= 80) ? W2 : W1;
            int s = cc / 20, o = cc % 20;
            sWt[c * SAS + kk] = Wsrc[((size_t)s * Din + k0 + kk) * 20 + o];
        }
        __syncthreads();

        const unsigned long long* pa0 = (const unsigned long long*)(sA + rs * SAS);
        const unsigned long long* pa1 = (const unsigned long long*)(sA + (rs + 64) * SAS);
        const float* wbase = sWt + cg * 20 * SAS;
#pragma unroll 5
        for (int kp = 0; kp < KC / 2; kp++) {
            unsigned long long a0 = pa0[kp];
            unsigned long long a1 = pa1[kp];
#pragma unroll
            for (int c = 0; c < 20; c++) {
                unsigned long long w =
                    *(const unsigned long long*)(wbase + c * SAS + 2 * kp);
                acc[0][c] = ffma2(a0, w, acc[0][c]);
                acc[1][c] = ffma2(a1, w, acc[1][c]);
            }
        }
        __syncthreads();
    }

    const int colbase = cg * 20;
#pragma unroll
    for (int i = 0; i < 2; i++) {
        int row = rowbase + rs + i * 64;
        if (row >= NNODES) continue;
        float res[20];
#pragma unroll
        for (int c = 0; c < 20; c++) {
            float lo = __uint_as_float((unsigned)(acc[i][c] & 0xffffffffull));
            float hi = __uint_as_float((unsigned)(acc[i][c] >> 32));
            int col = colbase + c;
            int cc = (col >= 80) ? col - 80 : col;
            const float* bp = (col >= 80) ? b2 : b1;
            res[c] = lo + hi + bp[cc];
        }
        float* dst = (colbase >= 80) ? (outB + (size_t)row * 80 + (colbase - 80))
                                     : (outA + (size_t)row * 80 + colbase);
#pragma unroll
        for (int c = 0; c < 20; c += 4) {
            *(float4*)(dst + c) = make_float4(res[c], res[c + 1], res[c + 2], res[c + 3]);
        }
    }
}

// ------------------------- edge pipeline -------------------------
__global__ void init_kernel() {
    int i = blockIdx.x * blockDim.x + threadIdx.x;
    if (i < NNODES * 20) g_agg[i] = 0.f;
    if (i < NNODES) { g_menc[i] = 0u; g_denom[i] = 0.f; }
    if (i < 40) g_stats[i] = 0.f;
}

__global__ void pass1_kernel(const float* __restrict__ qkv,
                             const int* __restrict__ src,
                             const int* __restrict__ dst) {
    int e = blockIdx.x * blockDim.x + threadIdx.x;
    if (e >= NEDGE) return;
    int s = src[e], d = dst[e];
    const float4* qp = (const float4*)(qkv + (size_t)d * 80);
    const float4* kp = (const float4*)(qkv + (size_t)s * 80 + 20);
    float dot = 0.f;
#pragma unroll
    for (int i = 0; i < 5; i++) {
        float4 q = qp[i], k = kp[i];
        dot += q.x * k.x + q.y * k.y + q.z * k.z + q.w * k.w;
    }
    float lg = dot * 0.22360679774997896f;  // 1/sqrt(20)
    g_logit[e] = lg;
    atomicMax(&g_menc[d], fenc(lg));
}

__global__ void pass2_kernel(const float* __restrict__ qkv,
                             const int* __restrict__ src,
                             const int* __restrict__ dst) {
    int e = blockIdx.x * blockDim.x + threadIdx.x;
    if (e >= NEDGE) return;
    int s = src[e], d = dst[e];
    float m = fdec(g_menc[d]);
    float ev = __expf(g_logit[e] - m);
    atomicAdd(&g_denom[d], ev);
    const float4* vp = (const float4*)(qkv + (size_t)s * 80 + 40);
    float* ap = g_agg + (size_t)d * 20;
#pragma unroll
    for (int i = 0; i < 5; i++) {
        float4 v = vp[i];
        red_add4(ap + 4 * i, ev * v.x, ev * v.y, ev * v.z, ev * v.w);
    }
}

// out_pre = agg/denom + skip ; accumulate per-column sum & sumsq for BN
__global__ void finalize_stats(const float* __restrict__ qkv) {
    float s[20], ss[20];
#pragma unroll
    for (int c = 0; c < 20; c++) { s[c] = 0.f; ss[c] = 0.f; }
    for (int n = blockIdx.x * blockDim.x + threadIdx.x; n < NNODES;
         n += gridDim.x * blockDim.x) {
        float inv = 1.f / fmaxf(g_denom[n], 1e-16f);
        const float4* ap = (const float4*)(g_agg + (size_t)n * 20);
        const float4* kp = (const float4*)(qkv + (size_t)n * 80 + 60);
        float4* pp = (float4*)(g_pre + (size_t)n * 20);
#pragma unroll
        for (int i = 0; i < 5; i++) {
            float4 a = ap[i];
            float4 sk = kp[i];
            float4 r;
            r.x = a.x * inv + sk.x;
            r.y = a.y * inv + sk.y;
            r.z = a.z * inv + sk.z;
            r.w = a.w * inv + sk.w;
            pp[i] = r;
            s[4 * i + 0] += r.x; ss[4 * i + 0] += r.x * r.x;
            s[4 * i + 1] += r.y; ss[4 * i + 1] += r.y * r.y;
            s[4 * i + 2] += r.z; ss[4 * i + 2] += r.z * r.z;
            s[4 * i + 3] += r.w; ss[4 * i + 3] += r.w * r.w;
        }
    }
#pragma unroll
    for (int c = 0; c < 20; c++) {
#pragma unroll
        for (int off = 16; off; off >>= 1) {
            s[c] += __shfl_xor_sync(0xffffffffu, s[c], off);
            ss[c] += __shfl_xor_sync(0xffffffffu, ss[c], off);
        }
    }
    __shared__ float red[2][8][20];
    int wid = threadIdx.x >> 5, lane = threadIdx.x & 31;
    if (lane == 0) {
#pragma unroll
        for (int c = 0; c < 20; c++) { red[0][wid][c] = s[c]; red[1][wid][c] = ss[c]; }
    }
    __syncthreads();
    if (threadIdx.x < 40) {
        int which = threadIdx.x / 20, c = threadIdx.x % 20;
        float t = 0.f;
#pragma unroll
        for (int w = 0; w < 8; w++) t += red[which][w][c];
        atomicAdd(&g_stats[which * 20 + c], t);
    }
}

__global__ void bn_apply(const float* __restrict__ gamma, const float* __restrict__ beta,
                         float* __restrict__ dst, int stride, int off) {
    int idx = blockIdx.x * blockDim.x + threadIdx.x;
    if (idx >= NNODES * 20) return;
    int n = idx / 20, c = idx % 20;
    const float invN = 1.f / (float)NNODES;
    float mu = g_stats[c] * invN;
    float var = g_stats[20 + c] * invN - mu * mu;
    float scv = gamma[c] * rsqrtf(var + EPS_BN);
    float v = (g_pre[idx] - mu) * scv + beta[c];
    v = (v >= 0.f) ? v : LSLOPE * v;
    dst[(size_t)n * stride + off + c] = v;
}

__global__ void fc_kernel(const float* __restrict__ W, const float* __restrict__ b,
                          float* __restrict__ out) {
    __shared__ float sw[200];
    for (int l = threadIdx.x; l < 200; l += blockDim.x) sw[l] = W[l];
    __syncthreads();
    int n = blockIdx.x * blockDim.x + threadIdx.x;
    if (n >= NNODES) return;
    float a0 = b[0], a1 = b[1];
    const float4* fp = (const float4*)(g_fc + (size_t)n * 100);
#pragma unroll
    for (int i = 0; i < 25; i++) {
        float4 f = fp[i];
        int c = 4 * i;
        a0 += f.x * sw[2 * c + 0] + f.y * sw[2 * c + 2] + f.z * sw[2 * c + 4] + f.w * sw[2 * c + 6];
        a1 += f.x * sw[2 * c + 1] + f.y * sw[2 * c + 3] + f.z * sw[2 * c + 5] + f.w * sw[2 * c + 7];
    }
    out[2 * n] = a0;
    out[2 * n + 1] = a1;
}

// ------------------------- host orchestration -------------------------
static void edge_pipeline(const float* qkv, const int* ei) {
    const int GE = (NEDGE + 255) / 256;
    init_kernel<<<GE, 256>>>();
    pass1_kernel<<<GE, 256>>>(qkv, ei, ei + NEDGE);
    pass2_kernel<<<GE, 256>>>(qkv, ei, ei + NEDGE);
    finalize_stats<<<296, 256>>>(qkv);
}

extern "C" void kernel_launch(void* const* d_in, const int* in_sizes, int n_in,
                              void* d_out, int out_size) {
    (void)in_sizes; (void)n_in; (void)out_size;
    const float* features = (const float*)d_in[0];
    const int* edge_index = (const int*)d_in[3];
    const int* same2      = (const int*)d_in[4];
    const int* diff2      = (const int*)d_in[5];
    const float* c1_W0 = (const float*)d_in[6];
    const float* c1_b0 = (const float*)d_in[7];
    const float* c2_W0 = (const float*)d_in[8];
    const float* c2_b0 = (const float*)d_in[9];
    const float* c1_W  = (const float*)d_in[10];
    const float* c1_b  = (const float*)d_in[11];
    const float* c2_W  = (const float*)d_in[12];
    const float* c2_b  = (const float*)d_in[13];
    const float* c3_W  = (const float*)d_in[14];
    const float* c3_b  = (const float*)d_in[15];
    const float* bn1_g = (const float*)d_in[16];
    const float* bn1_b = (const float*)d_in[17];
    const float* bn2_g = (const float*)d_in[18];
    const float* bn2_b = (const float*)d_in[19];
    const float* bn3_g = (const float*)d_in[20];
    const float* bn3_b = (const float*)d_in[21];
    const float* fc_W  = (const float*)d_in[22];
    const float* fc_b  = (const float*)d_in[23];
    float* out = (float*)d_out;

    float *qkvA, *qkvB, *x1, *x2, *fcb;
    cudaGetSymbolAddress((void**)&qkvA, g_qkvA);
    cudaGetSymbolAddress((void**)&qkvB, g_qkvB);
    cudaGetSymbolAddress((void**)&x1, g_x1);
    cudaGetSymbolAddress((void**)&x2, g_x2);
    cudaGetSymbolAddress((void**)&fcb, g_fc);

    const int GB = (NNODES + 127) / 128;       // 391 row-blocks
    const int GN = (NNODES * 20 + 255) / 256;  // elementwise grid

    // ---- layer 0: big GEMM (features -> qkv for c1 and c2) ----
    gemm_kernel<160><<<GB, 512>>>(features, nullptr, nullptr, DIN0,
                                  c1_W0, c2_W0, c1_b0, c2_b0, qkvA, qkvB);
    edge_pipeline(qkvA, same2);
    bn_apply<<<GN, 256>>>(bn1_g, bn1_b, x1, 20, 0);
    edge_pipeline(qkvB, diff2);
    bn_apply<<<GN, 256>>>(bn2_g, bn2_b, x2, 20, 0);

    // ---- first c3 conv -> fc slot 0 ----
    gemm_kernel<80><<<GB, 256>>>(nullptr, x1, x2, 40,
                                 c3_W, nullptr, c3_b, nullptr, qkvA, nullptr);
    edge_pipeline(qkvA, edge_index);
    bn_apply<<<GN, 256>>>(bn3_g, bn3_b, fcb, 100, 0);

    // ---- 4 iterations ----
    for (int l = 0; l < 4; l++) {
        gemm_kernel<80><<<GB, 256>>>(nullptr, x1, x2, 40,
                                     c1_W + (size_t)l * 3200, nullptr,
                                     c1_b + (size_t)l * 80, nullptr, qkvA, nullptr);
        gemm_kernel<80><<<GB, 256>>>(nullptr, x2, x1, 40,
                                     c2_W + (size_t)l * 3200, nullptr,
                                     c2_b + (size_t)l * 80, nullptr, qkvB, nullptr);
        edge_pipeline(qkvA, same2);
        bn_apply<<<GN, 256>>>(bn1_g + (l + 1) * 20, bn1_b + (l + 1) * 20, x1, 20, 0);
        edge_pipeline(qkvB, diff2);
        bn_apply<<<GN, 256>>>(bn2_g + (l + 1) * 20, bn2_b + (l + 1) * 20, x2, 20, 0);

        gemm_kernel<80><<<GB, 256>>>(nullptr, x1, x2, 40,
                                     c3_W + (size_t)(l + 1) * 3200, nullptr,
                                     c3_b + (size_t)(l + 1) * 80, nullptr, qkvA, nullptr);
        edge_pipeline(qkvA, edge_index);
        bn_apply<<<GN, 256>>>(bn3_g + (l + 1) * 20, bn3_b + (l + 1) * 20,
                              fcb, 100, (l + 1) * 20);
    }

    fc_kernel<<<(NNODES + 127) / 128, 128>>>(fc_W, fc_b, out);
}

// round 2
// speedup vs baseline: 1.0223x; 1.0223x over previous
#include <cuda_runtime.h>

#define NNODES 50000
#define NEDGE  1000000
#define DIN0   2000
#define EPS_BN 1e-5f
#define LSLOPE 0.01f
#define KC     40
#define SAS    42   /* padded smem stride */

// ------------------------- scratch (device globals) -------------------------
__device__ float g_qkvA[NNODES * 80];
__device__ float g_qkvB[NNODES * 80];
__device__ float g_denom[NNODES];      // zero-init at load; self-cleaned each use
__device__ float g_agg[NNODES * 20];   // zero-init at load; self-cleaned each use
__device__ float g_pre[NNODES * 20];
__device__ float g_x1[NNODES * 20];
__device__ float g_x2[NNODES * 20];
__device__ float g_fc[NNODES * 100];
__device__ float g_stats[15 * 40];     // per-layer BN sum/sumsq slots

// ------------------------- helpers -------------------------
__device__ __forceinline__ unsigned long long ffma2(unsigned long long a,
                                                    unsigned long long b,
                                                    unsigned long long c) {
    unsigned long long d;
    asm("fma.rn.f32x2 %0, %1, %2, %3;" : "=l"(d) : "l"(a), "l"(b), "l"(c));
    return d;
}
__device__ __forceinline__ unsigned long long pack2(float lo, float hi) {
    unsigned long long r;
    asm("mov.b64 %0, {%1, %2};" : "=l"(r) : "f"(lo), "f"(hi));
    return r;
}
__device__ __forceinline__ void red_add4(float* a, float x, float y, float z, float w) {
    asm volatile("red.global.add.v4.f32 [%0], {%1,%2,%3,%4};"
                 :: "l"(a), "f"(x), "f"(y), "f"(z), "f"(w) : "memory");
}

// ------------------------- big GEMM (f32x2 packed, Din=2000, 160 cols) -----
__global__ void __launch_bounds__(512, 1)
gemm_big(const float* __restrict__ A,
         const float* __restrict__ W1, const float* __restrict__ W2,
         const float* __restrict__ b1, const float* __restrict__ b2,
         float* __restrict__ outA, float* __restrict__ outB) {
    __shared__ __align__(16) float sA[128 * SAS];
    __shared__ __align__(16) float sWt[160 * SAS];

    const int tid = threadIdx.x;
    const int rowbase = blockIdx.x * 128;
    const int cg = tid / 64;   // column group (20 cols each), 8 groups
    const int rs = tid % 64;   // rows rs and rs+64

    unsigned long long acc[2][20];
#pragma unroll
    for (int i = 0; i < 2; i++)
#pragma unroll
        for (int c = 0; c < 20; c++) acc[i][c] = 0ull;

    for (int ch = 0; ch < DIN0 / KC; ch++) {
        const int k0 = ch * KC;
        for (int l = tid; l < 128 * KC; l += 512) {
            int r = l / KC, k = l % KC;
            int row = rowbase + r;
            sA[r * SAS + k] = (row < NNODES) ? A[(size_t)row * DIN0 + k0 + k] : 0.f;
        }
        for (int l = tid; l < 160 * KC; l += 512) {
            int kk = l / 160, c = l % 160;
            int cc = (c >= 80) ? c - 80 : c;
            const float* Wsrc = (c >= 80) ? W2 : W1;
            int s = cc / 20, o = cc % 20;
            sWt[c * SAS + kk] = Wsrc[((size_t)s * DIN0 + k0 + kk) * 20 + o];
        }
        __syncthreads();

        const unsigned long long* pa0 = (const unsigned long long*)(sA + rs * SAS);
        const unsigned long long* pa1 = (const unsigned long long*)(sA + (rs + 64) * SAS);
        const float* wbase = sWt + cg * 20 * SAS;
#pragma unroll 5
        for (int kp = 0; kp < KC / 2; kp++) {
            unsigned long long a0 = pa0[kp];
            unsigned long long a1 = pa1[kp];
#pragma unroll
            for (int c = 0; c < 20; c++) {
                unsigned long long w =
                    *(const unsigned long long*)(wbase + c * SAS + 2 * kp);
                acc[0][c] = ffma2(a0, w, acc[0][c]);
                acc[1][c] = ffma2(a1, w, acc[1][c]);
            }
        }
        __syncthreads();
    }

    const int colbase = cg * 20;
#pragma unroll
    for (int i = 0; i < 2; i++) {
        int row = rowbase + rs + i * 64;
        if (row >= NNODES) continue;
        float res[20];
#pragma unroll
        for (int c = 0; c < 20; c++) {
            float lo = __uint_as_float((unsigned)(acc[i][c] & 0xffffffffull));
            float hi = __uint_as_float((unsigned)(acc[i][c] >> 32));
            int col = colbase + c;
            int cc = (col >= 80) ? col - 80 : col;
            const float* bp = (col >= 80) ? b2 : b1;
            res[c] = lo + hi + bp[cc];
        }
        float* dst = (colbase >= 80) ? (outB + (size_t)row * 80 + (colbase - 80))
                                     : (outA + (size_t)row * 80 + colbase);
#pragma unroll
        for (int c = 0; c < 20; c += 4)
            *(float4*)(dst + c) = make_float4(res[c], res[c + 1], res[c + 2], res[c + 3]);
    }
}

// ------------------------- small GEMM (Din=40 concat, 80 cols) -------------
// out[row, s*20+o] = sum_k cat(xa,xb)[row,k] * W[s,k,o] + b[s,o]
__global__ void __launch_bounds__(256)
gemm_small(const float* __restrict__ xa, const float* __restrict__ xb,
           const float* __restrict__ W, const float* __restrict__ b,
           float* __restrict__ out) {
    __shared__ __align__(8) float sW[40][80];  // [k][col]
    __shared__ float sb[80];
    const int tid = threadIdx.x;
    for (int l = tid; l < 3200; l += 256) {
        int s = l / 800, rem = l % 800, k = rem / 20, o = rem % 20;
        sW[k][s * 20 + o] = W[l];
    }
    if (tid < 80) sb[tid] = b[tid];
    __syncthreads();

    const int row = blockIdx.x * 128 + (tid >> 1);
    const int cb = (tid & 1) * 40;
    if (row >= NNODES) return;

    float a[40];
    const float4* pa = (const float4*)(xa + (size_t)row * 20);
    const float4* pb = (const float4*)(xb + (size_t)row * 20);
#pragma unroll
    for (int i = 0; i < 5; i++) {
        float4 v = pa[i];
        a[4 * i] = v.x; a[4 * i + 1] = v.y; a[4 * i + 2] = v.z; a[4 * i + 3] = v.w;
        float4 w = pb[i];
        a[20 + 4 * i] = w.x; a[21 + 4 * i] = w.y; a[22 + 4 * i] = w.z; a[23 + 4 * i] = w.w;
    }

    unsigned long long acc[20];
#pragma unroll
    for (int c = 0; c < 20; c++) acc[c] = 0ull;
#pragma unroll 8
    for (int k = 0; k < 40; k++) {
        unsigned long long a2 = pack2(a[k], a[k]);
        const unsigned long long* wrow = (const unsigned long long*)(&sW[k][cb]);
#pragma unroll
        for (int c = 0; c < 20; c++) acc[c] = ffma2(a2, wrow[c], acc[c]);
    }

    float res[40];
#pragma unroll
    for (int c = 0; c < 20; c++) {
        res[2 * c]     = __uint_as_float((unsigned)(acc[c] & 0xffffffffull)) + sb[cb + 2 * c];
        res[2 * c + 1] = __uint_as_float((unsigned)(acc[c] >> 32)) + sb[cb + 2 * c + 1];
    }
    float* dst = out + (size_t)row * 80 + cb;
#pragma unroll
    for (int c = 0; c < 40; c += 4)
        *(float4*)(dst + c) = make_float4(res[c], res[c + 1], res[c + 2], res[c + 3]);
}

// ------------------------- edge pipeline -------------------------
__global__ void zero_stats() {
    int i = blockIdx.x * blockDim.x + threadIdx.x;
    if (i < 15 * 40) g_stats[i] = 0.f;
}

// fused: logits + exp + scatter (no max subtraction; softmax is shift-invariant
// and layer-0 logits peak ~|27| << fp32 overflow)
__global__ void __launch_bounds__(256)
edge_fused(const float* __restrict__ qkv,
           const int* __restrict__ src, const int* __restrict__ dst) {
    int e = blockIdx.x * blockDim.x + threadIdx.x;
    if (e >= NEDGE) return;
    int s = src[e], d = dst[e];
    const float4* qp = (const float4*)(qkv + (size_t)d * 80);
    const float4* kp = (const float4*)(qkv + (size_t)s * 80 + 20);
    float dot = 0.f;
#pragma unroll
    for (int i = 0; i < 5; i++) {
        float4 q = qp[i], k = kp[i];
        dot += q.x * k.x + q.y * k.y + q.z * k.z + q.w * k.w;
    }
    float ev = __expf(dot * 0.22360679774997896f);
    atomicAdd(&g_denom[d], ev);
    const float4* vp = (const float4*)(qkv + (size_t)s * 80 + 40);
    float* ap = g_agg + (size_t)d * 20;
#pragma unroll
    for (int i = 0; i < 5; i++) {
        float4 v = vp[i];
        red_add4(ap + 4 * i, ev * v.x, ev * v.y, ev * v.z, ev * v.w);
    }
}

// pre = agg/denom + skip; accumulate BN stats into slot; self-clean agg/denom
__global__ void __launch_bounds__(256)
finalize_stats(const float* __restrict__ qkv, float* __restrict__ stats) {
    float s[20], ss[20];
#pragma unroll
    for (int c = 0; c < 20; c++) { s[c] = 0.f; ss[c] = 0.f; }
    int n = blockIdx.x * blockDim.x + threadIdx.x;
    if (n < NNODES) {
        float inv = 1.f / fmaxf(g_denom[n], 1e-16f);
        g_denom[n] = 0.f;
        float4* ap = (float4*)(g_agg + (size_t)n * 20);
        const float4* kp = (const float4*)(qkv + (size_t)n * 80 + 60);
        float4* pp = (float4*)(g_pre + (size_t)n * 20);
        const float4 z4 = make_float4(0.f, 0.f, 0.f, 0.f);
#pragma unroll
        for (int i = 0; i < 5; i++) {
            float4 a = ap[i];
            ap[i] = z4;
            float4 sk = kp[i];
            float4 r;
            r.x = a.x * inv + sk.x; r.y = a.y * inv + sk.y;
            r.z = a.z * inv + sk.z; r.w = a.w * inv + sk.w;
            pp[i] = r;
            s[4 * i]     += r.x; ss[4 * i]     += r.x * r.x;
            s[4 * i + 1] += r.y; ss[4 * i + 1] += r.y * r.y;
            s[4 * i + 2] += r.z; ss[4 * i + 2] += r.z * r.z;
            s[4 * i + 3] += r.w; ss[4 * i + 3] += r.w * r.w;
        }
    }
#pragma unroll
    for (int c = 0; c < 20; c++) {
#pragma unroll
        for (int off = 16; off; off >>= 1) {
            s[c] += __shfl_xor_sync(0xffffffffu, s[c], off);
            ss[c] += __shfl_xor_sync(0xffffffffu, ss[c], off);
        }
    }
    __shared__ float red[2][8][20];
    int wid = threadIdx.x >> 5, lane = threadIdx.x & 31;
    if (lane == 0) {
#pragma unroll
        for (int c = 0; c < 20; c++) { red[0][wid][c] = s[c]; red[1][wid][c] = ss[c]; }
    }
    __syncthreads();
    if (threadIdx.x < 40) {
        int which = threadIdx.x / 20, c = threadIdx.x % 20;
        float t = 0.f;
#pragma unroll
        for (int w = 0; w < 8; w++) t += red[which][w][c];
        atomicAdd(&stats[which * 20 + c], t);
    }
}

__global__ void __launch_bounds__(256)
bn_apply(const float* __restrict__ stats,
         const float* __restrict__ gamma, const float* __restrict__ beta,
         float* __restrict__ dst, int stride, int off) {
    int idx = blockIdx.x * blockDim.x + threadIdx.x;
    if (idx >= NNODES * 20) return;
    int n = idx / 20, c = idx % 20;
    const float invN = 1.f / (float)NNODES;
    float mu = stats[c] * invN;
    float var = stats[20 + c] * invN - mu * mu;
    float scv = gamma[c] * rsqrtf(var + EPS_BN);
    float v = (g_pre[idx] - mu) * scv + beta[c];
    v = (v >= 0.f) ? v : LSLOPE * v;
    dst[(size_t)n * stride + off + c] = v;
}

__global__ void __launch_bounds__(128)
fc_kernel(const float* __restrict__ W, const float* __restrict__ b,
          float* __restrict__ out) {
    __shared__ float sw[200];
    for (int l = threadIdx.x; l < 200; l += blockDim.x) sw[l] = W[l];
    __syncthreads();
    int n = blockIdx.x * blockDim.x + threadIdx.x;
    if (n >= NNODES) return;
    float a0 = b[0], a1 = b[1];
    const float4* fp = (const float4*)(g_fc + (size_t)n * 100);
#pragma unroll
    for (int i = 0; i < 25; i++) {
        float4 f = fp[i];
        int c = 4 * i;
        a0 += f.x * sw[2 * c] + f.y * sw[2 * c + 2] + f.z * sw[2 * c + 4] + f.w * sw[2 * c + 6];
        a1 += f.x * sw[2 * c + 1] + f.y * sw[2 * c + 3] + f.z * sw[2 * c + 5] + f.w * sw[2 * c + 7];
    }
    out[2 * n] = a0;
    out[2 * n + 1] = a1;
}

// ------------------------- host orchestration -------------------------
static float* g_statsPtr;

static void edge_pipeline(const float* qkv, const int* ei, int slot) {
    const int GE = (NEDGE + 255) / 256;
    const int GF = (NNODES + 255) / 256;
    edge_fused<<<GE, 256>>>(qkv, ei, ei + NEDGE);
    finalize_stats<<<GF, 256>>>(qkv, g_statsPtr + slot * 40);
}

extern "C" void kernel_launch(void* const* d_in, const int* in_sizes, int n_in,
                              void* d_out, int out_size) {
    (void)in_sizes; (void)n_in; (void)out_size;
    const float* features = (const float*)d_in[0];
    const int* edge_index = (const int*)d_in[3];
    const int* same2      = (const int*)d_in[4];
    const int* diff2      = (const int*)d_in[5];
    const float* c1_W0 = (const float*)d_in[6];
    const float* c1_b0 = (const float*)d_in[7];
    const float* c2_W0 = (const float*)d_in[8];
    const float* c2_b0 = (const float*)d_in[9];
    const float* c1_W  = (const float*)d_in[10];
    const float* c1_b  = (const float*)d_in[11];
    const float* c2_W  = (const float*)d_in[12];
    const float* c2_b  = (const float*)d_in[13];
    const float* c3_W  = (const float*)d_in[14];
    const float* c3_b  = (const float*)d_in[15];
    const float* bn1_g = (const float*)d_in[16];
    const float* bn1_b = (const float*)d_in[17];
    const float* bn2_g = (const float*)d_in[18];
    const float* bn2_b = (const float*)d_in[19];
    const float* bn3_g = (const float*)d_in[20];
    const float* bn3_b = (const float*)d_in[21];
    const float* fc_W  = (const float*)d_in[22];
    const float* fc_b  = (const float*)d_in[23];
    float* out = (float*)d_out;

    float *qkvA, *qkvB, *x1, *x2, *fcb;
    cudaGetSymbolAddress((void**)&qkvA, g_qkvA);
    cudaGetSymbolAddress((void**)&qkvB, g_qkvB);
    cudaGetSymbolAddress((void**)&x1, g_x1);
    cudaGetSymbolAddress((void**)&x2, g_x2);
    cudaGetSymbolAddress((void**)&fcb, g_fc);
    cudaGetSymbolAddress((void**)&g_statsPtr, g_stats);

    const int GB = (NNODES + 127) / 128;       // 391 row-blocks
    const int GN = (NNODES * 20 + 255) / 256;

    zero_stats<<<3, 256>>>();

    // ---- layer 0: big GEMM (features -> qkv for c1 and c2) ----
    gemm_big<<<GB, 512>>>(features, c1_W0, c2_W0, c1_b0, c2_b0, qkvA, qkvB);
    edge_pipeline(qkvA, same2, 0);
    bn_apply<<<GN, 256>>>(g_statsPtr + 0 * 40, bn1_g, bn1_b, x1, 20, 0);
    edge_pipeline(qkvB, diff2, 1);
    bn_apply<<<GN, 256>>>(g_statsPtr + 1 * 40, bn2_g, bn2_b, x2, 20, 0);

    // ---- first c3 conv -> fc slot 0 ----
    gemm_small<<<GB, 256>>>(x1, x2, c3_W, c3_b, qkvA);
    edge_pipeline(qkvA, edge_index, 2);
    bn_apply<<<GN, 256>>>(g_statsPtr + 2 * 40, bn3_g, bn3_b, fcb, 100, 0);

    // ---- 4 iterations ----
    for (int l = 0; l < 4; l++) {
        int sl = 3 + l * 3;
        gemm_small<<<GB, 256>>>(x1, x2, c1_W + (size_t)l * 3200,
                                c1_b + (size_t)l * 80, qkvA);
        gemm_small<<<GB, 256>>>(x2, x1, c2_W + (size_t)l * 3200,
                                c2_b + (size_t)l * 80, qkvB);
        edge_pipeline(qkvA, same2, sl);
        bn_apply<<<GN, 256>>>(g_statsPtr + sl * 40,
                              bn1_g + (l + 1) * 20, bn1_b + (l + 1) * 20, x1, 20, 0);
        edge_pipeline(qkvB, diff2, sl + 1);
        bn_apply<<<GN, 256>>>(g_statsPtr + (sl + 1) * 40,
                              bn2_g + (l + 1) * 20, bn2_b + (l + 1) * 20, x2, 20, 0);

        gemm_small<<<GB, 256>>>(x1, x2, c3_W + (size_t)(l + 1) * 3200,
                                c3_b + (size_t)(l + 1) * 80, qkvA);
        edge_pipeline(qkvA, edge_index, sl + 2);
        bn_apply<<<GN, 256>>>(g_statsPtr + (sl + 2) * 40,
                              bn3_g + (l + 1) * 20, bn3_b + (l + 1) * 20,
                              fcb, 100, (l + 1) * 20);
    }

    fc_kernel<<<(NNODES + 127) / 128, 128>>>(fc_W, fc_b, out);
}

// round 3
// speedup vs baseline: 1.1467x; 1.1216x over previous
#include <cuda_runtime.h>

#define NNODES 50000
#define NEDGE  1000000
#define DIN0   2000
#define EPS_BN 1e-5f
#define LSLOPE 0.01f
#define KC     40
#define SAS    42

// ------------------------- scratch (device globals, zero-init) -------------
__device__ float g_qkvA[NNODES * 80];
__device__ float g_qkvB[NNODES * 80];
__device__ float g_denomA[NNODES];
__device__ float g_denomB[NNODES];
__device__ float g_aggA[NNODES * 20];
__device__ float g_aggB[NNODES * 20];
__device__ float g_preA[NNODES * 20];
__device__ float g_preB[NNODES * 20];
__device__ float g_preC[NNODES * 20];
__device__ float g_fc[NNODES * 100];
__device__ float g_stats[15 * 40];

// ------------------------- helpers -------------------------
__device__ __forceinline__ unsigned long long ffma2(unsigned long long a,
                                                    unsigned long long b,
                                                    unsigned long long c) {
    unsigned long long d;
    asm("fma.rn.f32x2 %0, %1, %2, %3;" : "=l"(d) : "l"(a), "l"(b), "l"(c));
    return d;
}
__device__ __forceinline__ unsigned long long pack2(float lo, float hi) {
    unsigned long long r;
    asm("mov.b64 %0, {%1, %2};" : "=l"(r) : "f"(lo), "f"(hi));
    return r;
}
__device__ __forceinline__ void red_add4(float* a, float x, float y, float z, float w) {
    asm volatile("red.global.add.v4.f32 [%0], {%1,%2,%3,%4};"
                 :: "l"(a), "f"(x), "f"(y), "f"(z), "f"(w) : "memory");
}

// ------------------------- big GEMM (f32x2 packed, Din=2000, 160 cols) -----
__global__ void __launch_bounds__(512, 1)
gemm_big(const float* __restrict__ A,
         const float* __restrict__ W1, const float* __restrict__ W2,
         const float* __restrict__ b1, const float* __restrict__ b2,
         float* __restrict__ outA, float* __restrict__ outB) {
    __shared__ __align__(16) float sA[128 * SAS];
    __shared__ __align__(16) float sWt[160 * SAS];

    const int tid = threadIdx.x;
    const int rowbase = blockIdx.x * 128;
    const int cg = tid / 64;
    const int rs = tid % 64;

    unsigned long long acc[2][20];
#pragma unroll
    for (int i = 0; i < 2; i++)
#pragma unroll
        for (int c = 0; c < 20; c++) acc[i][c] = 0ull;

    for (int ch = 0; ch < DIN0 / KC; ch++) {
        const int k0 = ch * KC;
        for (int l = tid; l < 128 * KC; l += 512) {
            int r = l / KC, k = l % KC;
            int row = rowbase + r;
            sA[r * SAS + k] = (row < NNODES) ? A[(size_t)row * DIN0 + k0 + k] : 0.f;
        }
        for (int l = tid; l < 160 * KC; l += 512) {
            int kk = l / 160, c = l % 160;
            int cc = (c >= 80) ? c - 80 : c;
            const float* Wsrc = (c >= 80) ? W2 : W1;
            int s = cc / 20, o = cc % 20;
            sWt[c * SAS + kk] = Wsrc[((size_t)s * DIN0 + k0 + kk) * 20 + o];
        }
        __syncthreads();

        const unsigned long long* pa0 = (const unsigned long long*)(sA + rs * SAS);
        const unsigned long long* pa1 = (const unsigned long long*)(sA + (rs + 64) * SAS);
        const float* wbase = sWt + cg * 20 * SAS;
#pragma unroll 5
        for (int kp = 0; kp < KC / 2; kp++) {
            unsigned long long a0 = pa0[kp];
            unsigned long long a1 = pa1[kp];
#pragma unroll
            for (int c = 0; c < 20; c++) {
                unsigned long long w =
                    *(const unsigned long long*)(wbase + c * SAS + 2 * kp);
                acc[0][c] = ffma2(a0, w, acc[0][c]);
                acc[1][c] = ffma2(a1, w, acc[1][c]);
            }
        }
        __syncthreads();
    }

    const int colbase = cg * 20;
#pragma unroll
    for (int i = 0; i < 2; i++) {
        int row = rowbase + rs + i * 64;
        if (row >= NNODES) continue;
        float res[20];
#pragma unroll
        for (int c = 0; c < 20; c++) {
            float lo = __uint_as_float((unsigned)(acc[i][c] & 0xffffffffull));
            float hi = __uint_as_float((unsigned)(acc[i][c] >> 32));
            int col = colbase + c;
            int cc = (col >= 80) ? col - 80 : col;
            const float* bp = (col >= 80) ? b2 : b1;
            res[c] = lo + hi + bp[cc];
        }
        float* dst = (colbase >= 80) ? (outB + (size_t)row * 80 + (colbase - 80))
                                     : (outA + (size_t)row * 80 + colbase);
#pragma unroll
        for (int c = 0; c < 20; c += 4)
            *(float4*)(dst + c) = make_float4(res[c], res[c + 1], res[c + 2], res[c + 3]);
    }
}

// ------------------------- small GEMM with fused BN+LeakyReLU input --------
// Input row = lrelu(BN(cat(preX_row, preY_row))); out = in @ W[4,40,20] + b.
__global__ void __launch_bounds__(256)
gemm_small_bn(const float* __restrict__ preX, const float* __restrict__ preY,
              const float* __restrict__ statsX, const float* __restrict__ statsY,
              const float* __restrict__ gX, const float* __restrict__ betX,
              const float* __restrict__ gY, const float* __restrict__ betY,
              const float* __restrict__ W, const float* __restrict__ b,
              float* __restrict__ out) {
    __shared__ __align__(8) float sW[40][80];
    __shared__ float sb[80];
    __shared__ float sMu[40], sScv[40], sBeta[40];
    const int tid = threadIdx.x;
    for (int l = tid; l < 3200; l += 256) {
        int s = l / 800, rem = l % 800, k = rem / 20, o = rem % 20;
        sW[k][s * 20 + o] = W[l];
    }
    if (tid < 80) sb[tid] = b[tid];
    if (tid < 40) {
        const float invN = 1.f / (float)NNODES;
        int c = tid % 20;
        const float* st = (tid < 20) ? statsX : statsY;
        const float* gg = (tid < 20) ? gX : gY;
        const float* bb = (tid < 20) ? betX : betY;
        float mu = st[c] * invN;
        float var = st[20 + c] * invN - mu * mu;
        sMu[tid] = mu;
        sScv[tid] = gg[c] * rsqrtf(var + EPS_BN);
        sBeta[tid] = bb[c];
    }
    __syncthreads();

    const int row = blockIdx.x * 128 + (tid >> 1);
    const int cb = (tid & 1) * 40;
    if (row >= NNODES) return;

    float a[40];
    {
        const float4* pa = (const float4*)(preX + (size_t)row * 20);
        const float4* pb = (const float4*)(preY + (size_t)row * 20);
        float4 va[5], vb[5];
#pragma unroll
        for (int i = 0; i < 5; i++) va[i] = pa[i];
#pragma unroll
        for (int i = 0; i < 5; i++) vb[i] = pb[i];
#pragma unroll
        for (int i = 0; i < 5; i++) {
            a[4 * i]     = va[i].x; a[4 * i + 1] = va[i].y;
            a[4 * i + 2] = va[i].z; a[4 * i + 3] = va[i].w;
            a[20 + 4 * i]     = vb[i].x; a[21 + 4 * i] = vb[i].y;
            a[22 + 4 * i] = vb[i].z; a[23 + 4 * i] = vb[i].w;
        }
    }
#pragma unroll
    for (int k = 0; k < 40; k++) {
        float v = (a[k] - sMu[k]) * sScv[k] + sBeta[k];
        a[k] = (v >= 0.f) ? v : LSLOPE * v;
    }

    unsigned long long acc[20];
#pragma unroll
    for (int c = 0; c < 20; c++) acc[c] = 0ull;
#pragma unroll 8
    for (int k = 0; k < 40; k++) {
        unsigned long long a2 = pack2(a[k], a[k]);
        const unsigned long long* wrow = (const unsigned long long*)(&sW[k][cb]);
#pragma unroll
        for (int c = 0; c < 20; c++) acc[c] = ffma2(a2, wrow[c], acc[c]);
    }

    float res[40];
#pragma unroll
    for (int c = 0; c < 20; c++) {
        res[2 * c]     = __uint_as_float((unsigned)(acc[c] & 0xffffffffull)) + sb[cb + 2 * c];
        res[2 * c + 1] = __uint_as_float((unsigned)(acc[c] >> 32)) + sb[cb + 2 * c + 1];
    }
    float* dst = out + (size_t)row * 80 + cb;
#pragma unroll
    for (int c = 0; c < 40; c += 4)
        *(float4*)(dst + c) = make_float4(res[c], res[c + 1], res[c + 2], res[c + 3]);
}

// ------------------------- edge kernels -------------------------
__global__ void zero_stats() {
    int i = blockIdx.x * blockDim.x + threadIdx.x;
    if (i < 15 * 40) g_stats[i] = 0.f;
}

// merged A/B edge scatter (blocksPerSet blocks per edge set)
__global__ void __launch_bounds__(256)
edge2(const float* __restrict__ qkvA, const int* __restrict__ eiA,
      float* __restrict__ aggA, float* __restrict__ denomA,
      const float* __restrict__ qkvB, const int* __restrict__ eiB,
      float* __restrict__ aggB, float* __restrict__ denomB, int blocksPerSet) {
    const bool isB = (int)blockIdx.x >= blocksPerSet;
    const float* qkv = isB ? qkvB : qkvA;
    const int* ei = isB ? eiB : eiA;
    float* agg = isB ? aggB : aggA;
    float* denom = isB ? denomB : denomA;
    int bi = isB ? blockIdx.x - blocksPerSet : blockIdx.x;
    int e = bi * 256 + threadIdx.x;
    if (e >= NEDGE) return;
    int s = ei[e], d = ei[NEDGE + e];
    const float4* qp = (const float4*)(qkv + (size_t)d * 80);
    const float4* kp = (const float4*)(qkv + (size_t)s * 80 + 20);
    float dot = 0.f;
#pragma unroll
    for (int i = 0; i < 5; i++) {
        float4 q = qp[i], k = kp[i];
        dot += q.x * k.x + q.y * k.y + q.z * k.z + q.w * k.w;
    }
    float ev = __expf(dot * 0.22360679774997896f);
    atomicAdd(&denom[d], ev);
    const float4* vp = (const float4*)(qkv + (size_t)s * 80 + 40);
    float* ap = agg + (size_t)d * 20;
#pragma unroll
    for (int i = 0; i < 5; i++) {
        float4 v = vp[i];
        red_add4(ap + 4 * i, ev * v.x, ev * v.y, ev * v.z, ev * v.w);
    }
}

// merged A/B finalize: pre = agg/denom + skip, BN stats, self-clean agg/denom
__global__ void __launch_bounds__(256)
finalize2(const float* __restrict__ qkvA, float* __restrict__ aggA,
          float* __restrict__ denomA, float* __restrict__ preA, float* __restrict__ statsA,
          const float* __restrict__ qkvB, float* __restrict__ aggB,
          float* __restrict__ denomB, float* __restrict__ preB, float* __restrict__ statsB,
          int blocksPerSet) {
    const bool isB = (int)blockIdx.x >= blocksPerSet;
    const float* qkv = isB ? qkvB : qkvA;
    float* agg = isB ? aggB : aggA;
    float* denom = isB ? denomB : denomA;
    float* pre = isB ? preB : preA;
    float* stats = isB ? statsB : statsA;
    int bi = isB ? blockIdx.x - blocksPerSet : blockIdx.x;
    int n = bi * 256 + threadIdx.x;

    float s[20], ss[20];
#pragma unroll
    for (int c = 0; c < 20; c++) { s[c] = 0.f; ss[c] = 0.f; }

    if (n < NNODES) {
        float dn = __ldcg(denom + n);
        float4 av[5], sv[5];
        const float4* ap = (const float4*)(agg + (size_t)n * 20);
        const float4* kp = (const float4*)(qkv + (size_t)n * 80 + 60);
#pragma unroll
        for (int i = 0; i < 5; i++) av[i] = __ldcg(ap + i);
#pragma unroll
        for (int i = 0; i < 5; i++) sv[i] = kp[i];
        float inv = 1.f / fmaxf(dn, 1e-16f);
        denom[n] = 0.f;
        float4* apw = (float4*)(agg + (size_t)n * 20);
        float4* pp = (float4*)(pre + (size_t)n * 20);
        const float4 z4 = make_float4(0.f, 0.f, 0.f, 0.f);
#pragma unroll
        for (int i = 0; i < 5; i++) {
            float4 r;
            r.x = av[i].x * inv + sv[i].x; r.y = av[i].y * inv + sv[i].y;
            r.z = av[i].z * inv + sv[i].z; r.w = av[i].w * inv + sv[i].w;
            pp[i] = r;
            apw[i] = z4;
            s[4 * i]     += r.x; ss[4 * i]     += r.x * r.x;
            s[4 * i + 1] += r.y; ss[4 * i + 1] += r.y * r.y;
            s[4 * i + 2] += r.z; ss[4 * i + 2] += r.z * r.z;
            s[4 * i + 3] += r.w; ss[4 * i + 3] += r.w * r.w;
        }
    }
#pragma unroll
    for (int c = 0; c < 20; c++) {
#pragma unroll
        for (int off = 16; off; off >>= 1) {
            s[c] += __shfl_xor_sync(0xffffffffu, s[c], off);
            ss[c] += __shfl_xor_sync(0xffffffffu, ss[c], off);
        }
    }
    __shared__ float red[2][8][20];
    int wid = threadIdx.x >> 5, lane = threadIdx.x & 31;
    if (lane == 0) {
#pragma unroll
        for (int c = 0; c < 20; c++) { red[0][wid][c] = s[c]; red[1][wid][c] = ss[c]; }
    }
    __syncthreads();
    if (threadIdx.x < 40) {
        int which = threadIdx.x / 20, c = threadIdx.x % 20;
        float t = 0.f;
#pragma unroll
        for (int w = 0; w < 8; w++) t += red[which][w][c];
        atomicAdd(&stats[which * 20 + c], t);
    }
}

// BN+lrelu of preC into the fc concat buffer
__global__ void __launch_bounds__(256)
bn_fc(const float* __restrict__ pre, const float* __restrict__ stats,
      const float* __restrict__ gamma, const float* __restrict__ beta,
      float* __restrict__ dst, int off) {
    int idx = blockIdx.x * blockDim.x + threadIdx.x;
    if (idx >= NNODES * 20) return;
    int n = idx / 20, c = idx % 20;
    const float invN = 1.f / (float)NNODES;
    float mu = stats[c] * invN;
    float var = stats[20 + c] * invN - mu * mu;
    float scv = gamma[c] * rsqrtf(var + EPS_BN);
    float v = (pre[idx] - mu) * scv + beta[c];
    v = (v >= 0.f) ? v : LSLOPE * v;
    dst[(size_t)n * 100 + off + c] = v;
}

__global__ void __launch_bounds__(128)
fc_kernel(const float* __restrict__ W, const float* __restrict__ b,
          float* __restrict__ out) {
    __shared__ float sw[200];
    for (int l = threadIdx.x; l < 200; l += blockDim.x) sw[l] = W[l];
    __syncthreads();
    int n = blockIdx.x * blockDim.x + threadIdx.x;
    if (n >= NNODES) return;
    float a0 = b[0], a1 = b[1];
    const float4* fp = (const float4*)(g_fc + (size_t)n * 100);
#pragma unroll
    for (int i = 0; i < 25; i++) {
        float4 f = fp[i];
        int c = 4 * i;
        a0 += f.x * sw[2 * c] + f.y * sw[2 * c + 2] + f.z * sw[2 * c + 4] + f.w * sw[2 * c + 6];
        a1 += f.x * sw[2 * c + 1] + f.y * sw[2 * c + 3] + f.z * sw[2 * c + 5] + f.w * sw[2 * c + 7];
    }
    out[2 * n] = a0;
    out[2 * n + 1] = a1;
}

// ------------------------- host orchestration -------------------------
extern "C" void kernel_launch(void* const* d_in, const int* in_sizes, int n_in,
                              void* d_out, int out_size) {
    (void)in_sizes; (void)n_in; (void)out_size;
    const float* features = (const float*)d_in[0];
    const int* edge_index = (const int*)d_in[3];
    const int* same2      = (const int*)d_in[4];
    const int* diff2      = (const int*)d_in[5];
    const float* c1_W0 = (const float*)d_in[6];
    const float* c1_b0 = (const float*)d_in[7];
    const float* c2_W0 = (const float*)d_in[8];
    const float* c2_b0 = (const float*)d_in[9];
    const float* c1_W  = (const float*)d_in[10];
    const float* c1_b  = (const float*)d_in[11];
    const float* c2_W  = (const float*)d_in[12];
    const float* c2_b  = (const float*)d_in[13];
    const float* c3_W  = (const float*)d_in[14];
    const float* c3_b  = (const float*)d_in[15];
    const float* bn1_g = (const float*)d_in[16];
    const float* bn1_b = (const float*)d_in[17];
    const float* bn2_g = (const float*)d_in[18];
    const float* bn2_b = (const float*)d_in[19];
    const float* bn3_g = (const float*)d_in[20];
    const float* bn3_b = (const float*)d_in[21];
    const float* fc_W  = (const float*)d_in[22];
    const float* fc_b  = (const float*)d_in[23];
    float* out = (float*)d_out;

    float *qkvA, *qkvB, *aggA, *aggB, *denA, *denB, *preA, *preB, *preC, *fcb, *stats;
    cudaGetSymbolAddress((void**)&qkvA, g_qkvA);
    cudaGetSymbolAddress((void**)&qkvB, g_qkvB);
    cudaGetSymbolAddress((void**)&aggA, g_aggA);
    cudaGetSymbolAddress((void**)&aggB, g_aggB);
    cudaGetSymbolAddress((void**)&denA, g_denomA);
    cudaGetSymbolAddress((void**)&denB, g_denomB);
    cudaGetSymbolAddress((void**)&preA, g_preA);
    cudaGetSymbolAddress((void**)&preB, g_preB);
    cudaGetSymbolAddress((void**)&preC, g_preC);
    cudaGetSymbolAddress((void**)&fcb, g_fc);
    cudaGetSymbolAddress((void**)&stats, g_stats);

    const int GB = (NNODES + 127) / 128;
    const int GE = (NEDGE + 255) / 256;
    const int GF = (NNODES + 255) / 256;
    const int GN = (NNODES * 20 + 255) / 256;

    zero_stats<<<3, 256>>>();

    // ---- layer 0 ----
    gemm_big<<<GB, 512>>>(features, c1_W0, c2_W0, c1_b0, c2_b0, qkvA, qkvB);
    edge2<<<2 * GE, 256>>>(qkvA, same2, aggA, denA, qkvB, diff2, aggB, denB, GE);
    finalize2<<<2 * GF, 256>>>(qkvA, aggA, denA, preA, stats + 0 * 40,
                               qkvB, aggB, denB, preB, stats + 1 * 40, GF);

    for (int L = 0; L <= 4; L++) {
        const float* stX = stats + (3 * L) * 40;
        const float* stY = stats + (3 * L + 1) * 40;
        const float* g1 = bn1_g + L * 20; const float* b1 = bn1_b + L * 20;
        const float* g2 = bn2_g + L * 20; const float* b2 = bn2_b + L * 20;

        // c3 conv at layer L (consumes freshly BN'd x1,x2)
        gemm_small_bn<<<GB, 256>>>(preA, preB, stX, stY, g1, b1, g2, b2,
                                   c3_W + (size_t)L * 3200, c3_b + (size_t)L * 80, qkvA);
        edge2<<<GE, 256>>>(qkvA, edge_index, aggA, denA,
                           qkvA, edge_index, aggA, denA, GE);
        finalize2<<<GF, 256>>>(qkvA, aggA, denA, preC, stats + (3 * L + 2) * 40,
                               qkvA, aggA, denA, preC, stats + (3 * L + 2) * 40, GF);
        bn_fc<<<GN, 256>>>(preC, stats + (3 * L + 2) * 40,
                           bn3_g + L * 20, bn3_b + L * 20, fcb, L * 20);

        if (L == 4) break;

        // next-iteration c1/c2 convs (consume same x1,x2; swapped concat for c2)
        gemm_small_bn<<<GB, 256>>>(preA, preB, stX, stY, g1, b1, g2, b2,
                                   c1_W + (size_t)L * 3200, c1_b + (size_t)L * 80, qkvA);
        gemm_small_bn<<<GB, 256>>>(preB, preA, stY, stX, g2, b2, g1, b1,
                                   c2_W + (size_t)L * 3200, c2_b + (size_t)L * 80, qkvB);
        edge2<<<2 * GE, 256>>>(qkvA, same2, aggA, denA, qkvB, diff2, aggB, denB, GE);
        finalize2<<<2 * GF, 256>>>(qkvA, aggA, denA, preA, stats + (3 * L + 3) * 40,
                                   qkvB, aggB, denB, preB, stats + (3 * L + 4) * 40, GF);
    }

    fc_kernel<<<(NNODES + 127) / 128, 128>>>(fc_W, fc_b, out);
}

// round 4
// speedup vs baseline: 1.3159x; 1.1476x over previous
#include <cuda_runtime.h>

#define NNODES 50000
#define NEDGE  1000000
#define DIN0   2000
#define EPS_BN 1e-5f
#define LSLOPE 0.01f
#define KC     40
#define SAS    42
#define NN3    150000          /* 3 sets * NNODES */
#define SCAN_BLOCKS 147        /* ceil(150000/1024) */

// ------------------------- scratch (device globals, zero-init) -------------
__device__ float g_qkvA[NNODES * 80];
__device__ float g_qkvB[NNODES * 80];
__device__ float g_preA[NNODES * 20];
__device__ float g_preB[NNODES * 20];
__device__ float g_preC[NNODES * 20];
__device__ float g_fc[NNODES * 100];
__device__ float g_stats[15 * 40];
// CSR scratch
__device__ int g_cnt[NN3];
__device__ int g_off[NN3 + 1];
__device__ int g_cur[NN3];
__device__ int g_csr[3 * NEDGE];
__device__ int g_partraw[SCAN_BLOCKS];
__device__ int g_part[SCAN_BLOCKS];

// ------------------------- helpers -------------------------
__device__ __forceinline__ unsigned long long ffma2(unsigned long long a,
                                                    unsigned long long b,
                                                    unsigned long long c) {
    unsigned long long d;
    asm("fma.rn.f32x2 %0, %1, %2, %3;" : "=l"(d) : "l"(a), "l"(b), "l"(c));
    return d;
}
__device__ __forceinline__ unsigned long long pack2(float lo, float hi) {
    unsigned long long r;
    asm("mov.b64 %0, {%1, %2};" : "=l"(r) : "f"(lo), "f"(hi));
    return r;
}

// ------------------------- CSR build -------------------------
__global__ void zero_all() {
    int i = blockIdx.x * blockDim.x + threadIdx.x;
    if (i < NN3) g_cnt[i] = 0;
    if (i < 15 * 40) g_stats[i] = 0.f;
}

__global__ void hist_kernel(const int* __restrict__ e0, const int* __restrict__ e1,
                            const int* __restrict__ e2) {
    int i = blockIdx.x * blockDim.x + threadIdx.x;
    if (i >= 3 * NEDGE) return;
    int set = i / NEDGE, e = i - set * NEDGE;
    const int* ei = (set == 0) ? e0 : ((set == 1) ? e1 : e2);
    int d = ei[NEDGE + e];
    atomicAdd(&g_cnt[set * NNODES + d], 1);
}

__global__ void __launch_bounds__(1024) scanA() {
    int gid = blockIdx.x * 1024 + threadIdx.x;
    int v = (gid < NN3) ? g_cnt[gid] : 0;
#pragma unroll
    for (int o = 16; o; o >>= 1) v += __shfl_xor_sync(~0u, v, o);
    __shared__ int sw[32];
    if ((threadIdx.x & 31) == 0) sw[threadIdx.x >> 5] = v;
    __syncthreads();
    if (threadIdx.x < 32) {
        int t = sw[threadIdx.x];
#pragma unroll
        for (int o = 16; o; o >>= 1) t += __shfl_xor_sync(~0u, t, o);
        if (threadIdx.x == 0) g_partraw[blockIdx.x] = t;
    }
}

__global__ void scanB() {
    __shared__ int sp[SCAN_BLOCKS + 1];
    int tid = threadIdx.x;
    if (tid < SCAN_BLOCKS) sp[tid + 1] = g_partraw[tid];
    if (tid == 0) sp[0] = 0;
    __syncthreads();
    if (tid == 0)
        for (int b = 1; b <= SCAN_BLOCKS; b++) sp[b] += sp[b - 1];
    __syncthreads();
    if (tid < SCAN_BLOCKS) g_part[tid] = sp[tid];
}

__global__ void __launch_bounds__(1024) scanC() {
    __shared__ int sdat[1024];
    int tid = threadIdx.x;
    int gid = blockIdx.x * 1024 + tid;
    int v = (gid < NN3) ? g_cnt[gid] : 0;
    sdat[tid] = v;
    __syncthreads();
    for (int o = 1; o < 1024; o <<= 1) {
        int t = (tid >= o) ? sdat[tid - o] : 0;
        __syncthreads();
        sdat[tid] += t;
        __syncthreads();
    }
    int excl = sdat[tid] - v + g_part[blockIdx.x];
    if (gid < NN3) { g_off[gid] = excl; g_cur[gid] = excl; }
    if (gid == 0) g_off[NN3] = 3 * NEDGE;
}

__global__ void scatter_kernel(const int* __restrict__ e0, const int* __restrict__ e1,
                               const int* __restrict__ e2) {
    int i = blockIdx.x * blockDim.x + threadIdx.x;
    if (i >= 3 * NEDGE) return;
    int set = i / NEDGE, e = i - set * NEDGE;
    const int* ei = (set == 0) ? e0 : ((set == 1) ? e1 : e2);
    int s = ei[e], d = ei[NEDGE + e];
    int pos = atomicAdd(&g_cur[set * NNODES + d], 1);
    g_csr[pos] = s;
}

// ------------------------- big GEMM (f32x2, Din=2000, 160 cols) ------------
__global__ void __launch_bounds__(512, 1)
gemm_big(const float* __restrict__ A,
         const float* __restrict__ W1, const float* __restrict__ W2,
         const float* __restrict__ b1, const float* __restrict__ b2,
         float* __restrict__ outA, float* __restrict__ outB) {
    __shared__ __align__(16) float sA[128 * SAS];
    __shared__ __align__(16) float sWt[160 * SAS];

    const int tid = threadIdx.x;
    const int rowbase = blockIdx.x * 128;
    const int cg = tid / 64;
    const int rs = tid % 64;

    unsigned long long acc[2][20];
#pragma unroll
    for (int i = 0; i < 2; i++)
#pragma unroll
        for (int c = 0; c < 20; c++) acc[i][c] = 0ull;

    for (int ch = 0; ch < DIN0 / KC; ch++) {
        const int k0 = ch * KC;
        for (int l = tid; l < 128 * KC; l += 512) {
            int r = l / KC, k = l % KC;
            int row = rowbase + r;
            sA[r * SAS + k] = (row < NNODES) ? A[(size_t)row * DIN0 + k0 + k] : 0.f;
        }
        for (int l = tid; l < 160 * KC; l += 512) {
            int kk = l / 160, c = l % 160;
            int cc = (c >= 80) ? c - 80 : c;
            const float* Wsrc = (c >= 80) ? W2 : W1;
            int s = cc / 20, o = cc % 20;
            sWt[c * SAS + kk] = Wsrc[((size_t)s * DIN0 + k0 + kk) * 20 + o];
        }
        __syncthreads();

        const unsigned long long* pa0 = (const unsigned long long*)(sA + rs * SAS);
        const unsigned long long* pa1 = (const unsigned long long*)(sA + (rs + 64) * SAS);
        const float* wbase = sWt + cg * 20 * SAS;
#pragma unroll 5
        for (int kp = 0; kp < KC / 2; kp++) {
            unsigned long long a0 = pa0[kp];
            unsigned long long a1 = pa1[kp];
#pragma unroll
            for (int c = 0; c < 20; c++) {
                unsigned long long w =
                    *(const unsigned long long*)(wbase + c * SAS + 2 * kp);
                acc[0][c] = ffma2(a0, w, acc[0][c]);
                acc[1][c] = ffma2(a1, w, acc[1][c]);
            }
        }
        __syncthreads();
    }

    const int colbase = cg * 20;
#pragma unroll
    for (int i = 0; i < 2; i++) {
        int row = rowbase + rs + i * 64;
        if (row >= NNODES) continue;
        float res[20];
#pragma unroll
        for (int c = 0; c < 20; c++) {
            float lo = __uint_as_float((unsigned)(acc[i][c] & 0xffffffffull));
            float hi = __uint_as_float((unsigned)(acc[i][c] >> 32));
            int col = colbase + c;
            int cc = (col >= 80) ? col - 80 : col;
            const float* bp = (col >= 80) ? b2 : b1;
            res[c] = lo + hi + bp[cc];
        }
        float* dst = (colbase >= 80) ? (outB + (size_t)row * 80 + (colbase - 80))
                                     : (outA + (size_t)row * 80 + colbase);
#pragma unroll
        for (int c = 0; c < 20; c += 4)
            *(float4*)(dst + c) = make_float4(res[c], res[c + 1], res[c + 2], res[c + 3]);
    }
}

// ------------------------- small GEMM with fused BN+LeakyReLU --------------
__global__ void __launch_bounds__(256)
gemm_small_bn(const float* __restrict__ preX, const float* __restrict__ preY,
              const float* __restrict__ statsX, const float* __restrict__ statsY,
              const float* __restrict__ gX, const float* __restrict__ betX,
              const float* __restrict__ gY, const float* __restrict__ betY,
              const float* __restrict__ W, const float* __restrict__ b,
              float* __restrict__ out) {
    __shared__ __align__(8) float sW[40][80];
    __shared__ float sb[80];
    __shared__ float sMu[40], sScv[40], sBeta[40];
    const int tid = threadIdx.x;
    for (int l = tid; l < 3200; l += 256) {
        int s = l / 800, rem = l % 800, k = rem / 20, o = rem % 20;
        sW[k][s * 20 + o] = W[l];
    }
    if (tid < 80) sb[tid] = b[tid];
    if (tid < 40) {
        const float invN = 1.f / (float)NNODES;
        int c = tid % 20;
        const float* st = (tid < 20) ? statsX : statsY;
        const float* gg = (tid < 20) ? gX : gY;
        const float* bb = (tid < 20) ? betX : betY;
        float mu = st[c] * invN;
        float var = st[20 + c] * invN - mu * mu;
        sMu[tid] = mu;
        sScv[tid] = gg[c] * rsqrtf(var + EPS_BN);
        sBeta[tid] = bb[c];
    }
    __syncthreads();

    const int row = blockIdx.x * 128 + (tid >> 1);
    const int cb = (tid & 1) * 40;
    if (row >= NNODES) return;

    float a[40];
    {
        const float4* pa = (const float4*)(preX + (size_t)row * 20);
        const float4* pb = (const float4*)(preY + (size_t)row * 20);
        float4 va[5], vb[5];
#pragma unroll
        for (int i = 0; i < 5; i++) va[i] = pa[i];
#pragma unroll
        for (int i = 0; i < 5; i++) vb[i] = pb[i];
#pragma unroll
        for (int i = 0; i < 5; i++) {
            a[4 * i]     = va[i].x; a[4 * i + 1] = va[i].y;
            a[4 * i + 2] = va[i].z; a[4 * i + 3] = va[i].w;
            a[20 + 4 * i] = vb[i].x; a[21 + 4 * i] = vb[i].y;
            a[22 + 4 * i] = vb[i].z; a[23 + 4 * i] = vb[i].w;
        }
    }
#pragma unroll
    for (int k = 0; k < 40; k++) {
        float v = (a[k] - sMu[k]) * sScv[k] + sBeta[k];
        a[k] = (v >= 0.f) ? v : LSLOPE * v;
    }

    unsigned long long acc[20];
#pragma unroll
    for (int c = 0; c < 20; c++) acc[c] = 0ull;
#pragma unroll 8
    for (int k = 0; k < 40; k++) {
        unsigned long long a2 = pack2(a[k], a[k]);
        const unsigned long long* wrow = (const unsigned long long*)(&sW[k][cb]);
#pragma unroll
        for (int c = 0; c < 20; c++) acc[c] = ffma2(a2, wrow[c], acc[c]);
    }

    float res[40];
#pragma unroll
    for (int c = 0; c < 20; c++) {
        res[2 * c]     = __uint_as_float((unsigned)(acc[c] & 0xffffffffull)) + sb[cb + 2 * c];
        res[2 * c + 1] = __uint_as_float((unsigned)(acc[c] >> 32)) + sb[cb + 2 * c + 1];
    }
    float* dst = out + (size_t)row * 80 + cb;
#pragma unroll
    for (int c = 0; c < 40; c += 4)
        *(float4*)(dst + c) = make_float4(res[c], res[c + 1], res[c + 2], res[c + 3]);
}

// ------------------------- CSR aggregation (softmax attention) -------------
// One warp per dst node, lane c<20 owns channel c. Computes
// pre = (sum_e exp(dot_e) * v[src_e]) / sum_e exp(dot_e) + skip, plus BN stats.
__global__ void __launch_bounds__(256)
agg_csr(const float* __restrict__ qkvA, int baseA, float* __restrict__ preA,
        float* __restrict__ statsA,
        const float* __restrict__ qkvB, int baseB, float* __restrict__ preB,
        float* __restrict__ statsB, int blocksPerSet) {
    const bool isB = (int)blockIdx.x >= blocksPerSet;
    const float* qkv = isB ? qkvB : qkvA;
    float* pre = isB ? preB : preA;
    float* stats = isB ? statsB : statsA;
    const int nbase = isB ? baseB : baseA;
    const int bi = isB ? blockIdx.x - blocksPerSet : blockIdx.x;

    const int wid = threadIdx.x >> 5, lane = threadIdx.x & 31;
    const int n = bi * 8 + wid;
    const bool act = lane < 20;
    const int c = lane;

    __shared__ float sst[2][8][20];
    for (int l = threadIdx.x; l < 320; l += 256) ((float*)sst)[l] = 0.f;
    __syncthreads();

    if (n < NNODES) {
        const int gi = nbase + n;
        const int off0 = g_off[gi], off1 = g_off[gi + 1];
        const float qc = act ? qkv[(size_t)n * 80 + c] * 0.22360679774997896f : 0.f;
        float acc = 0.f, denom = 0.f;
        int p = off0;
        for (; p + 2 <= off1; p += 2) {
            int s0 = g_csr[p], s1 = g_csr[p + 1];
            float k0 = 0.f, k1 = 0.f, v0 = 0.f, v1 = 0.f;
            if (act) {
                k0 = qkv[(size_t)s0 * 80 + 20 + c];
                k1 = qkv[(size_t)s1 * 80 + 20 + c];
                v0 = qkv[(size_t)s0 * 80 + 40 + c];
                v1 = qkv[(size_t)s1 * 80 + 40 + c];
            }
            float d0 = qc * k0, d1 = qc * k1;
#pragma unroll
            for (int o = 16; o; o >>= 1) {
                d0 += __shfl_xor_sync(~0u, d0, o);
                d1 += __shfl_xor_sync(~0u, d1, o);
            }
            float e0 = __expf(d0), e1 = __expf(d1);
            denom += e0 + e1;
            acc += e0 * v0 + e1 * v1;
        }
        if (p < off1) {
            int s0 = g_csr[p];
            float k0 = act ? qkv[(size_t)s0 * 80 + 20 + c] : 0.f;
            float v0 = act ? qkv[(size_t)s0 * 80 + 40 + c] : 0.f;
            float d0 = qc * k0;
#pragma unroll
            for (int o = 16; o; o >>= 1) d0 += __shfl_xor_sync(~0u, d0, o);
            float e0 = __expf(d0);
            denom += e0;
            acc += e0 * v0;
        }
        float inv = 1.f / fmaxf(denom, 1e-16f);
        if (act) {
            float r = acc * inv + qkv[(size_t)n * 80 + 60 + c];
            pre[(size_t)n * 20 + c] = r;
            sst[0][wid][c] = r;
            sst[1][wid][c] = r * r;
        }
    }
    __syncthreads();
    if (threadIdx.x < 40) {
        int which = threadIdx.x / 20, cc = threadIdx.x % 20;
        float t = 0.f;
#pragma unroll
        for (int w = 0; w < 8; w++) t += sst[which][w][cc];
        atomicAdd(&stats[which * 20 + cc], t);
    }
}

// ------------------------- BN into fc buffer, final FC -------------------
__global__ void __launch_bounds__(256)
bn_fc(const float* __restrict__ pre, const float* __restrict__ stats,
      const float* __restrict__ gamma, const float* __restrict__ beta,
      float* __restrict__ dst, int off) {
    int idx = blockIdx.x * blockDim.x + threadIdx.x;
    if (idx >= NNODES * 20) return;
    int n = idx / 20, c = idx % 20;
    const float invN = 1.f / (float)NNODES;
    float mu = stats[c] * invN;
    float var = stats[20 + c] * invN - mu * mu;
    float scv = gamma[c] * rsqrtf(var + EPS_BN);
    float v = (pre[idx] - mu) * scv + beta[c];
    v = (v >= 0.f) ? v : LSLOPE * v;
    dst[(size_t)n * 100 + off + c] = v;
}

__global__ void __launch_bounds__(128)
fc_kernel(const float* __restrict__ W, const float* __restrict__ b,
          float* __restrict__ out) {
    __shared__ float sw[200];
    for (int l = threadIdx.x; l < 200; l += blockDim.x) sw[l] = W[l];
    __syncthreads();
    int n = blockIdx.x * blockDim.x + threadIdx.x;
    if (n >= NNODES) return;
    float a0 = b[0], a1 = b[1];
    const float4* fp = (const float4*)(g_fc + (size_t)n * 100);
#pragma unroll
    for (int i = 0; i < 25; i++) {
        float4 f = fp[i];
        int c = 4 * i;
        a0 += f.x * sw[2 * c] + f.y * sw[2 * c + 2] + f.z * sw[2 * c + 4] + f.w * sw[2 * c + 6];
        a1 += f.x * sw[2 * c + 1] + f.y * sw[2 * c + 3] + f.z * sw[2 * c + 5] + f.w * sw[2 * c + 7];
    }
    out[2 * n] = a0;
    out[2 * n + 1] = a1;
}

// ------------------------- host orchestration -------------------------
extern "C" void kernel_launch(void* const* d_in, const int* in_sizes, int n_in,
                              void* d_out, int out_size) {
    (void)in_sizes; (void)n_in; (void)out_size;
    const float* features = (const float*)d_in[0];
    const int* edge_index = (const int*)d_in[3];
    const int* same2      = (const int*)d_in[4];
    const int* diff2      = (const int*)d_in[5];
    const float* c1_W0 = (const float*)d_in[6];
    const float* c1_b0 = (const float*)d_in[7];
    const float* c2_W0 = (const float*)d_in[8];
    const float* c2_b0 = (const float*)d_in[9];
    const float* c1_W  = (const float*)d_in[10];
    const float* c1_b  = (const float*)d_in[11];
    const float* c2_W  = (const float*)d_in[12];
    const float* c2_b  = (const float*)d_in[13];
    const float* c3_W  = (const float*)d_in[14];
    const float* c3_b  = (const float*)d_in[15];
    const float* bn1_g = (const float*)d_in[16];
    const float* bn1_b = (const float*)d_in[17];
    const float* bn2_g = (const float*)d_in[18];
    const float* bn2_b = (const float*)d_in[19];
    const float* bn3_g = (const float*)d_in[20];
    const float* bn3_b = (const float*)d_in[21];
    const float* fc_W  = (const float*)d_in[22];
    const float* fc_b  = (const float*)d_in[23];
    float* out = (float*)d_out;

    float *qkvA, *qkvB, *preA, *preB, *preC, *fcb, *stats;
    cudaGetSymbolAddress((void**)&qkvA, g_qkvA);
    cudaGetSymbolAddress((void**)&qkvB, g_qkvB);
    cudaGetSymbolAddress((void**)&preA, g_preA);
    cudaGetSymbolAddress((void**)&preB, g_preB);
    cudaGetSymbolAddress((void**)&preC, g_preC);
    cudaGetSymbolAddress((void**)&fcb, g_fc);
    cudaGetSymbolAddress((void**)&stats, g_stats);

    const int GB = (NNODES + 127) / 128;
    const int G3E = (3 * NEDGE + 255) / 256;
    const int GA = (NNODES + 7) / 8;           // agg: 8 nodes/block
    const int GN = (NNODES * 20 + 255) / 256;

    // ---- CSR build (once per call; reused by all 15 conv layers) ----
    zero_all<<<(NN3 + 255) / 256, 256>>>();
    hist_kernel<<<G3E, 256>>>(same2, diff2, edge_index);
    scanA<<<SCAN_BLOCKS, 1024>>>();
    scanB<<<1, 256>>>();
    scanC<<<SCAN_BLOCKS, 1024>>>();
    scatter_kernel<<<G3E, 256>>>(same2, diff2, edge_index);

    // ---- layer 0 ----
    gemm_big<<<GB, 512>>>(features, c1_W0, c2_W0, c1_b0, c2_b0, qkvA, qkvB);
    agg_csr<<<2 * GA, 256>>>(qkvA, 0, preA, stats + 0 * 40,
                             qkvB, NNODES, preB, stats + 1 * 40, GA);

    for (int L = 0; L <= 4; L++) {
        const float* stX = stats + (3 * L) * 40;
        const float* stY = stats + (3 * L + 1) * 40;
        const float* g1 = bn1_g + L * 20; const float* b1 = bn1_b + L * 20;
        const float* g2 = bn2_g + L * 20; const float* b2 = bn2_b + L * 20;

        gemm_small_bn<<<GB, 256>>>(preA, preB, stX, stY, g1, b1, g2, b2,
                                   c3_W + (size_t)L * 3200, c3_b + (size_t)L * 80, qkvA);
        agg_csr<<<GA, 256>>>(qkvA, 2 * NNODES, preC, stats + (3 * L + 2) * 40,
                             qkvA, 2 * NNODES, preC, stats + (3 * L + 2) * 40, GA);
        bn_fc<<<GN, 256>>>(preC, stats + (3 * L + 2) * 40,
                           bn3_g + L * 20, bn3_b + L * 20, fcb, L * 20);

        if (L == 4) break;

        gemm_small_bn<<<GB, 256>>>(preA, preB, stX, stY, g1, b1, g2, b2,
                                   c1_W + (size_t)L * 3200, c1_b + (size_t)L * 80, qkvA);
        gemm_small_bn<<<GB, 256>>>(preB, preA, stY, stX, g2, b2, g1, b1,
                                   c2_W + (size_t)L * 3200, c2_b + (size_t)L * 80, qkvB);
        agg_csr<<<2 * GA, 256>>>(qkvA, 0, preA, stats + (3 * L + 3) * 40,
                                 qkvB, NNODES, preB, stats + (3 * L + 4) * 40, GA);
    }

    fc_kernel<<<(NNODES + 127) / 128, 128>>>(fc_W, fc_b, out);
}

// round 7
// speedup vs baseline: 2.1747x; 1.6527x over previous
#include <cuda_runtime.h>
#include <cuda_bf16.h>
#include <cstdint>

#define NNODES 50000
#define NEDGE  1000000
#define DIN0   2000
#define EPS_BN 1e-5f
#define LSLOPE 0.01f
#define NN3    150000
#define SCAN_BLOCKS 147

// ------------------------- scratch (device globals, zero-init) -------------
__device__ float g_qkvA[NNODES * 80];
__device__ float g_qkvB[NNODES * 80];
__device__ float g_preA[NNODES * 20];
__device__ float g_preB[NNODES * 20];
__device__ float g_preC[NNODES * 20];
__device__ float g_fc[NNODES * 100];
__device__ float g_stats[15 * 40];
__device__ __nv_bfloat16 g_wt_hi[2000 * 160];  // [k][n] transposed weights
__device__ __nv_bfloat16 g_wt_lo[2000 * 160];
// CSR scratch
__device__ int g_cnt[NN3];
__device__ int g_off[NN3 + 1];
__device__ int g_cur[NN3];
__device__ int g_csr[3 * NEDGE];
__device__ int g_partraw[SCAN_BLOCKS];
__device__ int g_part[SCAN_BLOCKS];

// ------------------------- helpers -------------------------
__device__ __forceinline__ unsigned long long ffma2(unsigned long long a,
                                                    unsigned long long b,
                                                    unsigned long long c) {
    unsigned long long d;
    asm("fma.rn.f32x2 %0, %1, %2, %3;" : "=l"(d) : "l"(a), "l"(b), "l"(c));
    return d;
}
__device__ __forceinline__ unsigned long long pack2(float lo, float hi) {
    unsigned long long r;
    asm("mov.b64 %0, {%1, %2};" : "=l"(r) : "f"(lo), "f"(hi));
    return r;
}
__device__ __forceinline__ uint32_t smem_u32(const void* p) {
    uint32_t a;
    asm("{ .reg .u64 t; cvta.to.shared.u64 t, %1; cvt.u32.u64 %0, t; }"
        : "=r"(a) : "l"(p));
    return a;
}
__device__ __forceinline__ uint32_t packbf2(float a, float b, float* lo_a, float* lo_b) {
    __nv_bfloat16 ha = __float2bfloat16(a), hb = __float2bfloat16(b);
    *lo_a = a - __bfloat162float(ha);
    *lo_b = b - __bfloat162float(hb);
    __nv_bfloat162 p; p.x = ha; p.y = hb;
    return *(uint32_t*)&p;
}
__device__ __forceinline__ uint32_t packbf2s(float a, float b) {
    __nv_bfloat162 p; p.x = __float2bfloat16(a); p.y = __float2bfloat16(b);
    return *(uint32_t*)&p;
}

// ------------------------- CSR build -------------------------
__global__ void zero_all() {
    int i = blockIdx.x * blockDim.x + threadIdx.x;
    if (i < NN3) g_cnt[i] = 0;
    if (i < 15 * 40) g_stats[i] = 0.f;
}
__global__ void hist_kernel(const int* __restrict__ e0, const int* __restrict__ e1,
                            const int* __restrict__ e2) {
    int i = blockIdx.x * blockDim.x + threadIdx.x;
    if (i >= 3 * NEDGE) return;
    int set = i / NEDGE, e = i - set * NEDGE;
    const int* ei = (set == 0) ? e0 : ((set == 1) ? e1 : e2);
    atomicAdd(&g_cnt[set * NNODES + ei[NEDGE + e]], 1);
}
__global__ void __launch_bounds__(1024) scanA() {
    int gid = blockIdx.x * 1024 + threadIdx.x;
    int v = (gid < NN3) ? g_cnt[gid] : 0;
#pragma unroll
    for (int o = 16; o; o >>= 1) v += __shfl_xor_sync(~0u, v, o);
    __shared__ int sw[32];
    if ((threadIdx.x & 31) == 0) sw[threadIdx.x >> 5] = v;
    __syncthreads();
    if (threadIdx.x < 32) {
        int t = sw[threadIdx.x];
#pragma unroll
        for (int o = 16; o; o >>= 1) t += __shfl_xor_sync(~0u, t, o);
        if (threadIdx.x == 0) g_partraw[blockIdx.x] = t;
    }
}
__global__ void scanB() {
    __shared__ int sp[SCAN_BLOCKS + 1];
    int tid = threadIdx.x;
    if (tid < SCAN_BLOCKS) sp[tid + 1] = g_partraw[tid];
    if (tid == 0) sp[0] = 0;
    __syncthreads();
    if (tid == 0)
        for (int b = 1; b <= SCAN_BLOCKS; b++) sp[b] += sp[b - 1];
    __syncthreads();
    if (tid < SCAN_BLOCKS) g_part[tid] = sp[tid];
}
__global__ void __launch_bounds__(1024) scanC() {
    __shared__ int sdat[1024];
    int tid = threadIdx.x;
    int gid = blockIdx.x * 1024 + tid;
    int v = (gid < NN3) ? g_cnt[gid] : 0;
    sdat[tid] = v;
    __syncthreads();
    for (int o = 1; o < 1024; o <<= 1) {
        int t = (tid >= o) ? sdat[tid - o] : 0;
        __syncthreads();
        sdat[tid] += t;
        __syncthreads();
    }
    int excl = sdat[tid] - v + g_part[blockIdx.x];
    if (gid < NN3) { g_off[gid] = excl; g_cur[gid] = excl; }
    if (gid == 0) g_off[NN3] = 3 * NEDGE;
}
__global__ void scatter_kernel(const int* __restrict__ e0, const int* __restrict__ e1,
                               const int* __restrict__ e2) {
    int i = blockIdx.x * blockDim.x + threadIdx.x;
    if (i >= 3 * NEDGE) return;
    int set = i / NEDGE, e = i - set * NEDGE;
    const int* ei = (set == 0) ? e0 : ((set == 1) ? e1 : e2);
    int s = ei[e], d = ei[NEDGE + e];
    int pos = atomicAdd(&g_cur[set * NNODES + d], 1);
    g_csr[pos] = s;
}

// ------------- W split+transpose (fp32 [4,2000,20]x2 -> bf16 [2000][160]) --
__global__ void conv_w(const float* __restrict__ W1, const float* __restrict__ W2) {
    int idx = blockIdx.x * blockDim.x + threadIdx.x;
    if (idx >= 2000 * 160) return;
    int k = idx / 160, n = idx - k * 160;
    const float* Wsrc = (n < 80) ? W1 : W2;
    int nn = (n < 80) ? n : n - 80;
    int s = nn / 20, o = nn % 20;
    float w = Wsrc[((size_t)s * 2000 + k) * 20 + o];
    __nv_bfloat16 h = __float2bfloat16(w);
    g_wt_hi[idx] = h;
    g_wt_lo[idx] = __float2bfloat16(w - __bfloat162float(h));
}

// ------------------------- big GEMM via mma.sync bf16-split ----------------
// D[128,160] = A[128,2000] @ W[2000,160]. Split products hi*hi + hi*lo + lo*hi
// realized via address tables over dedup'd smem sections A=[hi|lo], B=[hi|lo].
#define SA_STRIDE 168  /* bf16; 336B rows -> conflict-free ldmatrix */
#define SB_STRIDE 168

__global__ void __launch_bounds__(256)
gemm_big_mma(const float* __restrict__ A,
             const float* __restrict__ b1, const float* __restrict__ b2,
             float* __restrict__ outA, float* __restrict__ outB) {
    extern __shared__ __align__(16) char dsm[];
    __nv_bfloat16* sA = (__nv_bfloat16*)dsm;                          // [128][168]
    __nv_bfloat16* sB = (__nv_bfloat16*)(dsm + 128 * SA_STRIDE * 2);  // [160][168]
    __shared__ float s_bias[160];

    const int tid = threadIdx.x, wid = tid >> 5, lane = tid & 31;
    const int rowbase = blockIdx.x * 128;
    if (tid < 160) s_bias[tid] = (tid < 80) ? b1[tid] : b2[tid - 80];

    float acc[20][4];
#pragma unroll
    for (int t = 0; t < 20; t++)
#pragma unroll
        for (int i = 0; i < 4; i++) acc[t][i] = 0.f;

    // per-lane ldmatrix base addresses
    const int r_in = lane & 7, blkb = (lane >> 3) & 1, kh = (lane >> 4) & 1;
    const uint32_t aBase =
        smem_u32(sA) + (uint32_t)((wid * 16 + blkb * 8 + r_in) * SA_STRIDE + kh * 8) * 2;
    const uint32_t bBase = smem_u32(sB) + (uint32_t)((lane & 15) * SB_STRIDE) * 2;

    // physical k offsets per kstep: sections A=[hi(0-79)|lo(80-159)], B same.
    const int aoff[15] = {0, 16, 32, 48, 64, 0, 16, 32, 48, 64, 80, 96, 112, 128, 144};
    const int boff[15] = {0, 16, 32, 48, 64, 80, 96, 112, 128, 144, 0, 16, 32, 48, 64};

    const uint32_t* whi = (const uint32_t*)g_wt_hi;
    const uint32_t* wlo = (const uint32_t*)g_wt_lo;

    for (int ch = 0; ch < 25; ch++) {
        const int k0 = ch * 80;
        // ---- stage A: 128 rows x 80 k fp32 -> bf16 hi/lo sections ----
#pragma unroll
        for (int it = 0; it < 10; it++) {
            int q = tid + it * 256;
            int r = q / 20, f = q - r * 20;
            int row = rowbase + r;
            float4 v = (row < NNODES)
                           ? *(const float4*)(A + (size_t)row * 2000 + k0 + f * 4)
                           : make_float4(0.f, 0.f, 0.f, 0.f);
            float l0, l1, l2, l3;
            uint32_t h0 = packbf2(v.x, v.y, &l0, &l1);
            uint32_t h1 = packbf2(v.z, v.w, &l2, &l3);
            uint32_t p0 = packbf2s(l0, l1), p1 = packbf2s(l2, l3);
            int k = f * 4;
            __nv_bfloat16* rp = sA + r * SA_STRIDE;
            *(uint32_t*)(rp + k) = h0;
            *(uint32_t*)(rp + k + 2) = h1;
            *(uint32_t*)(rp + 80 + k) = p0;
            *(uint32_t*)(rp + 82 + k) = p1;
        }
        // ---- stage B: 80 k-rows x 160 n, hi + lo ----
#pragma unroll
        for (int it = 0; it < 25; it++) {
            int q = tid + it * 256;             // 0..6399 (u32 units)
            int kk = q / 80, nu = q - kk * 80;  // nu: u32 col (2 bf16)
            size_t src = (size_t)(k0 + kk) * 80 + nu;
            uint32_t h = whi[src], l = wlo[src];
            *(uint32_t*)(sB + kk * SB_STRIDE + nu * 2) = h;
            *(uint32_t*)(sB + (80 + kk) * SB_STRIDE + nu * 2) = l;
        }
        __syncthreads();
        // ---- compute: 15 ksteps x 20 n-tiles ----
#pragma unroll
        for (int j = 0; j < 15; j++) {
            uint32_t a0, a1, a2, a3;
            asm volatile(
                "ldmatrix.sync.aligned.m8n8.x4.shared.b16 {%0,%1,%2,%3}, [%4];"
                : "=r"(a0), "=r"(a1), "=r"(a2), "=r"(a3)
                : "r"(aBase + (uint32_t)aoff[j] * 2));
            const uint32_t bko = bBase + (uint32_t)(boff[j] * SB_STRIDE) * 2;
#pragma unroll
            for (int t = 0; t < 20; t++) {
                uint32_t b0, b1;
                asm volatile(
                    "ldmatrix.sync.aligned.m8n8.x2.trans.shared.b16 {%0,%1}, [%2];"
                    : "=r"(b0), "=r"(b1)
                    : "r"(bko + (uint32_t)t * 16));
                asm volatile(
                    "mma.sync.aligned.m16n8k16.row.col.f32.bf16.bf16.f32 "
                    "{%0,%1,%2,%3}, {%4,%5,%6,%7}, {%8,%9}, {%0,%1,%2,%3};"
                    : "+f"(acc[t][0]), "+f"(acc[t][1]), "+f"(acc[t][2]), "+f"(acc[t][3])
                    : "r"(a0), "r"(a1), "r"(a2), "r"(a3), "r"(b0), "r"(b1));
            }
        }
        __syncthreads();
    }

    // ---- epilogue ----
    const int r0 = rowbase + wid * 16 + lane / 4;
    const int r1 = r0 + 8;
    const int cb = (lane & 3) * 2;
#pragma unroll
    for (int t = 0; t < 20; t++) {
        int col = t * 8 + cb;
        float* base = (col < 80) ? outA : outB;
        int cc = (col < 80) ? col : col - 80;
        float bia0 = s_bias[col], bia1 = s_bias[col + 1];
        if (r0 < NNODES)
            *(float2*)(base + (size_t)r0 * 80 + cc) =
                make_float2(acc[t][0] + bia0, acc[t][1] + bia1);
        if (r1 < NNODES)
            *(float2*)(base + (size_t)r1 * 80 + cc) =
                make_float2(acc[t][2] + bia0, acc[t][3] + bia1);
    }
}

// ------------------------- small GEMM with fused BN+LeakyReLU --------------
__global__ void __launch_bounds__(256)
gemm_small_bn(const float* __restrict__ preX, const float* __restrict__ preY,
              const float* __restrict__ statsX, const float* __restrict__ statsY,
              const float* __restrict__ gX, const float* __restrict__ betX,
              const float* __restrict__ gY, const float* __restrict__ betY,
              const float* __restrict__ W, const float* __restrict__ b,
              float* __restrict__ out) {
    __shared__ __align__(8) float sW[40][80];
    __shared__ float sb[80];
    __shared__ float sMu[40], sScv[40], sBeta[40];
    const int tid = threadIdx.x;
    for (int l = tid; l < 3200; l += 256) {
        int s = l / 800, rem = l % 800, k = rem / 20, o = rem % 20;
        sW[k][s * 20 + o] = W[l];
    }
    if (tid < 80) sb[tid] = b[tid];
    if (tid < 40) {
        const float invN = 1.f / (float)NNODES;
        int c = tid % 20;
        const float* st = (tid < 20) ? statsX : statsY;
        const float* gg = (tid < 20) ? gX : gY;
        const float* bb = (tid < 20) ? betX : betY;
        float mu = st[c] * invN;
        float var = st[20 + c] * invN - mu * mu;
        sMu[tid] = mu;
        sScv[tid] = gg[c] * rsqrtf(var + EPS_BN);
        sBeta[tid] = bb[c];
    }
    __syncthreads();

    const int row = blockIdx.x * 128 + (tid >> 1);
    const int cb = (tid & 1) * 40;
    if (row >= NNODES) return;

    float a[40];
    {
        const float4* pa = (const float4*)(preX + (size_t)row * 20);
        const float4* pb = (const float4*)(preY + (size_t)row * 20);
        float4 va[5], vb[5];
#pragma unroll
        for (int i = 0; i < 5; i++) va[i] = pa[i];
#pragma unroll
        for (int i = 0; i < 5; i++) vb[i] = pb[i];
#pragma unroll
        for (int i = 0; i < 5; i++) {
            a[4 * i]     = va[i].x; a[4 * i + 1] = va[i].y;
            a[4 * i + 2] = va[i].z; a[4 * i + 3] = va[i].w;
            a[20 + 4 * i] = vb[i].x; a[21 + 4 * i] = vb[i].y;
            a[22 + 4 * i] = vb[i].z; a[23 + 4 * i] = vb[i].w;
        }
    }
#pragma unroll
    for (int k = 0; k < 40; k++) {
        float v = (a[k] - sMu[k]) * sScv[k] + sBeta[k];
        a[k] = (v >= 0.f) ? v : LSLOPE * v;
    }

    unsigned long long acc[20];
#pragma unroll
    for (int c = 0; c < 20; c++) acc[c] = 0ull;
#pragma unroll 8
    for (int k = 0; k < 40; k++) {
        unsigned long long a2 = pack2(a[k], a[k]);
        const unsigned long long* wrow = (const unsigned long long*)(&sW[k][cb]);
#pragma unroll
        for (int c = 0; c < 20; c++) acc[c] = ffma2(a2, wrow[c], acc[c]);
    }

    float res[40];
#pragma unroll
    for (int c = 0; c < 20; c++) {
        res[2 * c]     = __uint_as_float((unsigned)(acc[c] & 0xffffffffull)) + sb[cb + 2 * c];
        res[2 * c + 1] = __uint_as_float((unsigned)(acc[c] >> 32)) + sb[cb + 2 * c + 1];
    }
    float* dst = out + (size_t)row * 80 + cb;
#pragma unroll
    for (int c = 0; c < 40; c += 4)
        *(float4*)(dst + c) = make_float4(res[c], res[c + 1], res[c + 2], res[c + 3]);
}

// ------------------------- CSR aggregation (4-edge unroll) -----------------
__global__ void __launch_bounds__(256)
agg_csr(const float* __restrict__ qkvA, int baseA, float* __restrict__ preA,
        float* __restrict__ statsA,
        const float* __restrict__ qkvB, int baseB, float* __restrict__ preB,
        float* __restrict__ statsB, int blocksPerSet) {
    const bool isB = (int)blockIdx.x >= blocksPerSet;
    const float* qkv = isB ? qkvB : qkvA;
    float* pre = isB ? preB : preA;
    float* stats = isB ? statsB : statsA;
    const int nbase = isB ? baseB : baseA;
    const int bi = isB ? blockIdx.x - blocksPerSet : blockIdx.x;

    const int wid = threadIdx.x >> 5, lane = threadIdx.x & 31;
    const int n = bi * 8 + wid;
    const bool act = lane < 20;
    const int c = lane;

    __shared__ float sst[2][8][20];
    for (int l = threadIdx.x; l < 320; l += 256) ((float*)sst)[l] = 0.f;
    __syncthreads();

    if (n < NNODES) {
        const int gi = nbase + n;
        const int off0 = g_off[gi], off1 = g_off[gi + 1];
        const float qc = act ? qkv[(size_t)n * 80 + c] * 0.22360679774997896f : 0.f;
        float acc = 0.f, denom = 0.f;
        int p = off0;
        for (; p + 4 <= off1; p += 4) {
            int s0 = g_csr[p], s1 = g_csr[p + 1], s2 = g_csr[p + 2], s3 = g_csr[p + 3];
            float k0 = 0.f, k1 = 0.f, k2 = 0.f, k3 = 0.f;
            float v0 = 0.f, v1 = 0.f, v2 = 0.f, v3 = 0.f;
            if (act) {
                k0 = qkv[(size_t)s0 * 80 + 20 + c];
                k1 = qkv[(size_t)s1 * 80 + 20 + c];
                k2 = qkv[(size_t)s2 * 80 + 20 + c];
                k3 = qkv[(size_t)s3 * 80 + 20 + c];
                v0 = qkv[(size_t)s0 * 80 + 40 + c];
                v1 = qkv[(size_t)s1 * 80 + 40 + c];
                v2 = qkv[(size_t)s2 * 80 + 40 + c];
                v3 = qkv[(size_t)s3 * 80 + 40 + c];
            }
            float d0 = qc * k0, d1 = qc * k1, d2 = qc * k2, d3 = qc * k3;
#pragma unroll
            for (int o = 16; o; o >>= 1) {
                d0 += __shfl_xor_sync(~0u, d0, o);
                d1 += __shfl_xor_sync(~0u, d1, o);
                d2 += __shfl_xor_sync(~0u, d2, o);
                d3 += __shfl_xor_sync(~0u, d3, o);
            }
            float e0 = __expf(d0), e1 = __expf(d1), e2 = __expf(d2), e3 = __expf(d3);
            denom += (e0 + e1) + (e2 + e3);
            acc += e0 * v0 + e1 * v1 + e2 * v2 + e3 * v3;
        }
        for (; p < off1; p++) {
            int s0 = g_csr[p];
            float k0 = act ? qkv[(size_t)s0 * 80 + 20 + c] : 0.f;
            float v0 = act ? qkv[(size_t)s0 * 80 + 40 + c] : 0.f;
            float d0 = qc * k0;
#pragma unroll
            for (int o = 16; o; o >>= 1) d0 += __shfl_xor_sync(~0u, d0, o);
            float e0 = __expf(d0);
            denom += e0;
            acc += e0 * v0;
        }
        float inv = 1.f / fmaxf(denom, 1e-16f);
        if (act) {
            float r = acc * inv + qkv[(size_t)n * 80 + 60 + c];
            pre[(size_t)n * 20 + c] = r;
            sst[0][wid][c] = r;
            sst[1][wid][c] = r * r;
        }
    }
    __syncthreads();
    if (threadIdx.x < 40) {
        int which = threadIdx.x / 20, cc = threadIdx.x % 20;
        float t = 0.f;
#pragma unroll
        for (int w = 0; w < 8; w++) t += sst[which][w][cc];
        atomicAdd(&stats[which * 20 + cc], t);
    }
}

// ------------------------- BN into fc buffer, final FC ---------------------
__global__ void __launch_bounds__(256)
bn_fc(const float* __restrict__ pre, const float* __restrict__ stats,
      const float* __restrict__ gamma, const float* __restrict__ beta,
      float* __restrict__ dst, int off) {
    int idx = blockIdx.x * blockDim.x + threadIdx.x;
    if (idx >= NNODES * 20) return;
    int n = idx / 20, c = idx % 20;
    const float invN = 1.f / (float)NNODES;
    float mu = stats[c] * invN;
    float var = stats[20 + c] * invN - mu * mu;
    float scv = gamma[c] * rsqrtf(var + EPS_BN);
    float v = (pre[idx] - mu) * scv + beta[c];
    v = (v >= 0.f) ? v : LSLOPE * v;
    dst[(size_t)n * 100 + off + c] = v;
}

__global__ void __launch_bounds__(128)
fc_kernel(const float* __restrict__ W, const float* __restrict__ b,
          float* __restrict__ out) {
    __shared__ float sw[200];
    for (int l = threadIdx.x; l < 200; l += blockDim.x) sw[l] = W[l];
    __syncthreads();
    int n = blockIdx.x * blockDim.x + threadIdx.x;
    if (n >= NNODES) return;
    float a0 = b[0], a1 = b[1];
    const float4* fp = (const float4*)(g_fc + (size_t)n * 100);
#pragma unroll
    for (int i = 0; i < 25; i++) {
        float4 f = fp[i];
        int c = 4 * i;
        a0 += f.x * sw[2 * c] + f.y * sw[2 * c + 2] + f.z * sw[2 * c + 4] + f.w * sw[2 * c + 6];
        a1 += f.x * sw[2 * c + 1] + f.y * sw[2 * c + 3] + f.z * sw[2 * c + 5] + f.w * sw[2 * c + 7];
    }
    out[2 * n] = a0;
    out[2 * n + 1] = a1;
}

// ------------------------- host orchestration -------------------------
extern "C" void kernel_launch(void* const* d_in, const int* in_sizes, int n_in,
                              void* d_out, int out_size) {
    (void)in_sizes; (void)n_in; (void)out_size;
    const float* features = (const float*)d_in[0];
    const int* edge_index = (const int*)d_in[3];
    const int* same2      = (const int*)d_in[4];
    const int* diff2      = (const int*)d_in[5];
    const float* c1_W0 = (const float*)d_in[6];
    const float* c1_b0 = (const float*)d_in[7];
    const float* c2_W0 = (const float*)d_in[8];
    const float* c2_b0 = (const float*)d_in[9];
    const float* c1_W  = (const float*)d_in[10];
    const float* c1_b  = (const float*)d_in[11];
    const float* c2_W  = (const float*)d_in[12];
    const float* c2_b  = (const float*)d_in[13];
    const float* c3_W  = (const float*)d_in[14];
    const float* c3_b  = (const float*)d_in[15];
    const float* bn1_g = (const float*)d_in[16];
    const float* bn1_b = (const float*)d_in[17];
    const float* bn2_g = (const float*)d_in[18];
    const float* bn2_b = (const float*)d_in[19];
    const float* bn3_g = (const float*)d_in[20];
    const float* bn3_b = (const float*)d_in[21];
    const float* fc_W  = (const float*)d_in[22];
    const float* fc_b  = (const float*)d_in[23];
    float* out = (float*)d_out;

    float *qkvA, *qkvB, *preA, *preB, *preC, *fcb, *stats;
    cudaGetSymbolAddress((void**)&qkvA, g_qkvA);
    cudaGetSymbolAddress((void**)&qkvB, g_qkvB);
    cudaGetSymbolAddress((void**)&preA, g_preA);
    cudaGetSymbolAddress((void**)&preB, g_preB);
    cudaGetSymbolAddress((void**)&preC, g_preC);
    cudaGetSymbolAddress((void**)&fcb, g_fc);
    cudaGetSymbolAddress((void**)&stats, g_stats);

    const int GB = (NNODES + 127) / 128;
    const int G3E = (3 * NEDGE + 255) / 256;
    const int GA = (NNODES + 7) / 8;
    const int GN = (NNODES * 20 + 255) / 256;
    const int SMEM_MMA = (128 * SA_STRIDE + 160 * SB_STRIDE) * 2;  // 96768B

    cudaFuncSetAttribute(gemm_big_mma, cudaFuncAttributeMaxDynamicSharedMemorySize,
                         SMEM_MMA);

    // ---- CSR build + weight split/transpose ----
    zero_all<<<(NN3 + 255) / 256, 256>>>();
    hist_kernel<<<G3E, 256>>>(same2, diff2, edge_index);
    conv_w<<<(2000 * 160 + 255) / 256, 256>>>(c1_W0, c2_W0);
    scanA<<<SCAN_BLOCKS, 1024>>>();
    scanB<<<1, 256>>>();
    scanC<<<SCAN_BLOCKS, 1024>>>();
    scatter_kernel<<<G3E, 256>>>(same2, diff2, edge_index);

    // ---- layer 0: tensor-core GEMM (mma.sync bf16 split) ----
    gemm_big_mma<<<GB, 256, SMEM_MMA>>>(features, c1_b0, c2_b0, qkvA, qkvB);
    agg_csr<<<2 * GA, 256>>>(qkvA, 0, preA, stats + 0 * 40,
                             qkvB, NNODES, preB, stats + 1 * 40, GA);

    for (int L = 0; L <= 4; L++) {
        const float* stX = stats + (3 * L) * 40;
        const float* stY = stats + (3 * L + 1) * 40;
        const float* g1 = bn1_g + L * 20; const float* b1 = bn1_b + L * 20;
        const float* g2 = bn2_g + L * 20; const float* b2 = bn2_b + L * 20;

        gemm_small_bn<<<GB, 256>>>(preA, preB, stX, stY, g1, b1, g2, b2,
                                   c3_W + (size_t)L * 3200, c3_b + (size_t)L * 80, qkvA);
        agg_csr<<<GA, 256>>>(qkvA, 2 * NNODES, preC, stats + (3 * L + 2) * 40,
                             qkvA, 2 * NNODES, preC, stats + (3 * L + 2) * 40, GA);
        bn_fc<<<GN, 256>>>(preC, stats + (3 * L + 2) * 40,
                           bn3_g + L * 20, bn3_b + L * 20, fcb, L * 20);

        if (L == 4) break;

        gemm_small_bn<<<GB, 256>>>(preA, preB, stX, stY, g1, b1, g2, b2,
                                   c1_W + (size_t)L * 3200, c1_b + (size_t)L * 80, qkvA);
        gemm_small_bn<<<GB, 256>>>(preB, preA, stY, stX, g2, b2, g1, b1,
                                   c2_W + (size_t)L * 3200, c2_b + (size_t)L * 80, qkvB);
        agg_csr<<<2 * GA, 256>>>(qkvA, 0, preA, stats + (3 * L + 3) * 40,
                                 qkvB, NNODES, preB, stats + (3 * L + 4) * 40, GA);
    }

    fc_kernel<<<(NNODES + 127) / 128, 128>>>(fc_W, fc_b, out);
}

// round 8
// speedup vs baseline: 2.2867x; 1.0515x over previous
#include <cuda_runtime.h>
#include <cuda_bf16.h>
#include <cstdint>

#define NNODES 50000
#define NEDGE  1000000
#define DIN0   2000
#define EPS_BN 1e-5f
#define LSLOPE 0.01f
#define NN3    150000
#define SCAN_BLOCKS 147
#define GA_BLK 6250   /* (NNODES+7)/8 */

// ------------------------- scratch (device globals, zero-init) -------------
__device__ float g_qkvA[NNODES * 80];
__device__ float g_qkvB[NNODES * 80];
__device__ float g_qkvC[NNODES * 80];
__device__ float g_preA[NNODES * 20];
__device__ float g_preB[NNODES * 20];
__device__ float g_preC[NNODES * 20];
__device__ float g_fc[NNODES * 100];
__device__ float g_stats[15 * 40];
__device__ __nv_bfloat16 g_wt_hi[2000 * 160];  // [k][n] transposed weights
__device__ __nv_bfloat16 g_wt_lo[2000 * 160];
// CSR scratch
__device__ int g_cnt[NN3];
__device__ int g_off[NN3 + 1];
__device__ int g_cur[NN3];
__device__ int g_csr[3 * NEDGE];
__device__ int g_partraw[SCAN_BLOCKS];
__device__ int g_part[SCAN_BLOCKS];

// ------------------------- helpers -------------------------
__device__ __forceinline__ unsigned long long ffma2(unsigned long long a,
                                                    unsigned long long b,
                                                    unsigned long long c) {
    unsigned long long d;
    asm("fma.rn.f32x2 %0, %1, %2, %3;" : "=l"(d) : "l"(a), "l"(b), "l"(c));
    return d;
}
__device__ __forceinline__ unsigned long long pack2(float lo, float hi) {
    unsigned long long r;
    asm("mov.b64 %0, {%1, %2};" : "=l"(r) : "f"(lo), "f"(hi));
    return r;
}
__device__ __forceinline__ uint32_t smem_u32(const void* p) {
    uint32_t a;
    asm("{ .reg .u64 t; cvta.to.shared.u64 t, %1; cvt.u32.u64 %0, t; }"
        : "=r"(a) : "l"(p));
    return a;
}
__device__ __forceinline__ uint32_t packbf2(float a, float b, float* lo_a, float* lo_b) {
    __nv_bfloat16 ha = __float2bfloat16(a), hb = __float2bfloat16(b);
    *lo_a = a - __bfloat162float(ha);
    *lo_b = b - __bfloat162float(hb);
    __nv_bfloat162 p; p.x = ha; p.y = hb;
    return *(uint32_t*)&p;
}
__device__ __forceinline__ uint32_t packbf2s(float a, float b) {
    __nv_bfloat162 p; p.x = __float2bfloat16(a); p.y = __float2bfloat16(b);
    return *(uint32_t*)&p;
}

// ------------------------- CSR build -------------------------
__global__ void zero_all() {
    int i = blockIdx.x * blockDim.x + threadIdx.x;
    if (i < NN3) g_cnt[i] = 0;
    if (i < 15 * 40) g_stats[i] = 0.f;
}
__global__ void hist_kernel(const int* __restrict__ e0, const int* __restrict__ e1,
                            const int* __restrict__ e2) {
    int i = blockIdx.x * blockDim.x + threadIdx.x;
    if (i >= 3 * NEDGE) return;
    int set = i / NEDGE, e = i - set * NEDGE;
    const int* ei = (set == 0) ? e0 : ((set == 1) ? e1 : e2);
    atomicAdd(&g_cnt[set * NNODES + ei[NEDGE + e]], 1);
}
__global__ void __launch_bounds__(1024) scanA() {
    int gid = blockIdx.x * 1024 + threadIdx.x;
    int v = (gid < NN3) ? g_cnt[gid] : 0;
#pragma unroll
    for (int o = 16; o; o >>= 1) v += __shfl_xor_sync(~0u, v, o);
    __shared__ int sw[32];
    if ((threadIdx.x & 31) == 0) sw[threadIdx.x >> 5] = v;
    __syncthreads();
    if (threadIdx.x < 32) {
        int t = sw[threadIdx.x];
#pragma unroll
        for (int o = 16; o; o >>= 1) t += __shfl_xor_sync(~0u, t, o);
        if (threadIdx.x == 0) g_partraw[blockIdx.x] = t;
    }
}
__global__ void scanB() {
    __shared__ int sp[SCAN_BLOCKS + 1];
    int tid = threadIdx.x;
    if (tid < SCAN_BLOCKS) sp[tid + 1] = g_partraw[tid];
    if (tid == 0) sp[0] = 0;
    __syncthreads();
    if (tid == 0)
        for (int b = 1; b <= SCAN_BLOCKS; b++) sp[b] += sp[b - 1];
    __syncthreads();
    if (tid < SCAN_BLOCKS) g_part[tid] = sp[tid];
}
__global__ void __launch_bounds__(1024) scanC() {
    __shared__ int sdat[1024];
    int tid = threadIdx.x;
    int gid = blockIdx.x * 1024 + tid;
    int v = (gid < NN3) ? g_cnt[gid] : 0;
    sdat[tid] = v;
    __syncthreads();
    for (int o = 1; o < 1024; o <<= 1) {
        int t = (tid >= o) ? sdat[tid - o] : 0;
        __syncthreads();
        sdat[tid] += t;
        __syncthreads();
    }
    int excl = sdat[tid] - v + g_part[blockIdx.x];
    if (gid < NN3) { g_off[gid] = excl; g_cur[gid] = excl; }
    if (gid == 0) g_off[NN3] = 3 * NEDGE;
}
__global__ void scatter_kernel(const int* __restrict__ e0, const int* __restrict__ e1,
                               const int* __restrict__ e2) {
    int i = blockIdx.x * blockDim.x + threadIdx.x;
    if (i >= 3 * NEDGE) return;
    int set = i / NEDGE, e = i - set * NEDGE;
    const int* ei = (set == 0) ? e0 : ((set == 1) ? e1 : e2);
    int s = ei[e], d = ei[NEDGE + e];
    int pos = atomicAdd(&g_cur[set * NNODES + d], 1);
    g_csr[pos] = s;
}

// ------------- W split+transpose (fp32 [4,2000,20]x2 -> bf16 [2000][160]) --
__global__ void conv_w(const float* __restrict__ W1, const float* __restrict__ W2) {
    int idx = blockIdx.x * blockDim.x + threadIdx.x;
    if (idx >= 2000 * 160) return;
    int k = idx / 160, n = idx - k * 160;
    const float* Wsrc = (n < 80) ? W1 : W2;
    int nn = (n < 80) ? n : n - 80;
    int s = nn / 20, o = nn % 20;
    float w = Wsrc[((size_t)s * 2000 + k) * 20 + o];
    __nv_bfloat16 h = __float2bfloat16(w);
    g_wt_hi[idx] = h;
    g_wt_lo[idx] = __float2bfloat16(w - __bfloat162float(h));
}

// ------------------------- big GEMM via mma.sync bf16-split ----------------
#define SA_STRIDE 168
#define SB_STRIDE 168

__global__ void __launch_bounds__(256)
gemm_big_mma(const float* __restrict__ A,
             const float* __restrict__ b1, const float* __restrict__ b2,
             float* __restrict__ outA, float* __restrict__ outB) {
    extern __shared__ __align__(16) char dsm[];
    __nv_bfloat16* sA = (__nv_bfloat16*)dsm;                          // [128][168]
    __nv_bfloat16* sB = (__nv_bfloat16*)(dsm + 128 * SA_STRIDE * 2);  // [160][168]
    __shared__ float s_bias[160];

    const int tid = threadIdx.x, wid = tid >> 5, lane = tid & 31;
    const int rowbase = blockIdx.x * 128;
    if (tid < 160) s_bias[tid] = (tid < 80) ? b1[tid] : b2[tid - 80];

    float acc[20][4];
#pragma unroll
    for (int t = 0; t < 20; t++)
#pragma unroll
        for (int i = 0; i < 4; i++) acc[t][i] = 0.f;

    // ldmatrix bases
    const int r_in = lane & 7, blkb = (lane >> 3) & 1, kh = (lane >> 4) & 1;
    const uint32_t aBase =
        smem_u32(sA) + (uint32_t)((wid * 16 + blkb * 8 + r_in) * SA_STRIDE + kh * 8) * 2;
    const uint32_t bBase2 = smem_u32(sB) + (uint32_t)((lane & 15) * SB_STRIDE) * 2;
    const uint32_t bBase4 = smem_u32(sB) + (uint32_t)(lane * SB_STRIDE) * 2;

    // kstep-pair tables: A hi/lo section offsets (bf16 cols), B physical start row
    const int a0off[7] = {0, 32, 64, 16, 48, 80, 112};
    const int a1off[7] = {16, 48, 0, 32, 64, 96, 128};
    const int browt[7] = {0, 32, 64, 96, 128, 0, 32};

    for (int ch = 0; ch < 25; ch++) {
        const int k0 = ch * 80;
        // ---- stage B via cp.async (straight copy, hi rows 0-79, lo rows 80-159)
#pragma unroll
        for (int it = 0; it < 13; it++) {
            int q = tid + it * 256;
            if (q < 3200) {
                int row = q / 20, c16 = q - row * 20;
                int kk = (row >= 80) ? row - 80 : row;
                const __nv_bfloat16* src =
                    ((row >= 80) ? g_wt_lo : g_wt_hi) + (size_t)(k0 + kk) * 160 + c16 * 8;
                uint32_t dst = smem_u32(sB) + (uint32_t)(row * SB_STRIDE + c16 * 8) * 2;
                asm volatile("cp.async.ca.shared.global [%0], [%1], 16;"
                             :: "r"(dst), "l"(src));
            }
        }
        asm volatile("cp.async.commit_group;" ::: "memory");
        // ---- stage A: fp32 -> bf16 hi/lo sections
#pragma unroll
        for (int it = 0; it < 10; it++) {
            int q = tid + it * 256;
            int r = q / 20, f = q - r * 20;
            int row = rowbase + r;
            float4 v = (row < NNODES)
                           ? *(const float4*)(A + (size_t)row * 2000 + k0 + f * 4)
                           : make_float4(0.f, 0.f, 0.f, 0.f);
            float l0, l1, l2, l3;
            uint32_t h0 = packbf2(v.x, v.y, &l0, &l1);
            uint32_t h1 = packbf2(v.z, v.w, &l2, &l3);
            uint32_t p0 = packbf2s(l0, l1), p1 = packbf2s(l2, l3);
            int k = f * 4;
            __nv_bfloat16* rp = sA + r * SA_STRIDE;
            *(uint32_t*)(rp + k) = h0;
            *(uint32_t*)(rp + k + 2) = h1;
            *(uint32_t*)(rp + 80 + k) = p0;
            *(uint32_t*)(rp + 82 + k) = p1;
        }
        asm volatile("cp.async.wait_group 0;" ::: "memory");
        __syncthreads();
        // ---- compute: 7 kstep-pairs + 1 tail kstep, 20 n-tiles each ----
#pragma unroll
        for (int jp = 0; jp < 7; jp++) {
            uint32_t a0, a1, a2, a3, c0, c1, c2, c3;
            asm volatile(
                "ldmatrix.sync.aligned.m8n8.x4.shared.b16 {%0,%1,%2,%3}, [%4];"
                : "=r"(a0), "=r"(a1), "=r"(a2), "=r"(a3)
                : "r"(aBase + (uint32_t)a0off[jp] * 2));
            asm volatile(
                "ldmatrix.sync.aligned.m8n8.x4.shared.b16 {%0,%1,%2,%3}, [%4];"
                : "=r"(c0), "=r"(c1), "=r"(c2), "=r"(c3)
                : "r"(aBase + (uint32_t)a1off[jp] * 2));
            const uint32_t bb = bBase4 + (uint32_t)(browt[jp] * SB_STRIDE) * 2;
#pragma unroll
            for (int t = 0; t < 20; t++) {
                uint32_t b0, b1, b2, b3;
                asm volatile(
                    "ldmatrix.sync.aligned.m8n8.x4.trans.shared.b16 {%0,%1,%2,%3}, [%4];"
                    : "=r"(b0), "=r"(b1), "=r"(b2), "=r"(b3)
                    : "r"(bb + (uint32_t)t * 16));
                asm volatile(
                    "mma.sync.aligned.m16n8k16.row.col.f32.bf16.bf16.f32 "
                    "{%0,%1,%2,%3}, {%4,%5,%6,%7}, {%8,%9}, {%0,%1,%2,%3};"
                    : "+f"(acc[t][0]), "+f"(acc[t][1]), "+f"(acc[t][2]), "+f"(acc[t][3])
                    : "r"(a0), "r"(a1), "r"(a2), "r"(a3), "r"(b0), "r"(b1));
                asm volatile(
                    "mma.sync.aligned.m16n8k16.row.col.f32.bf16.bf16.f32 "
                    "{%0,%1,%2,%3}, {%4,%5,%6,%7}, {%8,%9}, {%0,%1,%2,%3};"
                    : "+f"(acc[t][0]), "+f"(acc[t][1]), "+f"(acc[t][2]), "+f"(acc[t][3])
                    : "r"(c0), "r"(c1), "r"(c2), "r"(c3), "r"(b2), "r"(b3));
            }
        }
        {   // tail: logical kstep 14 (A lo k64-79 x B hi k64-79)
            uint32_t a0, a1, a2, a3;
            asm volatile(
                "ldmatrix.sync.aligned.m8n8.x4.shared.b16 {%0,%1,%2,%3}, [%4];"
                : "=r"(a0), "=r"(a1), "=r"(a2), "=r"(a3)
                : "r"(aBase + 144u * 2));
            const uint32_t bb = bBase2 + (uint32_t)(64 * SB_STRIDE) * 2;
#pragma unroll
            for (int t = 0; t < 20; t++) {
                uint32_t b0, b1;
                asm volatile(
                    "ldmatrix.sync.aligned.m8n8.x2.trans.shared.b16 {%0,%1}, [%2];"
                    : "=r"(b0), "=r"(b1)
                    : "r"(bb + (uint32_t)t * 16));
                asm volatile(
                    "mma.sync.aligned.m16n8k16.row.col.f32.bf16.bf16.f32 "
                    "{%0,%1,%2,%3}, {%4,%5,%6,%7}, {%8,%9}, {%0,%1,%2,%3};"
                    : "+f"(acc[t][0]), "+f"(acc[t][1]), "+f"(acc[t][2]), "+f"(acc[t][3])
                    : "r"(a0), "r"(a1), "r"(a2), "r"(a3), "r"(b0), "r"(b1));
            }
        }
        __syncthreads();
    }

    // ---- epilogue ----
    const int r0 = rowbase + wid * 16 + lane / 4;
    const int r1 = r0 + 8;
    const int cb = (lane & 3) * 2;
#pragma unroll
    for (int t = 0; t < 20; t++) {
        int col = t * 8 + cb;
        float* base = (col < 80) ? outA : outB;
        int cc = (col < 80) ? col : col - 80;
        float bia0 = s_bias[col], bia1 = s_bias[col + 1];
        if (r0 < NNODES)
            *(float2*)(base + (size_t)r0 * 80 + cc) =
                make_float2(acc[t][0] + bia0, acc[t][1] + bia1);
        if (r1 < NNODES)
            *(float2*)(base + (size_t)r1 * 80 + cc) =
                make_float2(acc[t][2] + bia0, acc[t][3] + bia1);
    }
}

// ------------------------- small GEMM with fused BN+LeakyReLU --------------
__global__ void __launch_bounds__(256)
gemm_small_bn(const float* __restrict__ preX, const float* __restrict__ preY,
              const float* __restrict__ statsX, const float* __restrict__ statsY,
              const float* __restrict__ gX, const float* __restrict__ betX,
              const float* __restrict__ gY, const float* __restrict__ betY,
              const float* __restrict__ W, const float* __restrict__ b,
              float* __restrict__ out) {
    __shared__ __align__(8) float sW[40][80];
    __shared__ float sb[80];
    __shared__ float sMu[40], sScv[40], sBeta[40];
    const int tid = threadIdx.x;
    for (int l = tid; l < 3200; l += 256) {
        int s = l / 800, rem = l % 800, k = rem / 20, o = rem % 20;
        sW[k][s * 20 + o] = W[l];
    }
    if (tid < 80) sb[tid] = b[tid];
    if (tid < 40) {
        const float invN = 1.f / (float)NNODES;
        int c = tid % 20;
        const float* st = (tid < 20) ? statsX : statsY;
        const float* gg = (tid < 20) ? gX : gY;
        const float* bb = (tid < 20) ? betX : betY;
        float mu = st[c] * invN;
        float var = st[20 + c] * invN - mu * mu;
        sMu[tid] = mu;
        sScv[tid] = gg[c] * rsqrtf(var + EPS_BN);
        sBeta[tid] = bb[c];
    }
    __syncthreads();

    const int row = blockIdx.x * 128 + (tid >> 1);
    const int cb = (tid & 1) * 40;
    if (row >= NNODES) return;

    float a[40];
    {
        const float4* pa = (const float4*)(preX + (size_t)row * 20);
        const float4* pb = (const float4*)(preY + (size_t)row * 20);
        float4 va[5], vb[5];
#pragma unroll
        for (int i = 0; i < 5; i++) va[i] = pa[i];
#pragma unroll
        for (int i = 0; i < 5; i++) vb[i] = pb[i];
#pragma unroll
        for (int i = 0; i < 5; i++) {
            a[4 * i]     = va[i].x; a[4 * i + 1] = va[i].y;
            a[4 * i + 2] = va[i].z; a[4 * i + 3] = va[i].w;
            a[20 + 4 * i] = vb[i].x; a[21 + 4 * i] = vb[i].y;
            a[22 + 4 * i] = vb[i].z; a[23 + 4 * i] = vb[i].w;
        }
    }
#pragma unroll
    for (int k = 0; k < 40; k++) {
        float v = (a[k] - sMu[k]) * sScv[k] + sBeta[k];
        a[k] = (v >= 0.f) ? v : LSLOPE * v;
    }

    unsigned long long acc[20];
#pragma unroll
    for (int c = 0; c < 20; c++) acc[c] = 0ull;
#pragma unroll 8
    for (int k = 0; k < 40; k++) {
        unsigned long long a2 = pack2(a[k], a[k]);
        const unsigned long long* wrow = (const unsigned long long*)(&sW[k][cb]);
#pragma unroll
        for (int c = 0; c < 20; c++) acc[c] = ffma2(a2, wrow[c], acc[c]);
    }

    float res[40];
#pragma unroll
    for (int c = 0; c < 20; c++) {
        res[2 * c]     = __uint_as_float((unsigned)(acc[c] & 0xffffffffull)) + sb[cb + 2 * c];
        res[2 * c + 1] = __uint_as_float((unsigned)(acc[c] >> 32)) + sb[cb + 2 * c + 1];
    }
    float* dst = out + (size_t)row * 80 + cb;
#pragma unroll
    for (int c = 0; c < 40; c += 4)
        *(float4*)(dst + c) = make_float4(res[c], res[c + 1], res[c + 2], res[c + 3]);
}

// ------------------------- CSR aggregation, up to 3 sets per launch --------
__global__ void __launch_bounds__(256)
agg_csr3(const float* __restrict__ q0, int nb0, float* __restrict__ p0, float* __restrict__ s0,
         const float* __restrict__ q1, int nb1, float* __restrict__ p1, float* __restrict__ s1,
         const float* __restrict__ q2, int nb2, float* __restrict__ p2, float* __restrict__ s2) {
    const int set = blockIdx.x / GA_BLK;
    const int bi = blockIdx.x - set * GA_BLK;
    const float* qkv = (set == 0) ? q0 : ((set == 1) ? q1 : q2);
    float* pre = (set == 0) ? p0 : ((set == 1) ? p1 : p2);
    float* stats = (set == 0) ? s0 : ((set == 1) ? s1 : s2);
    const int nbase = (set == 0) ? nb0 : ((set == 1) ? nb1 : nb2);

    const int wid = threadIdx.x >> 5, lane = threadIdx.x & 31;
    const int n = bi * 8 + wid;
    const bool act = lane < 20;
    const int c = lane;

    __shared__ float sst[2][8][20];
    for (int l = threadIdx.x; l < 320; l += 256) ((float*)sst)[l] = 0.f;
    __syncthreads();

    if (n < NNODES) {
        const int gi = nbase + n;
        const int off0 = g_off[gi], off1 = g_off[gi + 1];
        const float qc = act ? qkv[(size_t)n * 80 + c] * 0.22360679774997896f : 0.f;
        float acc = 0.f, denom = 0.f;
        int p = off0;
        for (; p + 4 <= off1; p += 4) {
            int s0i = g_csr[p], s1i = g_csr[p + 1], s2i = g_csr[p + 2], s3i = g_csr[p + 3];
            float k0 = 0.f, k1 = 0.f, k2 = 0.f, k3 = 0.f;
            float v0 = 0.f, v1 = 0.f, v2 = 0.f, v3 = 0.f;
            if (act) {
                k0 = qkv[(size_t)s0i * 80 + 20 + c];
                k1 = qkv[(size_t)s1i * 80 + 20 + c];
                k2 = qkv[(size_t)s2i * 80 + 20 + c];
                k3 = qkv[(size_t)s3i * 80 + 20 + c];
                v0 = qkv[(size_t)s0i * 80 + 40 + c];
                v1 = qkv[(size_t)s1i * 80 + 40 + c];
                v2 = qkv[(size_t)s2i * 80 + 40 + c];
                v3 = qkv[(size_t)s3i * 80 + 40 + c];
            }
            float d0 = qc * k0, d1 = qc * k1, d2 = qc * k2, d3 = qc * k3;
#pragma unroll
            for (int o = 16; o; o >>= 1) {
                d0 += __shfl_xor_sync(~0u, d0, o);
                d1 += __shfl_xor_sync(~0u, d1, o);
                d2 += __shfl_xor_sync(~0u, d2, o);
                d3 += __shfl_xor_sync(~0u, d3, o);
            }
            float e0 = __expf(d0), e1 = __expf(d1), e2 = __expf(d2), e3 = __expf(d3);
            denom += (e0 + e1) + (e2 + e3);
            acc += e0 * v0 + e1 * v1 + e2 * v2 + e3 * v3;
        }
        for (; p < off1; p++) {
            int si = g_csr[p];
            float k0 = act ? qkv[(size_t)si * 80 + 20 + c] : 0.f;
            float v0 = act ? qkv[(size_t)si * 80 + 40 + c] : 0.f;
            float d0 = qc * k0;
#pragma unroll
            for (int o = 16; o; o >>= 1) d0 += __shfl_xor_sync(~0u, d0, o);
            float e0 = __expf(d0);
            denom += e0;
            acc += e0 * v0;
        }
        float inv = 1.f / fmaxf(denom, 1e-16f);
        if (act) {
            float r = acc * inv + qkv[(size_t)n * 80 + 60 + c];
            pre[(size_t)n * 20 + c] = r;
            sst[0][wid][c] = r;
            sst[1][wid][c] = r * r;
        }
    }
    __syncthreads();
    if (threadIdx.x < 40) {
        int which = threadIdx.x / 20, cc = threadIdx.x % 20;
        float t = 0.f;
#pragma unroll
        for (int w = 0; w < 8; w++) t += sst[which][w][cc];
        atomicAdd(&stats[which * 20 + cc], t);
    }
}

// ------------------------- BN into fc buffer, final FC ---------------------
__global__ void __launch_bounds__(256)
bn_fc(const float* __restrict__ pre, const float* __restrict__ stats,
      const float* __restrict__ gamma, const float* __restrict__ beta,
      float* __restrict__ dst, int off) {
    int idx = blockIdx.x * blockDim.x + threadIdx.x;
    if (idx >= NNODES * 20) return;
    int n = idx / 20, c = idx % 20;
    const float invN = 1.f / (float)NNODES;
    float mu = stats[c] * invN;
    float var = stats[20 + c] * invN - mu * mu;
    float scv = gamma[c] * rsqrtf(var + EPS_BN);
    float v = (pre[idx] - mu) * scv + beta[c];
    v = (v >= 0.f) ? v : LSLOPE * v;
    dst[(size_t)n * 100 + off + c] = v;
}

__global__ void __launch_bounds__(128)
fc_kernel(const float* __restrict__ W, const float* __restrict__ b,
          float* __restrict__ out) {
    __shared__ float sw[200];
    for (int l = threadIdx.x; l < 200; l += blockDim.x) sw[l] = W[l];
    __syncthreads();
    int n = blockIdx.x * blockDim.x + threadIdx.x;
    if (n >= NNODES) return;
    float a0 = b[0], a1 = b[1];
    const float4* fp = (const float4*)(g_fc + (size_t)n * 100);
#pragma unroll
    for (int i = 0; i < 25; i++) {
        float4 f = fp[i];
        int c = 4 * i;
        a0 += f.x * sw[2 * c] + f.y * sw[2 * c + 2] + f.z * sw[2 * c + 4] + f.w * sw[2 * c + 6];
        a1 += f.x * sw[2 * c + 1] + f.y * sw[2 * c + 3] + f.z * sw[2 * c + 5] + f.w * sw[2 * c + 7];
    }
    out[2 * n] = a0;
    out[2 * n + 1] = a1;
}

// ------------------------- host orchestration -------------------------
extern "C" void kernel_launch(void* const* d_in, const int* in_sizes, int n_in,
                              void* d_out, int out_size) {
    (void)in_sizes; (void)n_in; (void)out_size;
    const float* features = (const float*)d_in[0];
    const int* edge_index = (const int*)d_in[3];
    const int* same2      = (const int*)d_in[4];
    const int* diff2      = (const int*)d_in[5];
    const float* c1_W0 = (const float*)d_in[6];
    const float* c1_b0 = (const float*)d_in[7];
    const float* c2_W0 = (const float*)d_in[8];
    const float* c2_b0 = (const float*)d_in[9];
    const float* c1_W  = (const float*)d_in[10];
    const float* c1_b  = (const float*)d_in[11];
    const float* c2_W  = (const float*)d_in[12];
    const float* c2_b  = (const float*)d_in[13];
    const float* c3_W  = (const float*)d_in[14];
    const float* c3_b  = (const float*)d_in[15];
    const float* bn1_g = (const float*)d_in[16];
    const float* bn1_b = (const float*)d_in[17];
    const float* bn2_g = (const float*)d_in[18];
    const float* bn2_b = (const float*)d_in[19];
    const float* bn3_g = (const float*)d_in[20];
    const float* bn3_b = (const float*)d_in[21];
    const float* fc_W  = (const float*)d_in[22];
    const float* fc_b  = (const float*)d_in[23];
    float* out = (float*)d_out;

    float *qkvA, *qkvB, *qkvC, *preA, *preB, *preC, *fcb, *stats;
    cudaGetSymbolAddress((void**)&qkvA, g_qkvA);
    cudaGetSymbolAddress((void**)&qkvB, g_qkvB);
    cudaGetSymbolAddress((void**)&qkvC, g_qkvC);
    cudaGetSymbolAddress((void**)&preA, g_preA);
    cudaGetSymbolAddress((void**)&preB, g_preB);
    cudaGetSymbolAddress((void**)&preC, g_preC);
    cudaGetSymbolAddress((void**)&fcb, g_fc);
    cudaGetSymbolAddress((void**)&stats, g_stats);

    const int GB = (NNODES + 127) / 128;
    const int G3E = (3 * NEDGE + 255) / 256;
    const int GN = (NNODES * 20 + 255) / 256;
    const int SMEM_MMA = (128 * SA_STRIDE + 160 * SB_STRIDE) * 2;

    cudaFuncSetAttribute(gemm_big_mma, cudaFuncAttributeMaxDynamicSharedMemorySize,
                         SMEM_MMA);

    // ---- CSR build + weight split/transpose ----
    zero_all<<<(NN3 + 255) / 256, 256>>>();
    hist_kernel<<<G3E, 256>>>(same2, diff2, edge_index);
    conv_w<<<(2000 * 160 + 255) / 256, 256>>>(c1_W0, c2_W0);
    scanA<<<SCAN_BLOCKS, 1024>>>();
    scanB<<<1, 256>>>();
    scanC<<<SCAN_BLOCKS, 1024>>>();
    scatter_kernel<<<G3E, 256>>>(same2, diff2, edge_index);

    // ---- layer 0: tensor-core GEMM + 2-set agg ----
    gemm_big_mma<<<GB, 256, SMEM_MMA>>>(features, c1_b0, c2_b0, qkvA, qkvB);
    agg_csr3<<<2 * GA_BLK, 256>>>(qkvA, 0, preA, stats + 0 * 40,
                                  qkvB, NNODES, preB, stats + 1 * 40,
                                  qkvA, 0, preA, stats + 0 * 40);

    for (int L = 0; L <= 4; L++) {
        const float* stX = stats + (3 * L) * 40;
        const float* stY = stats + (3 * L + 1) * 40;
        const float* g1 = bn1_g + L * 20; const float* b1 = bn1_b + L * 20;
        const float* g2 = bn2_g + L * 20; const float* b2 = bn2_b + L * 20;

        // all three convs read the same preA/preB + stats -> run before any agg
        gemm_small_bn<<<GB, 256>>>(preA, preB, stX, stY, g1, b1, g2, b2,
                                   c3_W + (size_t)L * 3200, c3_b + (size_t)L * 80, qkvC);
        if (L < 4) {
            gemm_small_bn<<<GB, 256>>>(preA, preB, stX, stY, g1, b1, g2, b2,
                                       c1_W + (size_t)L * 3200, c1_b + (size_t)L * 80, qkvA);
            gemm_small_bn<<<GB, 256>>>(preB, preA, stY, stX, g2, b2, g1, b1,
                                       c2_W + (size_t)L * 3200, c2_b + (size_t)L * 80, qkvB);
            agg_csr3<<<3 * GA_BLK, 256>>>(qkvC, 2 * NNODES, preC, stats + (3 * L + 2) * 40,
                                          qkvA, 0, preA, stats + (3 * L + 3) * 40,
                                          qkvB, NNODES, preB, stats + (3 * L + 4) * 40);
        } else {
            agg_csr3<<<GA_BLK, 256>>>(qkvC, 2 * NNODES, preC, stats + (3 * L + 2) * 40,
                                      qkvC, 2 * NNODES, preC, stats + (3 * L + 2) * 40,
                                      qkvC, 2 * NNODES, preC, stats + (3 * L + 2) * 40);
        }
        bn_fc<<<GN, 256>>>(preC, stats + (3 * L + 2) * 40,
                           bn3_g + L * 20, bn3_b + L * 20, fcb, L * 20);
    }

    fc_kernel<<<(NNODES + 127) / 128, 128>>>(fc_W, fc_b, out);
}

// round 9
// speedup vs baseline: 2.3525x; 1.0288x over previous
#include <cuda_runtime.h>
#include <cuda_bf16.h>
#include <cstdint>

#define NNODES 50000
#define NEDGE  1000000
#define DIN0   2000
#define EPS_BN 1e-5f
#define LSLOPE 0.01f
#define NN3    150000
#define SCAN_BLOCKS 147
#define GA_BLK 6250   /* (NNODES+7)/8 */
#define GB_SM  391    /* (NNODES+127)/128 */

// ------------------------- scratch (device globals, zero-init) -------------
__device__ float g_qkvA[NNODES * 80];
__device__ float g_qkvB[NNODES * 80];
__device__ float g_qkvC[NNODES * 80];
__device__ float g_preA[NNODES * 20];
__device__ float g_preB[NNODES * 20];
__device__ float g_preC[NNODES * 20];
__device__ float g_fc[NNODES * 100];
__device__ float g_stats[15 * 40];
__device__ __nv_bfloat16 g_wt_hi[2000 * 160];
__device__ __nv_bfloat16 g_wt_lo[2000 * 160];
// CSR scratch
__device__ int g_cnt[NN3];
__device__ int g_off[NN3 + 1];
__device__ int g_cur[NN3];
__device__ int g_csr[3 * NEDGE];
__device__ int g_partraw[SCAN_BLOCKS];
__device__ int g_part[SCAN_BLOCKS];

// ------------------------- helpers -------------------------
__device__ __forceinline__ unsigned long long ffma2(unsigned long long a,
                                                    unsigned long long b,
                                                    unsigned long long c) {
    unsigned long long d;
    asm("fma.rn.f32x2 %0, %1, %2, %3;" : "=l"(d) : "l"(a), "l"(b), "l"(c));
    return d;
}
__device__ __forceinline__ unsigned long long pack2(float lo, float hi) {
    unsigned long long r;
    asm("mov.b64 %0, {%1, %2};" : "=l"(r) : "f"(lo), "f"(hi));
    return r;
}
__device__ __forceinline__ uint32_t smem_u32(const void* p) {
    uint32_t a;
    asm("{ .reg .u64 t; cvta.to.shared.u64 t, %1; cvt.u32.u64 %0, t; }"
        : "=r"(a) : "l"(p));
    return a;
}
__device__ __forceinline__ uint32_t packbf2(float a, float b, float* lo_a, float* lo_b) {
    __nv_bfloat16 ha = __float2bfloat16(a), hb = __float2bfloat16(b);
    *lo_a = a - __bfloat162float(ha);
    *lo_b = b - __bfloat162float(hb);
    __nv_bfloat162 p; p.x = ha; p.y = hb;
    return *(uint32_t*)&p;
}
__device__ __forceinline__ uint32_t packbf2s(float a, float b) {
    __nv_bfloat162 p; p.x = __float2bfloat16(a); p.y = __float2bfloat16(b);
    return *(uint32_t*)&p;
}

// ------------------------- CSR build -------------------------
__global__ void zero_all() {
    int i = blockIdx.x * blockDim.x + threadIdx.x;
    if (i < NN3) g_cnt[i] = 0;
    if (i < 15 * 40) g_stats[i] = 0.f;
}
__global__ void hist_kernel(const int* __restrict__ e0, const int* __restrict__ e1,
                            const int* __restrict__ e2) {
    int i = blockIdx.x * blockDim.x + threadIdx.x;
    if (i >= 3 * NEDGE) return;
    int set = i / NEDGE, e = i - set * NEDGE;
    const int* ei = (set == 0) ? e0 : ((set == 1) ? e1 : e2);
    atomicAdd(&g_cnt[set * NNODES + ei[NEDGE + e]], 1);
}
__global__ void __launch_bounds__(1024) scanA() {
    int gid = blockIdx.x * 1024 + threadIdx.x;
    int v = (gid < NN3) ? g_cnt[gid] : 0;
#pragma unroll
    for (int o = 16; o; o >>= 1) v += __shfl_xor_sync(~0u, v, o);
    __shared__ int sw[32];
    if ((threadIdx.x & 31) == 0) sw[threadIdx.x >> 5] = v;
    __syncthreads();
    if (threadIdx.x < 32) {
        int t = sw[threadIdx.x];
#pragma unroll
        for (int o = 16; o; o >>= 1) t += __shfl_xor_sync(~0u, t, o);
        if (threadIdx.x == 0) g_partraw[blockIdx.x] = t;
    }
}
__global__ void scanB() {
    __shared__ int sp[SCAN_BLOCKS + 1];
    int tid = threadIdx.x;
    if (tid < SCAN_BLOCKS) sp[tid + 1] = g_partraw[tid];
    if (tid == 0) sp[0] = 0;
    __syncthreads();
    if (tid == 0)
        for (int b = 1; b <= SCAN_BLOCKS; b++) sp[b] += sp[b - 1];
    __syncthreads();
    if (tid < SCAN_BLOCKS) g_part[tid] = sp[tid];
}
__global__ void __launch_bounds__(1024) scanC() {
    __shared__ int sdat[1024];
    int tid = threadIdx.x;
    int gid = blockIdx.x * 1024 + tid;
    int v = (gid < NN3) ? g_cnt[gid] : 0;
    sdat[tid] = v;
    __syncthreads();
    for (int o = 1; o < 1024; o <<= 1) {
        int t = (tid >= o) ? sdat[tid - o] : 0;
        __syncthreads();
        sdat[tid] += t;
        __syncthreads();
    }
    int excl = sdat[tid] - v + g_part[blockIdx.x];
    if (gid < NN3) { g_off[gid] = excl; g_cur[gid] = excl; }
    if (gid == 0) g_off[NN3] = 3 * NEDGE;
}
__global__ void scatter_kernel(const int* __restrict__ e0, const int* __restrict__ e1,
                               const int* __restrict__ e2) {
    int i = blockIdx.x * blockDim.x + threadIdx.x;
    if (i >= 3 * NEDGE) return;
    int set = i / NEDGE, e = i - set * NEDGE;
    const int* ei = (set == 0) ? e0 : ((set == 1) ? e1 : e2);
    int s = ei[e], d = ei[NEDGE + e];
    int pos = atomicAdd(&g_cur[set * NNODES + d], 1);
    g_csr[pos] = s;
}

// ------------- W split+transpose -------------
__global__ void conv_w(const float* __restrict__ W1, const float* __restrict__ W2) {
    int idx = blockIdx.x * blockDim.x + threadIdx.x;
    if (idx >= 2000 * 160) return;
    int k = idx / 160, n = idx - k * 160;
    const float* Wsrc = (n < 80) ? W1 : W2;
    int nn = (n < 80) ? n : n - 80;
    int s = nn / 20, o = nn % 20;
    float w = Wsrc[((size_t)s * 2000 + k) * 20 + o];
    __nv_bfloat16 h = __float2bfloat16(w);
    g_wt_hi[idx] = h;
    g_wt_lo[idx] = __float2bfloat16(w - __bfloat162float(h));
}

// ------------------------- big GEMM via mma.sync bf16-split ----------------
#define SA_STRIDE 168
#define SB_STRIDE 168

__global__ void __launch_bounds__(256)
gemm_big_mma(const float* __restrict__ A,
             const float* __restrict__ b1, const float* __restrict__ b2,
             float* __restrict__ outA, float* __restrict__ outB) {
    extern __shared__ __align__(16) char dsm[];
    __nv_bfloat16* sA = (__nv_bfloat16*)dsm;
    __nv_bfloat16* sB = (__nv_bfloat16*)(dsm + 128 * SA_STRIDE * 2);
    __shared__ float s_bias[160];

    const int tid = threadIdx.x, wid = tid >> 5, lane = tid & 31;
    const int rowbase = blockIdx.x * 128;
    if (tid < 160) s_bias[tid] = (tid < 80) ? b1[tid] : b2[tid - 80];

    float acc[20][4];
#pragma unroll
    for (int t = 0; t < 20; t++)
#pragma unroll
        for (int i = 0; i < 4; i++) acc[t][i] = 0.f;

    const int r_in = lane & 7, blkb = (lane >> 3) & 1, kh = (lane >> 4) & 1;
    const uint32_t aBase =
        smem_u32(sA) + (uint32_t)((wid * 16 + blkb * 8 + r_in) * SA_STRIDE + kh * 8) * 2;
    const uint32_t bBase2 = smem_u32(sB) + (uint32_t)((lane & 15) * SB_STRIDE) * 2;
    const uint32_t bBase4 = smem_u32(sB) + (uint32_t)(lane * SB_STRIDE) * 2;

    const int a0off[7] = {0, 32, 64, 16, 48, 80, 112};
    const int a1off[7] = {16, 48, 0, 32, 64, 96, 128};
    const int browt[7] = {0, 32, 64, 96, 128, 0, 32};

    for (int ch = 0; ch < 25; ch++) {
        const int k0 = ch * 80;
#pragma unroll
        for (int it = 0; it < 13; it++) {
            int q = tid + it * 256;
            if (q < 3200) {
                int row = q / 20, c16 = q - row * 20;
                int kk = (row >= 80) ? row - 80 : row;
                const __nv_bfloat16* src =
                    ((row >= 80) ? g_wt_lo : g_wt_hi) + (size_t)(k0 + kk) * 160 + c16 * 8;
                uint32_t dst = smem_u32(sB) + (uint32_t)(row * SB_STRIDE + c16 * 8) * 2;
                asm volatile("cp.async.ca.shared.global [%0], [%1], 16;"
                             :: "r"(dst), "l"(src));
            }
        }
        asm volatile("cp.async.commit_group;" ::: "memory");
#pragma unroll
        for (int it = 0; it < 10; it++) {
            int q = tid + it * 256;
            int r = q / 20, f = q - r * 20;
            int row = rowbase + r;
            float4 v = (row < NNODES)
                           ? *(const float4*)(A + (size_t)row * 2000 + k0 + f * 4)
                           : make_float4(0.f, 0.f, 0.f, 0.f);
            float l0, l1, l2, l3;
            uint32_t h0 = packbf2(v.x, v.y, &l0, &l1);
            uint32_t h1 = packbf2(v.z, v.w, &l2, &l3);
            uint32_t p0 = packbf2s(l0, l1), p1 = packbf2s(l2, l3);
            int k = f * 4;
            __nv_bfloat16* rp = sA + r * SA_STRIDE;
            *(uint32_t*)(rp + k) = h0;
            *(uint32_t*)(rp + k + 2) = h1;
            *(uint32_t*)(rp + 80 + k) = p0;
            *(uint32_t*)(rp + 82 + k) = p1;
        }
        asm volatile("cp.async.wait_group 0;" ::: "memory");
        __syncthreads();
#pragma unroll
        for (int jp = 0; jp < 7; jp++) {
            uint32_t a0, a1, a2, a3, c0, c1, c2, c3;
            asm volatile(
                "ldmatrix.sync.aligned.m8n8.x4.shared.b16 {%0,%1,%2,%3}, [%4];"
                : "=r"(a0), "=r"(a1), "=r"(a2), "=r"(a3)
                : "r"(aBase + (uint32_t)a0off[jp] * 2));
            asm volatile(
                "ldmatrix.sync.aligned.m8n8.x4.shared.b16 {%0,%1,%2,%3}, [%4];"
                : "=r"(c0), "=r"(c1), "=r"(c2), "=r"(c3)
                : "r"(aBase + (uint32_t)a1off[jp] * 2));
            const uint32_t bb = bBase4 + (uint32_t)(browt[jp] * SB_STRIDE) * 2;
#pragma unroll
            for (int t = 0; t < 20; t++) {
                uint32_t b0, b1, b2, b3;
                asm volatile(
                    "ldmatrix.sync.aligned.m8n8.x4.trans.shared.b16 {%0,%1,%2,%3}, [%4];"
                    : "=r"(b0), "=r"(b1), "=r"(b2), "=r"(b3)
                    : "r"(bb + (uint32_t)t * 16));
                asm volatile(
                    "mma.sync.aligned.m16n8k16.row.col.f32.bf16.bf16.f32 "
                    "{%0,%1,%2,%3}, {%4,%5,%6,%7}, {%8,%9}, {%0,%1,%2,%3};"
                    : "+f"(acc[t][0]), "+f"(acc[t][1]), "+f"(acc[t][2]), "+f"(acc[t][3])
                    : "r"(a0), "r"(a1), "r"(a2), "r"(a3), "r"(b0), "r"(b1));
                asm volatile(
                    "mma.sync.aligned.m16n8k16.row.col.f32.bf16.bf16.f32 "
                    "{%0,%1,%2,%3}, {%4,%5,%6,%7}, {%8,%9}, {%0,%1,%2,%3};"
                    : "+f"(acc[t][0]), "+f"(acc[t][1]), "+f"(acc[t][2]), "+f"(acc[t][3])
                    : "r"(c0), "r"(c1), "r"(c2), "r"(c3), "r"(b2), "r"(b3));
            }
        }
        {
            uint32_t a0, a1, a2, a3;
            asm volatile(
                "ldmatrix.sync.aligned.m8n8.x4.shared.b16 {%0,%1,%2,%3}, [%4];"
                : "=r"(a0), "=r"(a1), "=r"(a2), "=r"(a3)
                : "r"(aBase + 144u * 2));
            const uint32_t bb = bBase2 + (uint32_t)(64 * SB_STRIDE) * 2;
#pragma unroll
            for (int t = 0; t < 20; t++) {
                uint32_t b0, b1;
                asm volatile(
                    "ldmatrix.sync.aligned.m8n8.x2.trans.shared.b16 {%0,%1}, [%2];"
                    : "=r"(b0), "=r"(b1)
                    : "r"(bb + (uint32_t)t * 16));
                asm volatile(
                    "mma.sync.aligned.m16n8k16.row.col.f32.bf16.bf16.f32 "
                    "{%0,%1,%2,%3}, {%4,%5,%6,%7}, {%8,%9}, {%0,%1,%2,%3};"
                    : "+f"(acc[t][0]), "+f"(acc[t][1]), "+f"(acc[t][2]), "+f"(acc[t][3])
                    : "r"(a0), "r"(a1), "r"(a2), "r"(a3), "r"(b0), "r"(b1));
            }
        }
        __syncthreads();
    }

    const int r0 = rowbase + wid * 16 + lane / 4;
    const int r1 = r0 + 8;
    const int cb = (lane & 3) * 2;
#pragma unroll
    for (int t = 0; t < 20; t++) {
        int col = t * 8 + cb;
        float* base = (col < 80) ? outA : outB;
        int cc = (col < 80) ? col : col - 80;
        float bia0 = s_bias[col], bia1 = s_bias[col + 1];
        if (r0 < NNODES)
            *(float2*)(base + (size_t)r0 * 80 + cc) =
                make_float2(acc[t][0] + bia0, acc[t][1] + bia1);
        if (r1 < NNODES)
            *(float2*)(base + (size_t)r1 * 80 + cc) =
                make_float2(acc[t][2] + bia0, acc[t][3] + bia1);
    }
}

// --------------- fused small GEMMs: up to 3 convs in one launch ------------
__global__ void __launch_bounds__(256)
gemm_small3(const float* __restrict__ preA, const float* __restrict__ preB,
            const float* __restrict__ stX, const float* __restrict__ stY,
            const float* __restrict__ g1, const float* __restrict__ be1,
            const float* __restrict__ g2, const float* __restrict__ be2,
            const float* __restrict__ Wc3, const float* __restrict__ bc3,
            float* __restrict__ outC,
            const float* __restrict__ Wc1, const float* __restrict__ bc1,
            float* __restrict__ outA,
            const float* __restrict__ Wc2, const float* __restrict__ bc2,
            float* __restrict__ outB) {
    const int set = blockIdx.x / GB_SM;
    const int bi = blockIdx.x - set * GB_SM;
    const bool swap = (set == 2);
    const float* preX = swap ? preB : preA;
    const float* preY = swap ? preA : preB;
    const float* statsX = swap ? stY : stX;
    const float* statsY = swap ? stX : stY;
    const float* gX = swap ? g2 : g1;
    const float* betX = swap ? be2 : be1;
    const float* gY = swap ? g1 : g2;
    const float* betY = swap ? be1 : be2;
    const float* W = (set == 0) ? Wc3 : ((set == 1) ? Wc1 : Wc2);
    const float* b = (set == 0) ? bc3 : ((set == 1) ? bc1 : bc2);
    float* out = (set == 0) ? outC : ((set == 1) ? outA : outB);

    __shared__ __align__(8) float sW[40][80];
    __shared__ float sb[80];
    __shared__ float sMu[40], sScv[40], sBeta[40];
    const int tid = threadIdx.x;
    for (int l = tid; l < 3200; l += 256) {
        int s = l / 800, rem = l % 800, k = rem / 20, o = rem % 20;
        sW[k][s * 20 + o] = W[l];
    }
    if (tid < 80) sb[tid] = b[tid];
    if (tid < 40) {
        const float invN = 1.f / (float)NNODES;
        int c = tid % 20;
        const float* st = (tid < 20) ? statsX : statsY;
        const float* gg = (tid < 20) ? gX : gY;
        const float* bb = (tid < 20) ? betX : betY;
        float mu = st[c] * invN;
        float var = st[20 + c] * invN - mu * mu;
        sMu[tid] = mu;
        sScv[tid] = gg[c] * rsqrtf(var + EPS_BN);
        sBeta[tid] = bb[c];
    }
    __syncthreads();

    const int row = bi * 128 + (tid >> 1);
    const int cb = (tid & 1) * 40;
    if (row >= NNODES) return;

    float a[40];
    {
        const float4* pa = (const float4*)(preX + (size_t)row * 20);
        const float4* pb = (const float4*)(preY + (size_t)row * 20);
        float4 va[5], vb[5];
#pragma unroll
        for (int i = 0; i < 5; i++) va[i] = pa[i];
#pragma unroll
        for (int i = 0; i < 5; i++) vb[i] = pb[i];
#pragma unroll
        for (int i = 0; i < 5; i++) {
            a[4 * i]     = va[i].x; a[4 * i + 1] = va[i].y;
            a[4 * i + 2] = va[i].z; a[4 * i + 3] = va[i].w;
            a[20 + 4 * i] = vb[i].x; a[21 + 4 * i] = vb[i].y;
            a[22 + 4 * i] = vb[i].z; a[23 + 4 * i] = vb[i].w;
        }
    }
#pragma unroll
    for (int k = 0; k < 40; k++) {
        float v = (a[k] - sMu[k]) * sScv[k] + sBeta[k];
        a[k] = (v >= 0.f) ? v : LSLOPE * v;
    }

    unsigned long long acc[20];
#pragma unroll
    for (int c = 0; c < 20; c++) acc[c] = 0ull;
#pragma unroll 8
    for (int k = 0; k < 40; k++) {
        unsigned long long a2 = pack2(a[k], a[k]);
        const unsigned long long* wrow = (const unsigned long long*)(&sW[k][cb]);
#pragma unroll
        for (int c = 0; c < 20; c++) acc[c] = ffma2(a2, wrow[c], acc[c]);
    }

    float res[40];
#pragma unroll
    for (int c = 0; c < 20; c++) {
        res[2 * c]     = __uint_as_float((unsigned)(acc[c] & 0xffffffffull)) + sb[cb + 2 * c];
        res[2 * c + 1] = __uint_as_float((unsigned)(acc[c] >> 32)) + sb[cb + 2 * c + 1];
    }
    float* dst = out + (size_t)row * 80 + cb;
#pragma unroll
    for (int c = 0; c < 40; c += 4)
        *(float4*)(dst + c) = make_float4(res[c], res[c + 1], res[c + 2], res[c + 3]);
}

// ------------------------- CSR aggregation, 8-edge unroll ------------------
__global__ void __launch_bounds__(256)
agg_csr3(const float* __restrict__ q0, int nb0, float* __restrict__ p0, float* __restrict__ s0,
         const float* __restrict__ q1, int nb1, float* __restrict__ p1, float* __restrict__ s1,
         const float* __restrict__ q2, int nb2, float* __restrict__ p2, float* __restrict__ s2) {
    const int set = blockIdx.x / GA_BLK;
    const int bi = blockIdx.x - set * GA_BLK;
    const float* qkv = (set == 0) ? q0 : ((set == 1) ? q1 : q2);
    float* pre = (set == 0) ? p0 : ((set == 1) ? p1 : p2);
    float* stats = (set == 0) ? s0 : ((set == 1) ? s1 : s2);
    const int nbase = (set == 0) ? nb0 : ((set == 1) ? nb1 : nb2);

    const int wid = threadIdx.x >> 5, lane = threadIdx.x & 31;
    const int n = bi * 8 + wid;
    const bool act = lane < 20;
    const int c = lane;

    __shared__ float sst[2][8][20];
    for (int l = threadIdx.x; l < 320; l += 256) ((float*)sst)[l] = 0.f;
    __syncthreads();

    if (n < NNODES) {
        const int gi = nbase + n;
        const int off0 = g_off[gi], off1 = g_off[gi + 1];
        const float qc = act ? qkv[(size_t)n * 80 + c] * 0.22360679774997896f : 0.f;
        float acc = 0.f, denom = 0.f;
        int p = off0;
        for (; p + 8 <= off1; p += 8) {
            int si[8];
#pragma unroll
            for (int i = 0; i < 8; i++) si[i] = g_csr[p + i];
            float kk[8], vv[8];
#pragma unroll
            for (int i = 0; i < 8; i++) {
                kk[i] = act ? qkv[(size_t)si[i] * 80 + 20 + c] : 0.f;
                vv[i] = act ? qkv[(size_t)si[i] * 80 + 40 + c] : 0.f;
            }
            float d[8];
#pragma unroll
            for (int i = 0; i < 8; i++) d[i] = qc * kk[i];
#pragma unroll
            for (int o = 16; o; o >>= 1) {
#pragma unroll
                for (int i = 0; i < 8; i++) d[i] += __shfl_xor_sync(~0u, d[i], o);
            }
#pragma unroll
            for (int i = 0; i < 8; i++) {
                float e = __expf(d[i]);
                denom += e;
                acc += e * vv[i];
            }
        }
        if (p + 4 <= off1) {
            int si[4];
#pragma unroll
            for (int i = 0; i < 4; i++) si[i] = g_csr[p + i];
            float kk[4], vv[4], d[4];
#pragma unroll
            for (int i = 0; i < 4; i++) {
                kk[i] = act ? qkv[(size_t)si[i] * 80 + 20 + c] : 0.f;
                vv[i] = act ? qkv[(size_t)si[i] * 80 + 40 + c] : 0.f;
            }
#pragma unroll
            for (int i = 0; i < 4; i++) d[i] = qc * kk[i];
#pragma unroll
            for (int o = 16; o; o >>= 1) {
#pragma unroll
                for (int i = 0; i < 4; i++) d[i] += __shfl_xor_sync(~0u, d[i], o);
            }
#pragma unroll
            for (int i = 0; i < 4; i++) {
                float e = __expf(d[i]);
                denom += e;
                acc += e * vv[i];
            }
            p += 4;
        }
        for (; p < off1; p++) {
            int si = g_csr[p];
            float k0 = act ? qkv[(size_t)si * 80 + 20 + c] : 0.f;
            float v0 = act ? qkv[(size_t)si * 80 + 40 + c] : 0.f;
            float d0 = qc * k0;
#pragma unroll
            for (int o = 16; o; o >>= 1) d0 += __shfl_xor_sync(~0u, d0, o);
            float e0 = __expf(d0);
            denom += e0;
            acc += e0 * v0;
        }
        float inv = 1.f / fmaxf(denom, 1e-16f);
        if (act) {
            float r = acc * inv + qkv[(size_t)n * 80 + 60 + c];
            pre[(size_t)n * 20 + c] = r;
            sst[0][wid][c] = r;
            sst[1][wid][c] = r * r;
        }
    }
    __syncthreads();
    if (threadIdx.x < 40) {
        int which = threadIdx.x / 20, cc = threadIdx.x % 20;
        float t = 0.f;
#pragma unroll
        for (int w = 0; w < 8; w++) t += sst[which][w][cc];
        atomicAdd(&stats[which * 20 + cc], t);
    }
}

// ------------------------- BN into fc buffer, final FC ---------------------
__global__ void __launch_bounds__(256)
bn_fc(const float* __restrict__ pre, const float* __restrict__ stats,
      const float* __restrict__ gamma, const float* __restrict__ beta,
      float* __restrict__ dst, int off) {
    int idx = blockIdx.x * blockDim.x + threadIdx.x;
    if (idx >= NNODES * 20) return;
    int n = idx / 20, c = idx % 20;
    const float invN = 1.f / (float)NNODES;
    float mu = stats[c] * invN;
    float var = stats[20 + c] * invN - mu * mu;
    float scv = gamma[c] * rsqrtf(var + EPS_BN);
    float v = (pre[idx] - mu) * scv + beta[c];
    v = (v >= 0.f) ? v : LSLOPE * v;
    dst[(size_t)n * 100 + off + c] = v;
}

__global__ void __launch_bounds__(128)
fc_kernel(const float* __restrict__ W, const float* __restrict__ b,
          float* __restrict__ out) {
    __shared__ float sw[200];
    for (int l = threadIdx.x; l < 200; l += blockDim.x) sw[l] = W[l];
    __syncthreads();
    int n = blockIdx.x * blockDim.x + threadIdx.x;
    if (n >= NNODES) return;
    float a0 = b[0], a1 = b[1];
    const float4* fp = (const float4*)(g_fc + (size_t)n * 100);
#pragma unroll
    for (int i = 0; i < 25; i++) {
        float4 f = fp[i];
        int c = 4 * i;
        a0 += f.x * sw[2 * c] + f.y * sw[2 * c + 2] + f.z * sw[2 * c + 4] + f.w * sw[2 * c + 6];
        a1 += f.x * sw[2 * c + 1] + f.y * sw[2 * c + 3] + f.z * sw[2 * c + 5] + f.w * sw[2 * c + 7];
    }
    out[2 * n] = a0;
    out[2 * n + 1] = a1;
}

// ------------------------- host orchestration -------------------------
extern "C" void kernel_launch(void* const* d_in, const int* in_sizes, int n_in,
                              void* d_out, int out_size) {
    (void)in_sizes; (void)n_in; (void)out_size;
    const float* features = (const float*)d_in[0];
    const int* edge_index = (const int*)d_in[3];
    const int* same2      = (const int*)d_in[4];
    const int* diff2      = (const int*)d_in[5];
    const float* c1_W0 = (const float*)d_in[6];
    const float* c1_b0 = (const float*)d_in[7];
    const float* c2_W0 = (const float*)d_in[8];
    const float* c2_b0 = (const float*)d_in[9];
    const float* c1_W  = (const float*)d_in[10];
    const float* c1_b  = (const float*)d_in[11];
    const float* c2_W  = (const float*)d_in[12];
    const float* c2_b  = (const float*)d_in[13];
    const float* c3_W  = (const float*)d_in[14];
    const float* c3_b  = (const float*)d_in[15];
    const float* bn1_g = (const float*)d_in[16];
    const float* bn1_b = (const float*)d_in[17];
    const float* bn2_g = (const float*)d_in[18];
    const float* bn2_b = (const float*)d_in[19];
    const float* bn3_g = (const float*)d_in[20];
    const float* bn3_b = (const float*)d_in[21];
    const float* fc_W  = (const float*)d_in[22];
    const float* fc_b  = (const float*)d_in[23];
    float* out = (float*)d_out;

    float *qkvA, *qkvB, *qkvC, *preA, *preB, *preC, *fcb, *stats;
    cudaGetSymbolAddress((void**)&qkvA, g_qkvA);
    cudaGetSymbolAddress((void**)&qkvB, g_qkvB);
    cudaGetSymbolAddress((void**)&qkvC, g_qkvC);
    cudaGetSymbolAddress((void**)&preA, g_preA);
    cudaGetSymbolAddress((void**)&preB, g_preB);
    cudaGetSymbolAddress((void**)&preC, g_preC);
    cudaGetSymbolAddress((void**)&fcb, g_fc);
    cudaGetSymbolAddress((void**)&stats, g_stats);

    const int G3E = (3 * NEDGE + 255) / 256;
    const int GN = (NNODES * 20 + 255) / 256;
    const int SMEM_MMA = (128 * SA_STRIDE + 160 * SB_STRIDE) * 2;

    cudaFuncSetAttribute(gemm_big_mma, cudaFuncAttributeMaxDynamicSharedMemorySize,
                         SMEM_MMA);

    // ---- CSR build + weight split/transpose ----
    zero_all<<<(NN3 + 255) / 256, 256>>>();
    hist_kernel<<<G3E, 256>>>(same2, diff2, edge_index);
    conv_w<<<(2000 * 160 + 255) / 256, 256>>>(c1_W0, c2_W0);
    scanA<<<SCAN_BLOCKS, 1024>>>();
    scanB<<<1, 256>>>();
    scanC<<<SCAN_BLOCKS, 1024>>>();
    scatter_kernel<<<G3E, 256>>>(same2, diff2, edge_index);

    // ---- layer 0 ----
    gemm_big_mma<<<GB_SM, 256, SMEM_MMA>>>(features, c1_b0, c2_b0, qkvA, qkvB);
    agg_csr3<<<2 * GA_BLK, 256>>>(qkvA, 0, preA, stats + 0 * 40,
                                  qkvB, NNODES, preB, stats + 1 * 40,
                                  qkvA, 0, preA, stats + 0 * 40);

    for (int L = 0; L <= 4; L++) {
        const float* stX = stats + (3 * L) * 40;
        const float* stY = stats + (3 * L + 1) * 40;
        const float* g1 = bn1_g + L * 20; const float* b1 = bn1_b + L * 20;
        const float* g2 = bn2_g + L * 20; const float* b2 = bn2_b + L * 20;

        if (L < 4) {
            gemm_small3<<<3 * GB_SM, 256>>>(
                preA, preB, stX, stY, g1, b1, g2, b2,
                c3_W + (size_t)L * 3200, c3_b + (size_t)L * 80, qkvC,
                c1_W + (size_t)L * 3200, c1_b + (size_t)L * 80, qkvA,
                c2_W + (size_t)L * 3200, c2_b + (size_t)L * 80, qkvB);
            agg_csr3<<<3 * GA_BLK, 256>>>(qkvC, 2 * NNODES, preC, stats + (3 * L + 2) * 40,
                                          qkvA, 0, preA, stats + (3 * L + 3) * 40,
                                          qkvB, NNODES, preB, stats + (3 * L + 4) * 40);
        } else {
            gemm_small3<<<GB_SM, 256>>>(
                preA, preB, stX, stY, g1, b1, g2, b2,
                c3_W + (size_t)L * 3200, c3_b + (size_t)L * 80, qkvC,
                c3_W + (size_t)L * 3200, c3_b + (size_t)L * 80, qkvC,
                c3_W + (size_t)L * 3200, c3_b + (size_t)L * 80, qkvC);
            agg_csr3<<<GA_BLK, 256>>>(qkvC, 2 * NNODES, preC, stats + (3 * L + 2) * 40,
                                      qkvC, 2 * NNODES, preC, stats + (3 * L + 2) * 40,
                                      qkvC, 2 * NNODES, preC, stats + (3 * L + 2) * 40);
        }
        bn_fc<<<GN, 256>>>(preC, stats + (3 * L + 2) * 40,
                           bn3_g + L * 20, bn3_b + L * 20, fcb, L * 20);
    }

    fc_kernel<<<(NNODES + 127) / 128, 128>>>(fc_W, fc_b, out);
}

// round 10
// speedup vs baseline: 2.3572x; 1.0020x over previous
#include <cuda_runtime.h>
#include <cuda_bf16.h>
#include <cstdint>

#define NNODES 50000
#define NEDGE  1000000
#define DIN0   2000
#define EPS_BN 1e-5f
#define LSLOPE 0.01f
#define NN3    150000
#define SCAN_BLOCKS 147
#define GA_BLK 6250   /* (NNODES+7)/8 */
#define GB_SM  391    /* (NNODES+127)/128 */
#define GN_BLK 3907   /* (NNODES*20+255)/256 */

// qkv row layout (80 floats): [ q(0..19) | k0 v0 k1 v1 .. k19 v19 (20..59) | skip(60..79) ]

// ------------------------- scratch (device globals, zero-init) -------------
__device__ float g_qkvA[NNODES * 80];
__device__ float g_qkvB[NNODES * 80];
__device__ float g_qkvC[NNODES * 80];
__device__ float g_preA[NNODES * 20];
__device__ float g_preB[NNODES * 20];
__device__ float g_preC[NNODES * 20];
__device__ float g_fc[NNODES * 100];
__device__ float g_stats[15 * 40];
__device__ __nv_bfloat16 g_wt_hi[2000 * 160];
__device__ __nv_bfloat16 g_wt_lo[2000 * 160];
// CSR scratch
__device__ int g_cnt[NN3];
__device__ int g_off[NN3 + 1];
__device__ int g_cur[NN3];
__device__ int g_csr[3 * NEDGE];
__device__ int g_partraw[SCAN_BLOCKS];
__device__ int g_part[SCAN_BLOCKS];

// ------------------------- helpers -------------------------
__device__ __forceinline__ unsigned long long ffma2(unsigned long long a,
                                                    unsigned long long b,
                                                    unsigned long long c) {
    unsigned long long d;
    asm("fma.rn.f32x2 %0, %1, %2, %3;" : "=l"(d) : "l"(a), "l"(b), "l"(c));
    return d;
}
__device__ __forceinline__ unsigned long long pack2(float lo, float hi) {
    unsigned long long r;
    asm("mov.b64 %0, {%1, %2};" : "=l"(r) : "f"(lo), "f"(hi));
    return r;
}
__device__ __forceinline__ uint32_t smem_u32(const void* p) {
    uint32_t a;
    asm("{ .reg .u64 t; cvta.to.shared.u64 t, %1; cvt.u32.u64 %0, t; }"
        : "=r"(a) : "l"(p));
    return a;
}
__device__ __forceinline__ uint32_t packbf2(float a, float b, float* lo_a, float* lo_b) {
    __nv_bfloat16 ha = __float2bfloat16(a), hb = __float2bfloat16(b);
    *lo_a = a - __bfloat162float(ha);
    *lo_b = b - __bfloat162float(hb);
    __nv_bfloat162 p; p.x = ha; p.y = hb;
    return *(uint32_t*)&p;
}
__device__ __forceinline__ uint32_t packbf2s(float a, float b) {
    __nv_bfloat162 p; p.x = __float2bfloat16(a); p.y = __float2bfloat16(b);
    return *(uint32_t*)&p;
}
// logical qkv column (0..79) -> interleaved position
__device__ __forceinline__ int qkvpos(int c) {
    if (c < 20) return c;
    if (c < 40) return 2 * c - 20;   // k_c -> 20+2c
    if (c < 60) return 2 * c - 59;   // v_c -> 21+2c
    return c;
}

// ------------------------- CSR build -------------------------
__global__ void zero_all() {
    int i = blockIdx.x * blockDim.x + threadIdx.x;
    if (i < NN3) g_cnt[i] = 0;
    if (i < 15 * 40) g_stats[i] = 0.f;
}
__global__ void hist_kernel(const int* __restrict__ e0, const int* __restrict__ e1,
                            const int* __restrict__ e2) {
    int i = blockIdx.x * blockDim.x + threadIdx.x;
    if (i >= 3 * NEDGE) return;
    int set = i / NEDGE, e = i - set * NEDGE;
    const int* ei = (set == 0) ? e0 : ((set == 1) ? e1 : e2);
    atomicAdd(&g_cnt[set * NNODES + ei[NEDGE + e]], 1);
}
__global__ void __launch_bounds__(1024) scanA() {
    int gid = blockIdx.x * 1024 + threadIdx.x;
    int v = (gid < NN3) ? g_cnt[gid] : 0;
#pragma unroll
    for (int o = 16; o; o >>= 1) v += __shfl_xor_sync(~0u, v, o);
    __shared__ int sw[32];
    if ((threadIdx.x & 31) == 0) sw[threadIdx.x >> 5] = v;
    __syncthreads();
    if (threadIdx.x < 32) {
        int t = sw[threadIdx.x];
#pragma unroll
        for (int o = 16; o; o >>= 1) t += __shfl_xor_sync(~0u, t, o);
        if (threadIdx.x == 0) g_partraw[blockIdx.x] = t;
    }
}
__global__ void scanB() {
    __shared__ int sp[SCAN_BLOCKS + 1];
    int tid = threadIdx.x;
    if (tid < SCAN_BLOCKS) sp[tid + 1] = g_partraw[tid];
    if (tid == 0) sp[0] = 0;
    __syncthreads();
    if (tid == 0)
        for (int b = 1; b <= SCAN_BLOCKS; b++) sp[b] += sp[b - 1];
    __syncthreads();
    if (tid < SCAN_BLOCKS) g_part[tid] = sp[tid];
}
__global__ void __launch_bounds__(1024) scanC() {
    __shared__ int sdat[1024];
    int tid = threadIdx.x;
    int gid = blockIdx.x * 1024 + tid;
    int v = (gid < NN3) ? g_cnt[gid] : 0;
    sdat[tid] = v;
    __syncthreads();
    for (int o = 1; o < 1024; o <<= 1) {
        int t = (tid >= o) ? sdat[tid - o] : 0;
        __syncthreads();
        sdat[tid] += t;
        __syncthreads();
    }
    int excl = sdat[tid] - v + g_part[blockIdx.x];
    if (gid < NN3) { g_off[gid] = excl; g_cur[gid] = excl; }
    if (gid == 0) g_off[NN3] = 3 * NEDGE;
}
__global__ void scatter_kernel(const int* __restrict__ e0, const int* __restrict__ e1,
                               const int* __restrict__ e2) {
    int i = blockIdx.x * blockDim.x + threadIdx.x;
    if (i >= 3 * NEDGE) return;
    int set = i / NEDGE, e = i - set * NEDGE;
    const int* ei = (set == 0) ? e0 : ((set == 1) ? e1 : e2);
    int s = ei[e], d = ei[NEDGE + e];
    int pos = atomicAdd(&g_cur[set * NNODES + d], 1);
    g_csr[pos] = s;
}

// ------------- W split+transpose with kv-interleave column permutation -----
__global__ void conv_w(const float* __restrict__ W1, const float* __restrict__ W2) {
    int idx = blockIdx.x * blockDim.x + threadIdx.x;
    if (idx >= 2000 * 160) return;
    int k = idx / 160, n = idx - k * 160;
    const float* Wsrc = (n < 80) ? W1 : W2;
    int nn = (n < 80) ? n : n - 80;
    int s = nn / 20, o = nn % 20;
    float w = Wsrc[((size_t)s * 2000 + k) * 20 + o];
    __nv_bfloat16 h = __float2bfloat16(w);
    int nperm = ((n < 80) ? 0 : 80) + qkvpos(nn);
    g_wt_hi[(size_t)k * 160 + nperm] = h;
    g_wt_lo[(size_t)k * 160 + nperm] = __float2bfloat16(w - __bfloat162float(h));
}

// ------------------------- big GEMM via mma.sync bf16-split ----------------
#define SA_STRIDE 168
#define SB_STRIDE 168

__global__ void __launch_bounds__(256)
gemm_big_mma(const float* __restrict__ A,
             const float* __restrict__ b1, const float* __restrict__ b2,
             float* __restrict__ outA, float* __restrict__ outB) {
    extern __shared__ __align__(16) char dsm[];
    __nv_bfloat16* sA = (__nv_bfloat16*)dsm;
    __nv_bfloat16* sB = (__nv_bfloat16*)(dsm + 128 * SA_STRIDE * 2);
    __shared__ float s_bias[160];

    const int tid = threadIdx.x, wid = tid >> 5, lane = tid & 31;
    const int rowbase = blockIdx.x * 128;
    if (tid < 160) {  // bias permuted to match interleaved output columns
        int g = tid / 80, c = tid % 80;
        float bv = (g == 0) ? b1[c] : b2[c];
        s_bias[g * 80 + qkvpos(c)] = bv;
    }

    float acc[20][4];
#pragma unroll
    for (int t = 0; t < 20; t++)
#pragma unroll
        for (int i = 0; i < 4; i++) acc[t][i] = 0.f;

    const int r_in = lane & 7, blkb = (lane >> 3) & 1, kh = (lane >> 4) & 1;
    const uint32_t aBase =
        smem_u32(sA) + (uint32_t)((wid * 16 + blkb * 8 + r_in) * SA_STRIDE + kh * 8) * 2;
    const uint32_t bBase2 = smem_u32(sB) + (uint32_t)((lane & 15) * SB_STRIDE) * 2;
    const uint32_t bBase4 = smem_u32(sB) + (uint32_t)(lane * SB_STRIDE) * 2;

    const int a0off[7] = {0, 32, 64, 16, 48, 80, 112};
    const int a1off[7] = {16, 48, 0, 32, 64, 96, 128};
    const int browt[7] = {0, 32, 64, 96, 128, 0, 32};

    for (int ch = 0; ch < 25; ch++) {
        const int k0 = ch * 80;
#pragma unroll
        for (int it = 0; it < 13; it++) {
            int q = tid + it * 256;
            if (q < 3200) {
                int row = q / 20, c16 = q - row * 20;
                int kk = (row >= 80) ? row - 80 : row;
                const __nv_bfloat16* src =
                    ((row >= 80) ? g_wt_lo : g_wt_hi) + (size_t)(k0 + kk) * 160 + c16 * 8;
                uint32_t dst = smem_u32(sB) + (uint32_t)(row * SB_STRIDE + c16 * 8) * 2;
                asm volatile("cp.async.ca.shared.global [%0], [%1], 16;"
                             :: "r"(dst), "l"(src));
            }
        }
        asm volatile("cp.async.commit_group;" ::: "memory");
#pragma unroll
        for (int it = 0; it < 10; it++) {
            int q = tid + it * 256;
            int r = q / 20, f = q - r * 20;
            int row = rowbase + r;
            float4 v = (row < NNODES)
                           ? *(const float4*)(A + (size_t)row * 2000 + k0 + f * 4)
                           : make_float4(0.f, 0.f, 0.f, 0.f);
            float l0, l1, l2, l3;
            uint32_t h0 = packbf2(v.x, v.y, &l0, &l1);
            uint32_t h1 = packbf2(v.z, v.w, &l2, &l3);
            uint32_t p0 = packbf2s(l0, l1), p1 = packbf2s(l2, l3);
            int k = f * 4;
            __nv_bfloat16* rp = sA + r * SA_STRIDE;
            *(uint32_t*)(rp + k) = h0;
            *(uint32_t*)(rp + k + 2) = h1;
            *(uint32_t*)(rp + 80 + k) = p0;
            *(uint32_t*)(rp + 82 + k) = p1;
        }
        asm volatile("cp.async.wait_group 0;" ::: "memory");
        __syncthreads();
#pragma unroll
        for (int jp = 0; jp < 7; jp++) {
            uint32_t a0, a1, a2, a3, c0, c1, c2, c3;
            asm volatile(
                "ldmatrix.sync.aligned.m8n8.x4.shared.b16 {%0,%1,%2,%3}, [%4];"
                : "=r"(a0), "=r"(a1), "=r"(a2), "=r"(a3)
                : "r"(aBase + (uint32_t)a0off[jp] * 2));
            asm volatile(
                "ldmatrix.sync.aligned.m8n8.x4.shared.b16 {%0,%1,%2,%3}, [%4];"
                : "=r"(c0), "=r"(c1), "=r"(c2), "=r"(c3)
                : "r"(aBase + (uint32_t)a1off[jp] * 2));
            const uint32_t bb = bBase4 + (uint32_t)(browt[jp] * SB_STRIDE) * 2;
#pragma unroll
            for (int t = 0; t < 20; t++) {
                uint32_t b0, b1, b2, b3;
                asm volatile(
                    "ldmatrix.sync.aligned.m8n8.x4.trans.shared.b16 {%0,%1,%2,%3}, [%4];"
                    : "=r"(b0), "=r"(b1), "=r"(b2), "=r"(b3)
                    : "r"(bb + (uint32_t)t * 16));
                asm volatile(
                    "mma.sync.aligned.m16n8k16.row.col.f32.bf16.bf16.f32 "
                    "{%0,%1,%2,%3}, {%4,%5,%6,%7}, {%8,%9}, {%0,%1,%2,%3};"
                    : "+f"(acc[t][0]), "+f"(acc[t][1]), "+f"(acc[t][2]), "+f"(acc[t][3])
                    : "r"(a0), "r"(a1), "r"(a2), "r"(a3), "r"(b0), "r"(b1));
                asm volatile(
                    "mma.sync.aligned.m16n8k16.row.col.f32.bf16.bf16.f32 "
                    "{%0,%1,%2,%3}, {%4,%5,%6,%7}, {%8,%9}, {%0,%1,%2,%3};"
                    : "+f"(acc[t][0]), "+f"(acc[t][1]), "+f"(acc[t][2]), "+f"(acc[t][3])
                    : "r"(c0), "r"(c1), "r"(c2), "r"(c3), "r"(b2), "r"(b3));
            }
        }
        {
            uint32_t a0, a1, a2, a3;
            asm volatile(
                "ldmatrix.sync.aligned.m8n8.x4.shared.b16 {%0,%1,%2,%3}, [%4];"
                : "=r"(a0), "=r"(a1), "=r"(a2), "=r"(a3)
                : "r"(aBase + 144u * 2));
            const uint32_t bb = bBase2 + (uint32_t)(64 * SB_STRIDE) * 2;
#pragma unroll
            for (int t = 0; t < 20; t++) {
                uint32_t b0, b1;
                asm volatile(
                    "ldmatrix.sync.aligned.m8n8.x2.trans.shared.b16 {%0,%1}, [%2];"
                    : "=r"(b0), "=r"(b1)
                    : "r"(bb + (uint32_t)t * 16));
                asm volatile(
                    "mma.sync.aligned.m16n8k16.row.col.f32.bf16.bf16.f32 "
                    "{%0,%1,%2,%3}, {%4,%5,%6,%7}, {%8,%9}, {%0,%1,%2,%3};"
                    : "+f"(acc[t][0]), "+f"(acc[t][1]), "+f"(acc[t][2]), "+f"(acc[t][3])
                    : "r"(a0), "r"(a1), "r"(a2), "r"(a3), "r"(b0), "r"(b1));
            }
        }
        __syncthreads();
    }

    const int r0 = rowbase + wid * 16 + lane / 4;
    const int r1 = r0 + 8;
    const int cb = (lane & 3) * 2;
#pragma unroll
    for (int t = 0; t < 20; t++) {
        int col = t * 8 + cb;
        float* base = (col < 80) ? outA : outB;
        int cc = (col < 80) ? col : col - 80;
        float bia0 = s_bias[col], bia1 = s_bias[col + 1];
        if (r0 < NNODES)
            *(float2*)(base + (size_t)r0 * 80 + cc) =
                make_float2(acc[t][0] + bia0, acc[t][1] + bia1);
        if (r1 < NNODES)
            *(float2*)(base + (size_t)r1 * 80 + cc) =
                make_float2(acc[t][2] + bia0, acc[t][3] + bia1);
    }
}

// --------------- fused small GEMMs (+ optional bn_fc block range) ----------
__global__ void __launch_bounds__(256)
gemm_small3(const float* __restrict__ preA, const float* __restrict__ preB,
            const float* __restrict__ stX, const float* __restrict__ stY,
            const float* __restrict__ g1, const float* __restrict__ be1,
            const float* __restrict__ g2, const float* __restrict__ be2,
            const float* __restrict__ Wc3, const float* __restrict__ bc3,
            float* __restrict__ outC,
            const float* __restrict__ Wc1, const float* __restrict__ bc1,
            float* __restrict__ outA,
            const float* __restrict__ Wc2, const float* __restrict__ bc2,
            float* __restrict__ outB,
            int nsets,
            const float* __restrict__ bnPre, const float* __restrict__ bnStats,
            const float* __restrict__ bnG, const float* __restrict__ bnB,
            float* __restrict__ bnDst, int bnOff) {
    const int bnStart = nsets * GB_SM;
    if ((int)blockIdx.x >= bnStart) {
        // ---- fused bn_fc for the previous layer ----
        int idx = (blockIdx.x - bnStart) * 256 + threadIdx.x;
        if (idx >= NNODES * 20) return;
        int n = idx / 20, c = idx % 20;
        const float invN = 1.f / (float)NNODES;
        float mu = bnStats[c] * invN;
        float var = bnStats[20 + c] * invN - mu * mu;
        float scv = bnG[c] * rsqrtf(var + EPS_BN);
        float v = (bnPre[idx] - mu) * scv + bnB[c];
        v = (v >= 0.f) ? v : LSLOPE * v;
        bnDst[(size_t)n * 100 + bnOff + c] = v;
        return;
    }
    const int set = blockIdx.x / GB_SM;
    const int bi = blockIdx.x - set * GB_SM;
    const bool swap = (set == 2);
    const float* preX = swap ? preB : preA;
    const float* preY = swap ? preA : preB;
    const float* statsX = swap ? stY : stX;
    const float* statsY = swap ? stX : stY;
    const float* gX = swap ? g2 : g1;
    const float* betX = swap ? be2 : be1;
    const float* gY = swap ? g1 : g2;
    const float* betY = swap ? be1 : be2;
    const float* W = (set == 0) ? Wc3 : ((set == 1) ? Wc1 : Wc2);
    const float* b = (set == 0) ? bc3 : ((set == 1) ? bc1 : bc2);
    float* out = (set == 0) ? outC : ((set == 1) ? outA : outB);

    __shared__ __align__(8) float sW[40][80];
    __shared__ float sb[80];
    __shared__ float sMu[40], sScv[40], sBeta[40];
    const int tid = threadIdx.x;
    for (int l = tid; l < 3200; l += 256) {
        int s = l / 800, rem = l % 800, k = rem / 20, o = rem % 20;
        sW[k][qkvpos(s * 20 + o)] = W[l];  // permuted output columns
    }
    if (tid < 80) sb[qkvpos(tid)] = b[tid];
    if (tid < 40) {
        const float invN = 1.f / (float)NNODES;
        int c = tid % 20;
        const float* st = (tid < 20) ? statsX : statsY;
        const float* gg = (tid < 20) ? gX : gY;
        const float* bb = (tid < 20) ? betX : betY;
        float mu = st[c] * invN;
        float var = st[20 + c] * invN - mu * mu;
        sMu[tid] = mu;
        sScv[tid] = gg[c] * rsqrtf(var + EPS_BN);
        sBeta[tid] = bb[c];
    }
    __syncthreads();

    const int row = bi * 128 + (tid >> 1);
    const int cb = (tid & 1) * 40;
    if (row >= NNODES) return;

    float a[40];
    {
        const float4* pa = (const float4*)(preX + (size_t)row * 20);
        const float4* pb = (const float4*)(preY + (size_t)row * 20);
        float4 va[5], vb[5];
#pragma unroll
        for (int i = 0; i < 5; i++) va[i] = pa[i];
#pragma unroll
        for (int i = 0; i < 5; i++) vb[i] = pb[i];
#pragma unroll
        for (int i = 0; i < 5; i++) {
            a[4 * i]     = va[i].x; a[4 * i + 1] = va[i].y;
            a[4 * i + 2] = va[i].z; a[4 * i + 3] = va[i].w;
            a[20 + 4 * i] = vb[i].x; a[21 + 4 * i] = vb[i].y;
            a[22 + 4 * i] = vb[i].z; a[23 + 4 * i] = vb[i].w;
        }
    }
#pragma unroll
    for (int k = 0; k < 40; k++) {
        float v = (a[k] - sMu[k]) * sScv[k] + sBeta[k];
        a[k] = (v >= 0.f) ? v : LSLOPE * v;
    }

    unsigned long long acc[20];
#pragma unroll
    for (int c = 0; c < 20; c++) acc[c] = 0ull;
#pragma unroll 8
    for (int k = 0; k < 40; k++) {
        unsigned long long a2 = pack2(a[k], a[k]);
        const unsigned long long* wrow = (const unsigned long long*)(&sW[k][cb]);
#pragma unroll
        for (int c = 0; c < 20; c++) acc[c] = ffma2(a2, wrow[c], acc[c]);
    }

    float res[40];
#pragma unroll
    for (int c = 0; c < 20; c++) {
        res[2 * c]     = __uint_as_float((unsigned)(acc[c] & 0xffffffffull)) + sb[cb + 2 * c];
        res[2 * c + 1] = __uint_as_float((unsigned)(acc[c] >> 32)) + sb[cb + 2 * c + 1];
    }
    float* dst = out + (size_t)row * 80 + cb;
#pragma unroll
    for (int c = 0; c < 40; c += 4)
        *(float4*)(dst + c) = make_float4(res[c], res[c + 1], res[c + 2], res[c + 3]);
}

// ------------------------- CSR aggregation (kv-interleaved reads) ----------
__global__ void __launch_bounds__(256)
agg_csr3(const float* __restrict__ q0, int nb0, float* __restrict__ p0, float* __restrict__ s0,
         const float* __restrict__ q1, int nb1, float* __restrict__ p1, float* __restrict__ s1,
         const float* __restrict__ q2, int nb2, float* __restrict__ p2, float* __restrict__ s2) {
    const int set = blockIdx.x / GA_BLK;
    const int bi = blockIdx.x - set * GA_BLK;
    const float* qkv = (set == 0) ? q0 : ((set == 1) ? q1 : q2);
    float* pre = (set == 0) ? p0 : ((set == 1) ? p1 : p2);
    float* stats = (set == 0) ? s0 : ((set == 1) ? s1 : s2);
    const int nbase = (set == 0) ? nb0 : ((set == 1) ? nb1 : nb2);

    const int wid = threadIdx.x >> 5, lane = threadIdx.x & 31;
    const int n = bi * 8 + wid;
    const bool act = lane < 20;
    const int c = lane;

    __shared__ float sst[2][8][20];
    for (int l = threadIdx.x; l < 320; l += 256) ((float*)sst)[l] = 0.f;
    __syncthreads();

    if (n < NNODES) {
        const int gi = nbase + n;
        const int off0 = g_off[gi], off1 = g_off[gi + 1];
        const float qc = act ? qkv[(size_t)n * 80 + c] * 0.22360679774997896f : 0.f;
        const uint32_t kvoff = 20 + 2 * c;
        float acc = 0.f, denom = 0.f;
        int p = off0;
        for (; p + 8 <= off1; p += 8) {
            int si[8];
#pragma unroll
            for (int i = 0; i < 8; i++) si[i] = g_csr[p + i];
            float2 kv[8];
#pragma unroll
            for (int i = 0; i < 8; i++)
                kv[i] = act ? *(const float2*)(qkv + (size_t)si[i] * 80 + kvoff)
                            : make_float2(0.f, 0.f);
            float d[8];
#pragma unroll
            for (int i = 0; i < 8; i++) d[i] = qc * kv[i].x;
#pragma unroll
            for (int o = 16; o; o >>= 1) {
#pragma unroll
                for (int i = 0; i < 8; i++) d[i] += __shfl_xor_sync(~0u, d[i], o);
            }
#pragma unroll
            for (int i = 0; i < 8; i++) {
                float e = __expf(d[i]);
                denom += e;
                acc += e * kv[i].y;
            }
        }
        if (p + 4 <= off1) {
            int si[4];
#pragma unroll
            for (int i = 0; i < 4; i++) si[i] = g_csr[p + i];
            float2 kv[4];
            float d[4];
#pragma unroll
            for (int i = 0; i < 4; i++)
                kv[i] = act ? *(const float2*)(qkv + (size_t)si[i] * 80 + kvoff)
                            : make_float2(0.f, 0.f);
#pragma unroll
            for (int i = 0; i < 4; i++) d[i] = qc * kv[i].x;
#pragma unroll
            for (int o = 16; o; o >>= 1) {
#pragma unroll
                for (int i = 0; i < 4; i++) d[i] += __shfl_xor_sync(~0u, d[i], o);
            }
#pragma unroll
            for (int i = 0; i < 4; i++) {
                float e = __expf(d[i]);
                denom += e;
                acc += e * kv[i].y;
            }
            p += 4;
        }
        for (; p < off1; p++) {
            int si = g_csr[p];
            float2 kv = act ? *(const float2*)(qkv + (size_t)si * 80 + kvoff)
                            : make_float2(0.f, 0.f);
            float d0 = qc * kv.x;
#pragma unroll
            for (int o = 16; o; o >>= 1) d0 += __shfl_xor_sync(~0u, d0, o);
            float e0 = __expf(d0);
            denom += e0;
            acc += e0 * kv.y;
        }
        float inv = 1.f / fmaxf(denom, 1e-16f);
        if (act) {
            float r = acc * inv + qkv[(size_t)n * 80 + 60 + c];
            pre[(size_t)n * 20 + c] = r;
            sst[0][wid][c] = r;
            sst[1][wid][c] = r * r;
        }
    }
    __syncthreads();
    if (threadIdx.x < 40) {
        int which = threadIdx.x / 20, cc = threadIdx.x % 20;
        float t = 0.f;
#pragma unroll
        for (int w = 0; w < 8; w++) t += sst[which][w][cc];
        atomicAdd(&stats[which * 20 + cc], t);
    }
}

// ------------------------- standalone bn_fc (last layer) + final FC --------
__global__ void __launch_bounds__(256)
bn_fc(const float* __restrict__ pre, const float* __restrict__ stats,
      const float* __restrict__ gamma, const float* __restrict__ beta,
      float* __restrict__ dst, int off) {
    int idx = blockIdx.x * blockDim.x + threadIdx.x;
    if (idx >= NNODES * 20) return;
    int n = idx / 20, c = idx % 20;
    const float invN = 1.f / (float)NNODES;
    float mu = stats[c] * invN;
    float var = stats[20 + c] * invN - mu * mu;
    float scv = gamma[c] * rsqrtf(var + EPS_BN);
    float v = (pre[idx] - mu) * scv + beta[c];
    v = (v >= 0.f) ? v : LSLOPE * v;
    dst[(size_t)n * 100 + off + c] = v;
}

__global__ void __launch_bounds__(128)
fc_kernel(const float* __restrict__ W, const float* __restrict__ b,
          float* __restrict__ out) {
    __shared__ float sw[200];
    for (int l = threadIdx.x; l < 200; l += blockDim.x) sw[l] = W[l];
    __syncthreads();
    int n = blockIdx.x * blockDim.x + threadIdx.x;
    if (n >= NNODES) return;
    float a0 = b[0], a1 = b[1];
    const float4* fp = (const float4*)(g_fc + (size_t)n * 100);
#pragma unroll
    for (int i = 0; i < 25; i++) {
        float4 f = fp[i];
        int c = 4 * i;
        a0 += f.x * sw[2 * c] + f.y * sw[2 * c + 2] + f.z * sw[2 * c + 4] + f.w * sw[2 * c + 6];
        a1 += f.x * sw[2 * c + 1] + f.y * sw[2 * c + 3] + f.z * sw[2 * c + 5] + f.w * sw[2 * c + 7];
    }
    out[2 * n] = a0;
    out[2 * n + 1] = a1;
}

// ------------------------- host orchestration -------------------------
extern "C" void kernel_launch(void* const* d_in, const int* in_sizes, int n_in,
                              void* d_out, int out_size) {
    (void)in_sizes; (void)n_in; (void)out_size;
    const float* features = (const float*)d_in[0];
    const int* edge_index = (const int*)d_in[3];
    const int* same2      = (const int*)d_in[4];
    const int* diff2      = (const int*)d_in[5];
    const float* c1_W0 = (const float*)d_in[6];
    const float* c1_b0 = (const float*)d_in[7];
    const float* c2_W0 = (const float*)d_in[8];
    const float* c2_b0 = (const float*)d_in[9];
    const float* c1_W  = (const float*)d_in[10];
    const float* c1_b  = (const float*)d_in[11];
    const float* c2_W  = (const float*)d_in[12];
    const float* c2_b  = (const float*)d_in[13];
    const float* c3_W  = (const float*)d_in[14];
    const float* c3_b  = (const float*)d_in[15];
    const float* bn1_g = (const float*)d_in[16];
    const float* bn1_b = (const float*)d_in[17];
    const float* bn2_g = (const float*)d_in[18];
    const float* bn2_b = (const float*)d_in[19];
    const float* bn3_g = (const float*)d_in[20];
    const float* bn3_b = (const float*)d_in[21];
    const float* fc_W  = (const float*)d_in[22];
    const float* fc_b  = (const float*)d_in[23];
    float* out = (float*)d_out;

    float *qkvA, *qkvB, *qkvC, *preA, *preB, *preC, *fcb, *stats;
    cudaGetSymbolAddress((void**)&qkvA, g_qkvA);
    cudaGetSymbolAddress((void**)&qkvB, g_qkvB);
    cudaGetSymbolAddress((void**)&qkvC, g_qkvC);
    cudaGetSymbolAddress((void**)&preA, g_preA);
    cudaGetSymbolAddress((void**)&preB, g_preB);
    cudaGetSymbolAddress((void**)&preC, g_preC);
    cudaGetSymbolAddress((void**)&fcb, g_fc);
    cudaGetSymbolAddress((void**)&stats, g_stats);

    const int G3E = (3 * NEDGE + 255) / 256;
    const int SMEM_MMA = (128 * SA_STRIDE + 160 * SB_STRIDE) * 2;

    cudaFuncSetAttribute(gemm_big_mma, cudaFuncAttributeMaxDynamicSharedMemorySize,
                         SMEM_MMA);

    // ---- CSR build + weight split/transpose ----
    zero_all<<<(NN3 + 255) / 256, 256>>>();
    hist_kernel<<<G3E, 256>>>(same2, diff2, edge_index);
    conv_w<<<(2000 * 160 + 255) / 256, 256>>>(c1_W0, c2_W0);
    scanA<<<SCAN_BLOCKS, 1024>>>();
    scanB<<<1, 256>>>();
    scanC<<<SCAN_BLOCKS, 1024>>>();
    scatter_kernel<<<G3E, 256>>>(same2, diff2, edge_index);

    // ---- layer 0 ----
    gemm_big_mma<<<GB_SM, 256, SMEM_MMA>>>(features, c1_b0, c2_b0, qkvA, qkvB);
    agg_csr3<<<2 * GA_BLK, 256>>>(qkvA, 0, preA, stats + 0 * 40,
                                  qkvB, NNODES, preB, stats + 1 * 40,
                                  qkvA, 0, preA, stats + 0 * 40);

    for (int L = 0; L <= 4; L++) {
        const float* stX = stats + (3 * L) * 40;
        const float* stY = stats + (3 * L + 1) * 40;
        const float* g1 = bn1_g + L * 20; const float* b1 = bn1_b + L * 20;
        const float* g2 = bn2_g + L * 20; const float* b2 = bn2_b + L * 20;
        const int nsets = (L < 4) ? 3 : 1;
        const int bnBlocks = (L > 0) ? GN_BLK : 0;  // fuse previous layer's bn_fc

        gemm_small3<<<nsets * GB_SM + bnBlocks, 256>>>(
            preA, preB, stX, stY, g1, b1, g2, b2,
            c3_W + (size_t)L * 3200, c3_b + (size_t)L * 80, qkvC,
            c1_W + (size_t)L * 3200, c1_b + (size_t)L * 80, qkvA,
            c2_W + (size_t)L * 3200, c2_b + (size_t)L * 80, qkvB,
            nsets,
            preC, stats + (3 * (L - 1) + 2) * 40,
            bn3_g + (L - 1) * 20, bn3_b + (L - 1) * 20, fcb, (L - 1) * 20);

        if (L < 4) {
            agg_csr3<<<3 * GA_BLK, 256>>>(qkvC, 2 * NNODES, preC, stats + (3 * L + 2) * 40,
                                          qkvA, 0, preA, stats + (3 * L + 3) * 40,
                                          qkvB, NNODES, preB, stats + (3 * L + 4) * 40);
        } else {
            agg_csr3<<<GA_BLK, 256>>>(qkvC, 2 * NNODES, preC, stats + (3 * L + 2) * 40,
                                      qkvC, 2 * NNODES, preC, stats + (3 * L + 2) * 40,
                                      qkvC, 2 * NNODES, preC, stats + (3 * L + 2) * 40);
        }
    }
    bn_fc<<<GN_BLK, 256>>>(preC, stats + 14 * 40, bn3_g + 80, bn3_b + 80, fcb, 80);

    fc_kernel<<<(NNODES + 127) / 128, 128>>>(fc_W, fc_b, out);
}

// round 11
// speedup vs baseline: 2.6354x; 1.1180x over previous
#include <cuda_runtime.h>
#include <cuda_bf16.h>
#include <cstdint>

#define NNODES 50000
#define NEDGE  1000000
#define DIN0   2000
#define EPS_BN 1e-5f
#define LSLOPE 0.01f
#define NN3    150000
#define SCAN_BLOCKS 147
#define GA_BLK 6250   /* (NNODES+7)/8 */
#define GB_SM  391    /* (NNODES+127)/128 */
#define GN_BLK 3907   /* (NNODES*20+255)/256 */

// qkv row layout (80 floats): [ q(0..19) | k0 v0 k1 v1 .. k19 v19 (20..59) | skip(60..79) ]

// ------------------------- scratch (device globals, zero-init) -------------
__device__ float g_qkvA[NNODES * 80];
__device__ float g_qkvB[NNODES * 80];
__device__ float g_qkvC[NNODES * 80];
__device__ float g_preA[NNODES * 20];
__device__ float g_preB[NNODES * 20];
__device__ float g_preC[NNODES * 20];
__device__ float g_fc[NNODES * 100];
__device__ float g_stats[15 * 40];
__device__ __nv_bfloat16 g_wt_hi[2000 * 160];
__device__ __nv_bfloat16 g_wt_lo[2000 * 160];
// CSR scratch
__device__ int g_cnt[NN3];
__device__ int g_off[NN3 + 1];
__device__ int g_cur[NN3];
__device__ int g_csr[3 * NEDGE];
__device__ int g_partraw[SCAN_BLOCKS];
__device__ int g_part[SCAN_BLOCKS];

// ------------------------- helpers -------------------------
__device__ __forceinline__ unsigned long long ffma2(unsigned long long a,
                                                    unsigned long long b,
                                                    unsigned long long c) {
    unsigned long long d;
    asm("fma.rn.f32x2 %0, %1, %2, %3;" : "=l"(d) : "l"(a), "l"(b), "l"(c));
    return d;
}
__device__ __forceinline__ unsigned long long pack2(float lo, float hi) {
    unsigned long long r;
    asm("mov.b64 %0, {%1, %2};" : "=l"(r) : "f"(lo), "f"(hi));
    return r;
}
__device__ __forceinline__ uint32_t smem_u32(const void* p) {
    uint32_t a;
    asm("{ .reg .u64 t; cvta.to.shared.u64 t, %1; cvt.u32.u64 %0, t; }"
        : "=r"(a) : "l"(p));
    return a;
}
__device__ __forceinline__ uint32_t packbf2(float a, float b, float* lo_a, float* lo_b) {
    __nv_bfloat16 ha = __float2bfloat16(a), hb = __float2bfloat16(b);
    *lo_a = a - __bfloat162float(ha);
    *lo_b = b - __bfloat162float(hb);
    __nv_bfloat162 p; p.x = ha; p.y = hb;
    return *(uint32_t*)&p;
}
__device__ __forceinline__ uint32_t packbf2s(float a, float b) {
    __nv_bfloat162 p; p.x = __float2bfloat16(a); p.y = __float2bfloat16(b);
    return *(uint32_t*)&p;
}
// logical qkv column (0..79) -> interleaved position
__device__ __forceinline__ int qkvpos(int c) {
    if (c < 20) return c;
    if (c < 40) return 2 * c - 20;   // k_c -> 20+2c
    if (c < 60) return 2 * c - 59;   // v_c -> 21+2c
    return c;
}

// ------------------------- CSR build -------------------------
__global__ void zero_all() {
    int i = blockIdx.x * blockDim.x + threadIdx.x;
    if (i < NN3) g_cnt[i] = 0;
    if (i < 15 * 40) g_stats[i] = 0.f;
}
__global__ void hist_kernel(const int* __restrict__ e0, const int* __restrict__ e1,
                            const int* __restrict__ e2) {
    int i = blockIdx.x * blockDim.x + threadIdx.x;
    if (i >= 3 * NEDGE) return;
    int set = i / NEDGE, e = i - set * NEDGE;
    const int* ei = (set == 0) ? e0 : ((set == 1) ? e1 : e2);
    atomicAdd(&g_cnt[set * NNODES + ei[NEDGE + e]], 1);
}
__global__ void __launch_bounds__(1024) scanA() {
    int gid = blockIdx.x * 1024 + threadIdx.x;
    int v = (gid < NN3) ? g_cnt[gid] : 0;
#pragma unroll
    for (int o = 16; o; o >>= 1) v += __shfl_xor_sync(~0u, v, o);
    __shared__ int sw[32];
    if ((threadIdx.x & 31) == 0) sw[threadIdx.x >> 5] = v;
    __syncthreads();
    if (threadIdx.x < 32) {
        int t = sw[threadIdx.x];
#pragma unroll
        for (int o = 16; o; o >>= 1) t += __shfl_xor_sync(~0u, t, o);
        if (threadIdx.x == 0) g_partraw[blockIdx.x] = t;
    }
}
__global__ void scanB() {
    __shared__ int sp[SCAN_BLOCKS + 1];
    int tid = threadIdx.x;
    if (tid < SCAN_BLOCKS) sp[tid + 1] = g_partraw[tid];
    if (tid == 0) sp[0] = 0;
    __syncthreads();
    if (tid == 0)
        for (int b = 1; b <= SCAN_BLOCKS; b++) sp[b] += sp[b - 1];
    __syncthreads();
    if (tid < SCAN_BLOCKS) g_part[tid] = sp[tid];
}
__global__ void __launch_bounds__(1024) scanC() {
    __shared__ int sdat[1024];
    int tid = threadIdx.x;
    int gid = blockIdx.x * 1024 + tid;
    int v = (gid < NN3) ? g_cnt[gid] : 0;
    sdat[tid] = v;
    __syncthreads();
    for (int o = 1; o < 1024; o <<= 1) {
        int t = (tid >= o) ? sdat[tid - o] : 0;
        __syncthreads();
        sdat[tid] += t;
        __syncthreads();
    }
    int excl = sdat[tid] - v + g_part[blockIdx.x];
    if (gid < NN3) { g_off[gid] = excl; g_cur[gid] = excl; }
    if (gid == 0) g_off[NN3] = 3 * NEDGE;
}
__global__ void scatter_kernel(const int* __restrict__ e0, const int* __restrict__ e1,
                               const int* __restrict__ e2) {
    int i = blockIdx.x * blockDim.x + threadIdx.x;
    if (i >= 3 * NEDGE) return;
    int set = i / NEDGE, e = i - set * NEDGE;
    const int* ei = (set == 0) ? e0 : ((set == 1) ? e1 : e2);
    int s = ei[e], d = ei[NEDGE + e];
    int pos = atomicAdd(&g_cur[set * NNODES + d], 1);
    g_csr[pos] = s;
}

// ------------- W split+transpose with kv-interleave column permutation -----
__global__ void conv_w(const float* __restrict__ W1, const float* __restrict__ W2) {
    int idx = blockIdx.x * blockDim.x + threadIdx.x;
    if (idx >= 2000 * 160) return;
    int k = idx / 160, n = idx - k * 160;
    const float* Wsrc = (n < 80) ? W1 : W2;
    int nn = (n < 80) ? n : n - 80;
    int s = nn / 20, o = nn % 20;
    float w = Wsrc[((size_t)s * 2000 + k) * 20 + o];
    __nv_bfloat16 h = __float2bfloat16(w);
    int nperm = ((n < 80) ? 0 : 80) + qkvpos(nn);
    g_wt_hi[(size_t)k * 160 + nperm] = h;
    g_wt_lo[(size_t)k * 160 + nperm] = __float2bfloat16(w - __bfloat162float(h));
}

// ------------------------- big GEMM via mma.sync bf16-split ----------------
#define SA_STRIDE 168
#define SB_STRIDE 168

__global__ void __launch_bounds__(256)
gemm_big_mma(const float* __restrict__ A,
             const float* __restrict__ b1, const float* __restrict__ b2,
             float* __restrict__ outA, float* __restrict__ outB) {
    extern __shared__ __align__(16) char dsm[];
    __nv_bfloat16* sA = (__nv_bfloat16*)dsm;
    __nv_bfloat16* sB = (__nv_bfloat16*)(dsm + 128 * SA_STRIDE * 2);
    __shared__ float s_bias[160];

    const int tid = threadIdx.x, wid = tid >> 5, lane = tid & 31;
    const int rowbase = blockIdx.x * 128;
    if (tid < 160) {
        int g = tid / 80, c = tid % 80;
        float bv = (g == 0) ? b1[c] : b2[c];
        s_bias[g * 80 + qkvpos(c)] = bv;
    }

    float acc[20][4];
#pragma unroll
    for (int t = 0; t < 20; t++)
#pragma unroll
        for (int i = 0; i < 4; i++) acc[t][i] = 0.f;

    const int r_in = lane & 7, blkb = (lane >> 3) & 1, kh = (lane >> 4) & 1;
    const uint32_t aBase =
        smem_u32(sA) + (uint32_t)((wid * 16 + blkb * 8 + r_in) * SA_STRIDE + kh * 8) * 2;
    const uint32_t bBase2 = smem_u32(sB) + (uint32_t)((lane & 15) * SB_STRIDE) * 2;
    const uint32_t bBase4 = smem_u32(sB) + (uint32_t)(lane * SB_STRIDE) * 2;

    const int a0off[7] = {0, 32, 64, 16, 48, 80, 112};
    const int a1off[7] = {16, 48, 0, 32, 64, 96, 128};
    const int browt[7] = {0, 32, 64, 96, 128, 0, 32};

    for (int ch = 0; ch < 25; ch++) {
        const int k0 = ch * 80;
#pragma unroll
        for (int it = 0; it < 13; it++) {
            int q = tid + it * 256;
            if (q < 3200) {
                int row = q / 20, c16 = q - row * 20;
                int kk = (row >= 80) ? row - 80 : row;
                const __nv_bfloat16* src =
                    ((row >= 80) ? g_wt_lo : g_wt_hi) + (size_t)(k0 + kk) * 160 + c16 * 8;
                uint32_t dst = smem_u32(sB) + (uint32_t)(row * SB_STRIDE + c16 * 8) * 2;
                asm volatile("cp.async.ca.shared.global [%0], [%1], 16;"
                             :: "r"(dst), "l"(src));
            }
        }
        asm volatile("cp.async.commit_group;" ::: "memory");
#pragma unroll
        for (int it = 0; it < 10; it++) {
            int q = tid + it * 256;
            int r = q / 20, f = q - r * 20;
            int row = rowbase + r;
            float4 v = (row < NNODES)
                           ? *(const float4*)(A + (size_t)row * 2000 + k0 + f * 4)
                           : make_float4(0.f, 0.f, 0.f, 0.f);
            float l0, l1, l2, l3;
            uint32_t h0 = packbf2(v.x, v.y, &l0, &l1);
            uint32_t h1 = packbf2(v.z, v.w, &l2, &l3);
            uint32_t p0 = packbf2s(l0, l1), p1 = packbf2s(l2, l3);
            int k = f * 4;
            __nv_bfloat16* rp = sA + r * SA_STRIDE;
            *(uint32_t*)(rp + k) = h0;
            *(uint32_t*)(rp + k + 2) = h1;
            *(uint32_t*)(rp + 80 + k) = p0;
            *(uint32_t*)(rp + 82 + k) = p1;
        }
        asm volatile("cp.async.wait_group 0;" ::: "memory");
        __syncthreads();
#pragma unroll
        for (int jp = 0; jp < 7; jp++) {
            uint32_t a0, a1, a2, a3, c0, c1, c2, c3;
            asm volatile(
                "ldmatrix.sync.aligned.m8n8.x4.shared.b16 {%0,%1,%2,%3}, [%4];"
                : "=r"(a0), "=r"(a1), "=r"(a2), "=r"(a3)
                : "r"(aBase + (uint32_t)a0off[jp] * 2));
            asm volatile(
                "ldmatrix.sync.aligned.m8n8.x4.shared.b16 {%0,%1,%2,%3}, [%4];"
                : "=r"(c0), "=r"(c1), "=r"(c2), "=r"(c3)
                : "r"(aBase + (uint32_t)a1off[jp] * 2));
            const uint32_t bb = bBase4 + (uint32_t)(browt[jp] * SB_STRIDE) * 2;
#pragma unroll
            for (int t = 0; t < 20; t++) {
                uint32_t b0, b1, b2, b3;
                asm volatile(
                    "ldmatrix.sync.aligned.m8n8.x4.trans.shared.b16 {%0,%1,%2,%3}, [%4];"
                    : "=r"(b0), "=r"(b1), "=r"(b2), "=r"(b3)
                    : "r"(bb + (uint32_t)t * 16));
                asm volatile(
                    "mma.sync.aligned.m16n8k16.row.col.f32.bf16.bf16.f32 "
                    "{%0,%1,%2,%3}, {%4,%5,%6,%7}, {%8,%9}, {%0,%1,%2,%3};"
                    : "+f"(acc[t][0]), "+f"(acc[t][1]), "+f"(acc[t][2]), "+f"(acc[t][3])
                    : "r"(a0), "r"(a1), "r"(a2), "r"(a3), "r"(b0), "r"(b1));
                asm volatile(
                    "mma.sync.aligned.m16n8k16.row.col.f32.bf16.bf16.f32 "
                    "{%0,%1,%2,%3}, {%4,%5,%6,%7}, {%8,%9}, {%0,%1,%2,%3};"
                    : "+f"(acc[t][0]), "+f"(acc[t][1]), "+f"(acc[t][2]), "+f"(acc[t][3])
                    : "r"(c0), "r"(c1), "r"(c2), "r"(c3), "r"(b2), "r"(b3));
            }
        }
        {
            uint32_t a0, a1, a2, a3;
            asm volatile(
                "ldmatrix.sync.aligned.m8n8.x4.shared.b16 {%0,%1,%2,%3}, [%4];"
                : "=r"(a0), "=r"(a1), "=r"(a2), "=r"(a3)
                : "r"(aBase + 144u * 2));
            const uint32_t bb = bBase2 + (uint32_t)(64 * SB_STRIDE) * 2;
#pragma unroll
            for (int t = 0; t < 20; t++) {
                uint32_t b0, b1;
                asm volatile(
                    "ldmatrix.sync.aligned.m8n8.x2.trans.shared.b16 {%0,%1}, [%2];"
                    : "=r"(b0), "=r"(b1)
                    : "r"(bb + (uint32_t)t * 16));
                asm volatile(
                    "mma.sync.aligned.m16n8k16.row.col.f32.bf16.bf16.f32 "
                    "{%0,%1,%2,%3}, {%4,%5,%6,%7}, {%8,%9}, {%0,%1,%2,%3};"
                    : "+f"(acc[t][0]), "+f"(acc[t][1]), "+f"(acc[t][2]), "+f"(acc[t][3])
                    : "r"(a0), "r"(a1), "r"(a2), "r"(a3), "r"(b0), "r"(b1));
            }
        }
        __syncthreads();
    }

    const int r0 = rowbase + wid * 16 + lane / 4;
    const int r1 = r0 + 8;
    const int cb = (lane & 3) * 2;
#pragma unroll
    for (int t = 0; t < 20; t++) {
        int col = t * 8 + cb;
        float* base = (col < 80) ? outA : outB;
        int cc = (col < 80) ? col : col - 80;
        float bia0 = s_bias[col], bia1 = s_bias[col + 1];
        if (r0 < NNODES)
            *(float2*)(base + (size_t)r0 * 80 + cc) =
                make_float2(acc[t][0] + bia0, acc[t][1] + bia1);
        if (r1 < NNODES)
            *(float2*)(base + (size_t)r1 * 80 + cc) =
                make_float2(acc[t][2] + bia0, acc[t][3] + bia1);
    }
}

// --------------- fused small GEMMs (+ optional bn_fc block range) ----------
__global__ void __launch_bounds__(256)
gemm_small3(const float* __restrict__ preA, const float* __restrict__ preB,
            const float* __restrict__ stX, const float* __restrict__ stY,
            const float* __restrict__ g1, const float* __restrict__ be1,
            const float* __restrict__ g2, const float* __restrict__ be2,
            const float* __restrict__ Wc3, const float* __restrict__ bc3,
            float* __restrict__ outC,
            const float* __restrict__ Wc1, const float* __restrict__ bc1,
            float* __restrict__ outA,
            const float* __restrict__ Wc2, const float* __restrict__ bc2,
            float* __restrict__ outB,
            int nsets,
            const float* __restrict__ bnPre, const float* __restrict__ bnStats,
            const float* __restrict__ bnG, const float* __restrict__ bnB,
            float* __restrict__ bnDst, int bnOff) {
    const int bnStart = nsets * GB_SM;
    if ((int)blockIdx.x >= bnStart) {
        int idx = (blockIdx.x - bnStart) * 256 + threadIdx.x;
        if (idx >= NNODES * 20) return;
        int n = idx / 20, c = idx % 20;
        const float invN = 1.f / (float)NNODES;
        float mu = bnStats[c] * invN;
        float var = bnStats[20 + c] * invN - mu * mu;
        float scv = bnG[c] * rsqrtf(var + EPS_BN);
        float v = (bnPre[idx] - mu) * scv + bnB[c];
        v = (v >= 0.f) ? v : LSLOPE * v;
        bnDst[(size_t)n * 100 + bnOff + c] = v;
        return;
    }
    const int set = blockIdx.x / GB_SM;
    const int bi = blockIdx.x - set * GB_SM;
    const bool swap = (set == 2);
    const float* preX = swap ? preB : preA;
    const float* preY = swap ? preA : preB;
    const float* statsX = swap ? stY : stX;
    const float* statsY = swap ? stX : stY;
    const float* gX = swap ? g2 : g1;
    const float* betX = swap ? be2 : be1;
    const float* gY = swap ? g1 : g2;
    const float* betY = swap ? be1 : be2;
    const float* W = (set == 0) ? Wc3 : ((set == 1) ? Wc1 : Wc2);
    const float* b = (set == 0) ? bc3 : ((set == 1) ? bc1 : bc2);
    float* out = (set == 0) ? outC : ((set == 1) ? outA : outB);

    __shared__ __align__(8) float sW[40][80];
    __shared__ float sb[80];
    __shared__ float sMu[40], sScv[40], sBeta[40];
    const int tid = threadIdx.x;
    for (int l = tid; l < 3200; l += 256) {
        int s = l / 800, rem = l % 800, k = rem / 20, o = rem % 20;
        sW[k][qkvpos(s * 20 + o)] = W[l];
    }
    if (tid < 80) sb[qkvpos(tid)] = b[tid];
    if (tid < 40) {
        const float invN = 1.f / (float)NNODES;
        int c = tid % 20;
        const float* st = (tid < 20) ? statsX : statsY;
        const float* gg = (tid < 20) ? gX : gY;
        const float* bb = (tid < 20) ? betX : betY;
        float mu = st[c] * invN;
        float var = st[20 + c] * invN - mu * mu;
        sMu[tid] = mu;
        sScv[tid] = gg[c] * rsqrtf(var + EPS_BN);
        sBeta[tid] = bb[c];
    }
    __syncthreads();

    const int row = bi * 128 + (tid >> 1);
    const int cb = (tid & 1) * 40;
    if (row >= NNODES) return;

    float a[40];
    {
        const float4* pa = (const float4*)(preX + (size_t)row * 20);
        const float4* pb = (const float4*)(preY + (size_t)row * 20);
        float4 va[5], vb[5];
#pragma unroll
        for (int i = 0; i < 5; i++) va[i] = pa[i];
#pragma unroll
        for (int i = 0; i < 5; i++) vb[i] = pb[i];
#pragma unroll
        for (int i = 0; i < 5; i++) {
            a[4 * i]     = va[i].x; a[4 * i + 1] = va[i].y;
            a[4 * i + 2] = va[i].z; a[4 * i + 3] = va[i].w;
            a[20 + 4 * i] = vb[i].x; a[21 + 4 * i] = vb[i].y;
            a[22 + 4 * i] = vb[i].z; a[23 + 4 * i] = vb[i].w;
        }
    }
#pragma unroll
    for (int k = 0; k < 40; k++) {
        float v = (a[k] - sMu[k]) * sScv[k] + sBeta[k];
        a[k] = (v >= 0.f) ? v : LSLOPE * v;
    }

    unsigned long long acc[20];
#pragma unroll
    for (int c = 0; c < 20; c++) acc[c] = 0ull;
#pragma unroll 8
    for (int k = 0; k < 40; k++) {
        unsigned long long a2 = pack2(a[k], a[k]);
        const unsigned long long* wrow = (const unsigned long long*)(&sW[k][cb]);
#pragma unroll
        for (int c = 0; c < 20; c++) acc[c] = ffma2(a2, wrow[c], acc[c]);
    }

    float res[40];
#pragma unroll
    for (int c = 0; c < 20; c++) {
        res[2 * c]     = __uint_as_float((unsigned)(acc[c] & 0xffffffffull)) + sb[cb + 2 * c];
        res[2 * c + 1] = __uint_as_float((unsigned)(acc[c] >> 32)) + sb[cb + 2 * c + 1];
    }
    float* dst = out + (size_t)row * 80 + cb;
#pragma unroll
    for (int c = 0; c < 40; c += 4)
        *(float4*)(dst + c) = make_float4(res[c], res[c + 1], res[c + 2], res[c + 3]);
}

// ---------- CSR aggregation: channel-pair lanes, 2 edges per warp-step ------
// Lane layout: half = lane>>4 (edge slot), hl = lane&15; lanes hl<10 own
// channel pair (2hl, 2hl+1). Dot reduces over a 4-level xor butterfly within
// each 16-lane half; the two halves process consecutive edges simultaneously.
__global__ void __launch_bounds__(256)
agg_csr3(const float* __restrict__ q0, int nb0, float* __restrict__ p0, float* __restrict__ s0,
         const float* __restrict__ q1, int nb1, float* __restrict__ p1, float* __restrict__ s1,
         const float* __restrict__ q2, int nb2, float* __restrict__ p2, float* __restrict__ s2) {
    const int set = blockIdx.x / GA_BLK;
    const int bi = blockIdx.x - set * GA_BLK;
    const float* qkv = (set == 0) ? q0 : ((set == 1) ? q1 : q2);
    float* pre = (set == 0) ? p0 : ((set == 1) ? p1 : p2);
    float* stats = (set == 0) ? s0 : ((set == 1) ? s1 : s2);
    const int nbase = (set == 0) ? nb0 : ((set == 1) ? nb1 : nb2);

    const int wid = threadIdx.x >> 5, lane = threadIdx.x & 31;
    const int n = bi * 8 + wid;
    const int half = lane >> 4;      // which edge of the pair
    const int hl = lane & 15;
    const bool act = hl < 10;        // channel-pair lanes
    const int cp = hl;               // channel pair index (0..9)

    __shared__ float sst[2][8][20];
    for (int l = threadIdx.x; l < 320; l += 256) ((float*)sst)[l] = 0.f;
    __syncthreads();

    if (n < NNODES) {
        const int gi = nbase + n;
        const int off0 = g_off[gi], off1 = g_off[gi + 1];
        float2 q2v = make_float2(0.f, 0.f);
        if (act) {
            q2v = *(const float2*)(qkv + (size_t)n * 80 + 2 * cp);
            q2v.x *= 0.22360679774997896f;
            q2v.y *= 0.22360679774997896f;
        }
        const uint32_t kvf = 20 + 4 * cp;
        float accx = 0.f, accy = 0.f, denom = 0.f;
        int p = off0;
        // main loop: 4 edges per iteration (2 per half, 2 sequential)
        for (; p + 4 <= off1; p += 4) {
            int sA = g_csr[p + half];
            int sB = g_csr[p + 2 + half];
            float4 kv0 = act ? *(const float4*)(qkv + (size_t)sA * 80 + kvf)
                             : make_float4(0.f, 0.f, 0.f, 0.f);
            float4 kv1 = act ? *(const float4*)(qkv + (size_t)sB * 80 + kvf)
                             : make_float4(0.f, 0.f, 0.f, 0.f);
            float d0 = q2v.x * kv0.x + q2v.y * kv0.z;
            float d1 = q2v.x * kv1.x + q2v.y * kv1.z;
#pragma unroll
            for (int o = 8; o; o >>= 1) {
                d0 += __shfl_xor_sync(~0u, d0, o);
                d1 += __shfl_xor_sync(~0u, d1, o);
            }
            float e0 = __expf(d0), e1 = __expf(d1);
            denom += e0 + e1;
            accx += e0 * kv0.y + e1 * kv1.y;
            accy += e0 * kv0.w + e1 * kv1.w;
        }
        // tail: 2 edges per iteration, guarded
        for (; p < off1; p += 2) {
            bool ea = (p + half) < off1;
            int sA = ea ? g_csr[p + half] : 0;
            float4 kv0 = (act && ea) ? *(const float4*)(qkv + (size_t)sA * 80 + kvf)
                                     : make_float4(0.f, 0.f, 0.f, 0.f);
            float d0 = q2v.x * kv0.x + q2v.y * kv0.z;
#pragma unroll
            for (int o = 8; o; o >>= 1) d0 += __shfl_xor_sync(~0u, d0, o);
            float e0 = ea ? __expf(d0) : 0.f;
            denom += e0;
            accx += e0 * kv0.y;
            accy += e0 * kv0.w;
        }
        // combine the two halves
        accx += __shfl_xor_sync(~0u, accx, 16);
        accy += __shfl_xor_sync(~0u, accy, 16);
        denom += __shfl_xor_sync(~0u, denom, 16);
        float inv = 1.f / fmaxf(denom, 1e-16f);
        if (act && half == 0) {
            float2 sk = *(const float2*)(qkv + (size_t)n * 80 + 60 + 2 * cp);
            float rx = accx * inv + sk.x;
            float ry = accy * inv + sk.y;
            *(float2*)(pre + (size_t)n * 20 + 2 * cp) = make_float2(rx, ry);
            sst[0][wid][2 * cp] = rx;
            sst[0][wid][2 * cp + 1] = ry;
            sst[1][wid][2 * cp] = rx * rx;
            sst[1][wid][2 * cp + 1] = ry * ry;
        }
    }
    __syncthreads();
    if (threadIdx.x < 40) {
        int which = threadIdx.x / 20, cc = threadIdx.x % 20;
        float t = 0.f;
#pragma unroll
        for (int w = 0; w < 8; w++) t += sst[which][w][cc];
        atomicAdd(&stats[which * 20 + cc], t);
    }
}

// ------------------------- standalone bn_fc (last layer) + final FC --------
__global__ void __launch_bounds__(256)
bn_fc(const float* __restrict__ pre, const float* __restrict__ stats,
      const float* __restrict__ gamma, const float* __restrict__ beta,
      float* __restrict__ dst, int off) {
    int idx = blockIdx.x * blockDim.x + threadIdx.x;
    if (idx >= NNODES * 20) return;
    int n = idx / 20, c = idx % 20;
    const float invN = 1.f / (float)NNODES;
    float mu = stats[c] * invN;
    float var = stats[20 + c] * invN - mu * mu;
    float scv = gamma[c] * rsqrtf(var + EPS_BN);
    float v = (pre[idx] - mu) * scv + beta[c];
    v = (v >= 0.f) ? v : LSLOPE * v;
    dst[(size_t)n * 100 + off + c] = v;
}

__global__ void __launch_bounds__(128)
fc_kernel(const float* __restrict__ W, const float* __restrict__ b,
          float* __restrict__ out) {
    __shared__ float sw[200];
    for (int l = threadIdx.x; l < 200; l += blockDim.x) sw[l] = W[l];
    __syncthreads();
    int n = blockIdx.x * blockDim.x + threadIdx.x;
    if (n >= NNODES) return;
    float a0 = b[0], a1 = b[1];
    const float4* fp = (const float4*)(g_fc + (size_t)n * 100);
#pragma unroll
    for (int i = 0; i < 25; i++) {
        float4 f = fp[i];
        int c = 4 * i;
        a0 += f.x * sw[2 * c] + f.y * sw[2 * c + 2] + f.z * sw[2 * c + 4] + f.w * sw[2 * c + 6];
        a1 += f.x * sw[2 * c + 1] + f.y * sw[2 * c + 3] + f.z * sw[2 * c + 5] + f.w * sw[2 * c + 7];
    }
    out[2 * n] = a0;
    out[2 * n + 1] = a1;
}

// ------------------------- host orchestration -------------------------
extern "C" void kernel_launch(void* const* d_in, const int* in_sizes, int n_in,
                              void* d_out, int out_size) {
    (void)in_sizes; (void)n_in; (void)out_size;
    const float* features = (const float*)d_in[0];
    const int* edge_index = (const int*)d_in[3];
    const int* same2      = (const int*)d_in[4];
    const int* diff2      = (const int*)d_in[5];
    const float* c1_W0 = (const float*)d_in[6];
    const float* c1_b0 = (const float*)d_in[7];
    const float* c2_W0 = (const float*)d_in[8];
    const float* c2_b0 = (const float*)d_in[9];
    const float* c1_W  = (const float*)d_in[10];
    const float* c1_b  = (const float*)d_in[11];
    const float* c2_W  = (const float*)d_in[12];
    const float* c2_b  = (const float*)d_in[13];
    const float* c3_W  = (const float*)d_in[14];
    const float* c3_b  = (const float*)d_in[15];
    const float* bn1_g = (const float*)d_in[16];
    const float* bn1_b = (const float*)d_in[17];
    const float* bn2_g = (const float*)d_in[18];
    const float* bn2_b = (const float*)d_in[19];
    const float* bn3_g = (const float*)d_in[20];
    const float* bn3_b = (const float*)d_in[21];
    const float* fc_W  = (const float*)d_in[22];
    const float* fc_b  = (const float*)d_in[23];
    float* out = (float*)d_out;

    float *qkvA, *qkvB, *qkvC, *preA, *preB, *preC, *fcb, *stats;
    cudaGetSymbolAddress((void**)&qkvA, g_qkvA);
    cudaGetSymbolAddress((void**)&qkvB, g_qkvB);
    cudaGetSymbolAddress((void**)&qkvC, g_qkvC);
    cudaGetSymbolAddress((void**)&preA, g_preA);
    cudaGetSymbolAddress((void**)&preB, g_preB);
    cudaGetSymbolAddress((void**)&preC, g_preC);
    cudaGetSymbolAddress((void**)&fcb, g_fc);
    cudaGetSymbolAddress((void**)&stats, g_stats);

    const int G3E = (3 * NEDGE + 255) / 256;
    const int SMEM_MMA = (128 * SA_STRIDE + 160 * SB_STRIDE) * 2;

    cudaFuncSetAttribute(gemm_big_mma, cudaFuncAttributeMaxDynamicSharedMemorySize,
                         SMEM_MMA);

    // ---- CSR build + weight split/transpose ----
    zero_all<<<(NN3 + 255) / 256, 256>>>();
    hist_kernel<<<G3E, 256>>>(same2, diff2, edge_index);
    conv_w<<<(2000 * 160 + 255) / 256, 256>>>(c1_W0, c2_W0);
    scanA<<<SCAN_BLOCKS, 1024>>>();
    scanB<<<1, 256>>>();
    scanC<<<SCAN_BLOCKS, 1024>>>();
    scatter_kernel<<<G3E, 256>>>(same2, diff2, edge_index);

    // ---- layer 0 ----
    gemm_big_mma<<<GB_SM, 256, SMEM_MMA>>>(features, c1_b0, c2_b0, qkvA, qkvB);
    agg_csr3<<<2 * GA_BLK, 256>>>(qkvA, 0, preA, stats + 0 * 40,
                                  qkvB, NNODES, preB, stats + 1 * 40,
                                  qkvA, 0, preA, stats + 0 * 40);

    for (int L = 0; L <= 4; L++) {
        const float* stX = stats + (3 * L) * 40;
        const float* stY = stats + (3 * L + 1) * 40;
        const float* g1 = bn1_g + L * 20; const float* b1 = bn1_b + L * 20;
        const float* g2 = bn2_g + L * 20; const float* b2 = bn2_b + L * 20;
        const int nsets = (L < 4) ? 3 : 1;
        const int bnBlocks = (L > 0) ? GN_BLK : 0;

        gemm_small3<<<nsets * GB_SM + bnBlocks, 256>>>(
            preA, preB, stX, stY, g1, b1, g2, b2,
            c3_W + (size_t)L * 3200, c3_b + (size_t)L * 80, qkvC,
            c1_W + (size_t)L * 3200, c1_b + (size_t)L * 80, qkvA,
            c2_W + (size_t)L * 3200, c2_b + (size_t)L * 80, qkvB,
            nsets,
            preC, stats + (3 * (L - 1) + 2) * 40,
            bn3_g + (L - 1) * 20, bn3_b + (L - 1) * 20, fcb, (L - 1) * 20);

        if (L < 4) {
            agg_csr3<<<3 * GA_BLK, 256>>>(qkvC, 2 * NNODES, preC, stats + (3 * L + 2) * 40,
                                          qkvA, 0, preA, stats + (3 * L + 3) * 40,
                                          qkvB, NNODES, preB, stats + (3 * L + 4) * 40);
        } else {
            agg_csr3<<<GA_BLK, 256>>>(qkvC, 2 * NNODES, preC, stats + (3 * L + 2) * 40,
                                      qkvC, 2 * NNODES, preC, stats + (3 * L + 2) * 40,
                                      qkvC, 2 * NNODES, preC, stats + (3 * L + 2) * 40);
        }
    }
    bn_fc<<<GN_BLK, 256>>>(preC, stats + 14 * 40, bn3_g + 80, bn3_b + 80, fcb, 80);

    fc_kernel<<<(NNODES + 127) / 128, 128>>>(fc_W, fc_b, out);
}